// round 3
// baseline (speedup 1.0000x reference)
#include <cuda_runtime.h>
#include <cuda_bf16.h>

typedef unsigned long long ull;

__device__ __forceinline__ ull pack2(float x, float y) {
    ull r; asm("mov.b64 %0, {%1, %2};" : "=l"(r) : "f"(x), "f"(y)); return r;
}
__device__ __forceinline__ float2 unpack2(ull v) {
    float2 f; asm("mov.b64 {%0, %1}, %2;" : "=f"(f.x), "=f"(f.y) : "l"(v)); return f;
}
__device__ __forceinline__ void ffma2(ull& d, ull a, ull b) {
    asm("fma.rn.f32x2 %0, %1, %2, %0;" : "+l"(d) : "l"(a), "l"(b));
}
__device__ __forceinline__ void fmul2(ull& d, ull a) {
    asm("mul.rn.f32x2 %0, %0, %1;" : "+l"(d) : "l"(a));
}

// scratch: qh,kh,vh,ctx (4M floats each) + packed weights (4M floats)
#define QH_OFF   0u
#define KH_OFF   (1u<<22)
#define VH_OFF   (2u<<22)
#define CTX_OFF  (3u<<22)
#define WQ_OFF   (4u<<22)
#define WO_OFF   ((4u<<22) + (3u<<20))

__device__ float g_scratch[(4u<<22) + (4u<<20)];

// WqP[d*1024 + h*64 + k] = W_q[h,d,k]; WoP[kk*1024 + n] = W_o[n,kk]
__global__ void pack_kernel(const float* __restrict__ Wq, const float* __restrict__ Wk,
                            const float* __restrict__ Wv, const float* __restrict__ Wo) {
    unsigned idx = blockIdx.x * 256u + threadIdx.x;
    unsigned seg = idx >> 20, i = idx & ((1u << 20) - 1u);
    if (seg < 3u) {
        unsigned d = i >> 10, n = i & 1023u, h = n >> 6, kk = n & 63u;
        const float* W = (seg == 0u) ? Wq : (seg == 1u) ? Wk : Wv;
        g_scratch[WQ_OFF + (seg << 20) + i] = W[h * 65536u + d * 64u + kk];
    } else {
        unsigned n = i >> 10, kk = i & 1023u;
        g_scratch[WO_OFF + kk * 1024u + n] = Wo[i];
    }
}

// C[Mx1024] = A[Mx1024]*B[1024x1024] (+bias). 128x128 tile, BK=16, 256 thr, 8x8/thr.
__device__ __forceinline__ void gemm_body(const float* __restrict__ A,
                                          const float* __restrict__ B,
                                          float* __restrict__ C,
                                          const float* __restrict__ bias,
                                          float* As, float* Bs) {
    const int tid = threadIdx.x;
    const int bm = blockIdx.y << 7, bn = blockIdx.x << 7;
    const int ar = tid >> 2, ac = (tid & 3) << 2;
    const int br = tid >> 5, bc = (tid & 31) << 2;
    const float* Ap = A + (bm + ar) * 1024 + ac;
    const float* Bp = B + br * 1024 + bn + bc;
    const int tr = (tid >> 4) << 3, tc = (tid & 15) << 3;

    ull acc[8][4];
#pragma unroll
    for (int r = 0; r < 8; r++)
#pragma unroll
        for (int c = 0; c < 4; c++) acc[r][c] = 0ull;

    float4 a0 = *(const float4*)Ap;
    float4 a1 = *(const float4*)(Ap + 64 * 1024);
    float4 b0 = *(const float4*)Bp;
    float4 b1 = *(const float4*)(Bp + 8 * 1024);

    for (int k0 = 0; k0 < 1024; k0 += 16) {
        As[(ac + 0) * 128 + ar] = a0.x; As[(ac + 1) * 128 + ar] = a0.y;
        As[(ac + 2) * 128 + ar] = a0.z; As[(ac + 3) * 128 + ar] = a0.w;
        As[(ac + 0) * 128 + ar + 64] = a1.x; As[(ac + 1) * 128 + ar + 64] = a1.y;
        As[(ac + 2) * 128 + ar + 64] = a1.z; As[(ac + 3) * 128 + ar + 64] = a1.w;
        *(float4*)&Bs[br * 128 + bc] = b0;
        *(float4*)&Bs[(br + 8) * 128 + bc] = b1;
        __syncthreads();

        if (k0 + 16 < 1024) {
            Ap += 16; Bp += 16 * 1024;
            a0 = *(const float4*)Ap;
            a1 = *(const float4*)(Ap + 64 * 1024);
            b0 = *(const float4*)Bp;
            b1 = *(const float4*)(Bp + 8 * 1024);
        }

#pragma unroll
        for (int kk = 0; kk < 16; kk++) {
            float4 qa = *(const float4*)&As[kk * 128 + tr];
            float4 qb = *(const float4*)&As[kk * 128 + tr + 4];
            float4 p0 = *(const float4*)&Bs[kk * 128 + tc];
            float4 p1 = *(const float4*)&Bs[kk * 128 + tc + 4];
            ull bp[4] = { pack2(p0.x, p0.y), pack2(p0.z, p0.w),
                          pack2(p1.x, p1.y), pack2(p1.z, p1.w) };
            float av[8] = { qa.x, qa.y, qa.z, qa.w, qb.x, qb.y, qb.z, qb.w };
#pragma unroll
            for (int r = 0; r < 8; r++) {
                ull ap = pack2(av[r], av[r]);
#pragma unroll
                for (int c = 0; c < 4; c++) ffma2(acc[r][c], ap, bp[c]);
            }
        }
        __syncthreads();
    }

#pragma unroll
    for (int r = 0; r < 8; r++) {
        float out[8];
#pragma unroll
        for (int c = 0; c < 4; c++) {
            float2 f = unpack2(acc[r][c]);
            out[2 * c] = f.x; out[2 * c + 1] = f.y;
        }
        if (bias) {
#pragma unroll
            for (int c = 0; c < 8; c++) out[c] += bias[bn + tc + c];
        }
        float4* dst = (float4*)&C[(bm + tr + r) * 1024 + bn + tc];
        dst[0] = make_float4(out[0], out[1], out[2], out[3]);
        dst[1] = make_float4(out[4], out[5], out[6], out[7]);
    }
}

__global__ void __launch_bounds__(256, 2) proj3_kernel(const float* __restrict__ q,
                                                       const float* __restrict__ k,
                                                       const float* __restrict__ v) {
    __shared__ float As[16 * 128], Bs[16 * 128];
    const float* A; const float* B; float* C;
    if (blockIdx.z == 0)      { A = q; B = &g_scratch[WQ_OFF];            C = &g_scratch[QH_OFF]; }
    else if (blockIdx.z == 1) { A = k; B = &g_scratch[WQ_OFF + (1u<<20)]; C = &g_scratch[KH_OFF]; }
    else                      { A = v; B = &g_scratch[WQ_OFF + (2u<<20)]; C = &g_scratch[VH_OFF]; }
    gemm_body(A, B, C, nullptr, As, Bs);
}

__global__ void __launch_bounds__(256, 2) outproj_kernel(const float* __restrict__ bias,
                                                         float* __restrict__ out) {
    __shared__ float As[16 * 128], Bs[16 * 128];
    gemm_body(&g_scratch[CTX_OFF], &g_scratch[WO_OFF], out, bias, As, Bs);
}

// flash attention fp32: BQ=128, BKEY=64, 128 threads, 8x8 reg tiles, f32x2 FFMA.
#define QS_LD 132
#define KS_LD 68
// smem floats: Qs 64*132=8448 | Ks 64*68=4352 | Vs 64*68=4352 | Ps 64*132=8448

__global__ void __launch_bounds__(128) attn_kernel() {
    extern __shared__ float sm[];
    float* Qs = sm;
    float* Ks = sm + 8448;
    float* Vs = sm + 12800;
    float* Ps = sm + 17152;

    const int tid = threadIdx.x;
    const int ty = tid >> 3, tx = tid & 7;
    const int b = blockIdx.y >> 4, h = blockIdx.y & 15;
    const int hoff = h << 6;
    const int m0 = b * 2048 + (blockIdx.x << 7);
    const int kv0 = b * 2048;

    const float* qh = &g_scratch[QH_OFF];
    const float* kh = &g_scratch[KH_OFF];
    const float* vh = &g_scratch[VH_OFF];
    float* ctx = &g_scratch[CTX_OFF];

#pragma unroll
    for (int i = 0; i < 16; i++) {           // Q tile, prescaled 1/8, transposed
        int flat = tid + (i << 7);
        int row = flat >> 4, c4 = (flat & 15) << 2;
        float4 qv = *(const float4*)&qh[(m0 + row) * 1024 + hoff + c4];
        Qs[(c4 + 0) * QS_LD + row] = qv.x * 0.125f;
        Qs[(c4 + 1) * QS_LD + row] = qv.y * 0.125f;
        Qs[(c4 + 2) * QS_LD + row] = qv.z * 0.125f;
        Qs[(c4 + 3) * QS_LD + row] = qv.w * 0.125f;
    }

    ull o2[4][8];
#pragma unroll
    for (int rp = 0; rp < 4; rp++)
#pragma unroll
        for (int c = 0; c < 8; c++) o2[rp][c] = 0ull;
    float mrow[8], lrow[8];
#pragma unroll
    for (int r = 0; r < 8; r++) { mrow[r] = -1e30f; lrow[r] = 0.f; }

    for (int t0 = 0; t0 < 2048; t0 += 64) {
#pragma unroll
        for (int i = 0; i < 8; i++) {        // K (transposed) + V tiles
            int flat = tid + (i << 7);
            int row = flat >> 4, c4 = (flat & 15) << 2;
            float4 kv = *(const float4*)&kh[(kv0 + t0 + row) * 1024 + hoff + c4];
            Ks[(c4 + 0) * KS_LD + row] = kv.x;
            Ks[(c4 + 1) * KS_LD + row] = kv.y;
            Ks[(c4 + 2) * KS_LD + row] = kv.z;
            Ks[(c4 + 3) * KS_LD + row] = kv.w;
            float4 vv = *(const float4*)&vh[(kv0 + t0 + row) * 1024 + hoff + c4];
            *(float4*)&Vs[row * KS_LD + c4] = vv;
        }
        __syncthreads();

        ull s2[4][8];
#pragma unroll
        for (int rp = 0; rp < 4; rp++)
#pragma unroll
            for (int c = 0; c < 8; c++) s2[rp][c] = 0ull;

#pragma unroll 8
        for (int kk = 0; kk < 64; kk++) {    // S = (Q/8) K^T
            float4 qa = *(const float4*)&Qs[kk * QS_LD + (ty << 3)];
            float4 qb = *(const float4*)&Qs[kk * QS_LD + (ty << 3) + 4];
            float4 ka = *(const float4*)&Ks[kk * KS_LD + (tx << 3)];
            float4 kb = *(const float4*)&Ks[kk * KS_LD + (tx << 3) + 4];
            ull qp[4] = { pack2(qa.x, qa.y), pack2(qa.z, qa.w),
                          pack2(qb.x, qb.y), pack2(qb.z, qb.w) };
            float kvv[8] = { ka.x, ka.y, ka.z, ka.w, kb.x, kb.y, kb.z, kb.w };
#pragma unroll
            for (int c = 0; c < 8; c++) {
                ull kp = pack2(kvv[c], kvv[c]);
#pragma unroll
                for (int rp = 0; rp < 4; rp++) ffma2(s2[rp][c], qp[rp], kp);
            }
        }

        float sv[8][8];                      // online softmax
#pragma unroll
        for (int rp = 0; rp < 4; rp++)
#pragma unroll
            for (int c = 0; c < 8; c++) {
                float2 f = unpack2(s2[rp][c]);
                sv[2 * rp][c] = f.x; sv[2 * rp + 1][c] = f.y;
            }
        float corr[8];
#pragma unroll
        for (int r = 0; r < 8; r++) {
            float rm = sv[r][0];
#pragma unroll
            for (int c = 1; c < 8; c++) rm = fmaxf(rm, sv[r][c]);
            rm = fmaxf(rm, __shfl_xor_sync(0xffffffffu, rm, 1));
            rm = fmaxf(rm, __shfl_xor_sync(0xffffffffu, rm, 2));
            rm = fmaxf(rm, __shfl_xor_sync(0xffffffffu, rm, 4));
            float nm = fmaxf(mrow[r], rm);
            corr[r] = __expf(mrow[r] - nm);
            float rs = 0.f;
#pragma unroll
            for (int c = 0; c < 8; c++) {
                float p = __expf(sv[r][c] - nm);
                sv[r][c] = p; rs += p;
            }
            rs += __shfl_xor_sync(0xffffffffu, rs, 1);
            rs += __shfl_xor_sync(0xffffffffu, rs, 2);
            rs += __shfl_xor_sync(0xffffffffu, rs, 4);
            lrow[r] = lrow[r] * corr[r] + rs;
            mrow[r] = nm;
        }
#pragma unroll
        for (int rp = 0; rp < 4; rp++) {
            ull cp = pack2(corr[2 * rp], corr[2 * rp + 1]);
#pragma unroll
            for (int c = 0; c < 8; c++) fmul2(o2[rp][c], cp);
        }
#pragma unroll
        for (int c = 0; c < 8; c++)          // P transposed [key][qrow]
#pragma unroll
            for (int rp = 0; rp < 4; rp++)
                *(float2*)&Ps[((tx << 3) + c) * QS_LD + (ty << 3) + (rp << 1)] =
                    make_float2(sv[2 * rp][c], sv[2 * rp + 1][c]);
        __syncthreads();

#pragma unroll 8
        for (int j = 0; j < 64; j++) {       // O += P V
            float4 pa = *(const float4*)&Ps[j * QS_LD + (ty << 3)];
            float4 pb = *(const float4*)&Ps[j * QS_LD + (ty << 3) + 4];
            float4 va = *(const float4*)&Vs[j * KS_LD + (tx << 3)];
            float4 vb = *(const float4*)&Vs[j * KS_LD + (tx << 3) + 4];
            ull pp[4] = { pack2(pa.x, pa.y), pack2(pa.z, pa.w),
                          pack2(pb.x, pb.y), pack2(pb.z, pb.w) };
            float vvv[8] = { va.x, va.y, va.z, va.w, vb.x, vb.y, vb.z, vb.w };
#pragma unroll
            for (int c = 0; c < 8; c++) {
                ull vp = pack2(vvv[c], vvv[c]);
#pragma unroll
                for (int rp = 0; rp < 4; rp++) ffma2(o2[rp][c], pp[rp], vp);
            }
        }
        __syncthreads();
    }

#pragma unroll
    for (int r = 0; r < 8; r++) {            // normalize, write ctx
        float inv = 1.0f / lrow[r];
        float ov[8];
#pragma unroll
        for (int c = 0; c < 8; c++) {
            float2 f = unpack2(o2[r >> 1][c]);
            ov[c] = ((r & 1) ? f.y : f.x) * inv;
        }
        float4* dst = (float4*)&ctx[(m0 + (ty << 3) + r) * 1024 + hoff + (tx << 3)];
        dst[0] = make_float4(ov[0], ov[1], ov[2], ov[3]);
        dst[1] = make_float4(ov[4], ov[5], ov[6], ov[7]);
    }
}

extern "C" void kernel_launch(void* const* d_in, const int* in_sizes, int n_in,
                              void* d_out, int out_size) {
    const float* q   = (const float*)d_in[0];
    const float* k   = (const float*)d_in[1];
    const float* v   = (const float*)d_in[2];
    const float* Wq  = (const float*)d_in[3];
    const float* Wk  = (const float*)d_in[4];
    const float* Wv  = (const float*)d_in[5];
    const float* Wo  = (const float*)d_in[6];
    const float* bo  = (const float*)d_in[7];
    float* out = (float*)d_out;

    pack_kernel<<<16384, 256>>>(Wq, Wk, Wv, Wo);

    dim3 gp(8, 32, 3);
    proj3_kernel<<<gp, 256>>>(q, k, v);

    cudaFuncSetAttribute(attn_kernel, cudaFuncAttributeMaxDynamicSharedMemorySize, 102400);
    dim3 ga(16, 32);
    attn_kernel<<<ga, 128, 102400>>>();

    dim3 go(8, 32);
    outproj_kernel<<<go, 256>>>(bo, out);
}

// round 5
// speedup vs baseline: 1.0973x; 1.0973x over previous
#include <cuda_runtime.h>
#include <cuda_bf16.h>

typedef unsigned long long ull;
typedef unsigned int u32;

// ================= f32x2 helpers (attention) =================
__device__ __forceinline__ ull pack2(float x, float y) {
    ull r; asm("mov.b64 %0, {%1, %2};" : "=l"(r) : "f"(x), "f"(y)); return r;
}
__device__ __forceinline__ float2 unpack2(ull v) {
    float2 f; asm("mov.b64 {%0, %1}, %2;" : "=f"(f.x), "=f"(f.y) : "l"(v)); return f;
}
__device__ __forceinline__ void ffma2(ull& d, ull a, ull b) {
    asm("fma.rn.f32x2 %0, %1, %2, %0;" : "+l"(d) : "l"(a), "l"(b));
}
__device__ __forceinline__ void fmul2(ull& d, ull a) {
    asm("mul.rn.f32x2 %0, %0, %1;" : "+l"(d) : "l"(a));
}

// ================= mma.sync / ldmatrix / cp.async =================
__device__ __forceinline__ u32 smem_to_u32(const void* p) {
    u32 a; asm("{ .reg .u64 t; cvta.to.shared.u64 t, %1; cvt.u32.u64 %0, t; }" : "=r"(a) : "l"(p));
    return a;
}
#define CP_ASYNC16(dst, src) asm volatile("cp.async.cg.shared.global [%0], [%1], 16;" :: "r"(dst), "l"(src) : "memory")
#define CP_COMMIT()          asm volatile("cp.async.commit_group;" ::: "memory")
#define CP_WAIT0()           asm volatile("cp.async.wait_group 0;" ::: "memory")
#define CP_WAIT1()           asm volatile("cp.async.wait_group 1;" ::: "memory")

#define LDMX4(r, addr) \
    asm volatile("ldmatrix.sync.aligned.m8n8.x4.shared.b16 {%0,%1,%2,%3}, [%4];" \
        : "=r"((r)[0]), "=r"((r)[1]), "=r"((r)[2]), "=r"((r)[3]) : "r"(addr))

__device__ __forceinline__ void mma16816(float* c, const u32* a, u32 b0, u32 b1) {
    asm volatile("mma.sync.aligned.m16n8k16.row.col.f32.bf16.bf16.f32 "
        "{%0,%1,%2,%3}, {%4,%5,%6,%7}, {%8,%9}, {%0,%1,%2,%3};"
        : "+f"(c[0]), "+f"(c[1]), "+f"(c[2]), "+f"(c[3])
        : "r"(a[0]), "r"(a[1]), "r"(a[2]), "r"(a[3]), "r"(b0), "r"(b1));
}

// ================= global scratch =================
__device__ float g_heads[3][4194304];                         // qh, kh, vh fp32
__device__ __align__(256) __nv_bfloat16 g_as[3][3][4194304];  // q/k/v splits [mat][split][m*1024+k]
__device__ __align__(256) __nv_bfloat16 g_bs[4][3][1048576];  // weight splits [mat][split][n*1024+k]
__device__ __align__(256) __nv_bfloat16 g_cs[2][4194304];     // ctx 2-splits

// pair tables: first 3 pairs for 2-split mats, all 6 for 3-split mats
__constant__ int c_pa[6] = { 0, 0, 1, 0, 2, 1 };
__constant__ int c_pb[6] = { 0, 1, 0, 2, 0, 1 };

// ================= split helpers =================
__device__ __forceinline__ void split3(float x, __nv_bfloat16& h, __nv_bfloat16& m, __nv_bfloat16& l) {
    h = __float2bfloat16(x);
    float r1 = x - __bfloat162float(h);
    m = __float2bfloat16(r1);
    float r2 = r1 - __bfloat162float(m);
    l = __float2bfloat16(r2);
}
__device__ __forceinline__ u32 pk2(__nv_bfloat16 a, __nv_bfloat16 b) {
    __nv_bfloat162 t = __halves2bfloat162(a, b);
    return *reinterpret_cast<u32*>(&t);
}

__global__ void split_qkv_kernel(const float* __restrict__ q, const float* __restrict__ k,
                                 const float* __restrict__ v) {
    u32 idx = blockIdx.x * 256u + threadIdx.x;     // [0, 1M) float4s
    int y = blockIdx.y;
    const float* in = (y == 0) ? q : (y == 1) ? k : v;
    float4 x = ((const float4*)in)[idx];
    float xs[4] = { x.x, x.y, x.z, x.w };
    __nv_bfloat16 h[4], m[4], l[4];
#pragma unroll
    for (int j = 0; j < 4; j++) split3(xs[j], h[j], m[j], l[j]);
    u32 o = idx * 4u;
    *(uint2*)&g_as[y][0][o] = make_uint2(pk2(h[0], h[1]), pk2(h[2], h[3]));
    *(uint2*)&g_as[y][1][o] = make_uint2(pk2(m[0], m[1]), pk2(m[2], m[3]));
    *(uint2*)&g_as[y][2][o] = make_uint2(pk2(l[0], l[1]), pk2(l[2], l[3]));
}

// Wq/Wk/Wv [h, d, kk] -> B[n=h*64+kk][k=d] splits
__global__ void split_w3_kernel(const float* __restrict__ Wq, const float* __restrict__ Wk,
                                const float* __restrict__ Wv) {
    u32 idx = blockIdx.x * 256u + threadIdx.x;     // [0, 786432)
    u32 mat = idx >> 18, r = idx & 262143u;
    u32 n = r >> 8, d4 = r & 255u;
    u32 h = n >> 6, kk = n & 63u;
    const float* W = (mat == 0) ? Wq : (mat == 1) ? Wk : Wv;
    __nv_bfloat16 hh[4], mm[4], ll[4];
#pragma unroll
    for (int j = 0; j < 4; j++) {
        float x = W[h * 65536u + (d4 * 4u + j) * 64u + kk];
        split3(x, hh[j], mm[j], ll[j]);
    }
    u32 o = n * 1024u + d4 * 4u;
    *(uint2*)&g_bs[mat][0][o] = make_uint2(pk2(hh[0], hh[1]), pk2(hh[2], hh[3]));
    *(uint2*)&g_bs[mat][1][o] = make_uint2(pk2(mm[0], mm[1]), pk2(mm[2], mm[3]));
    *(uint2*)&g_bs[mat][2][o] = make_uint2(pk2(ll[0], ll[1]), pk2(ll[2], ll[3]));
}

__global__ void split_wo_kernel(const float* __restrict__ Wo) {
    u32 idx = blockIdx.x * 256u + threadIdx.x;     // [0, 262144) float4s
    float4 x = ((const float4*)Wo)[idx];
    float xs[4] = { x.x, x.y, x.z, x.w };
    __nv_bfloat16 h[4], m[4], l[4];
#pragma unroll
    for (int j = 0; j < 4; j++) split3(xs[j], h[j], m[j], l[j]);
    u32 o = idx * 4u;
    *(uint2*)&g_bs[3][0][o] = make_uint2(pk2(h[0], h[1]), pk2(h[2], h[3]));
    *(uint2*)&g_bs[3][1][o] = make_uint2(pk2(m[0], m[1]), pk2(m[2], m[3]));
    *(uint2*)&g_bs[3][2][o] = make_uint2(pk2(l[0], l[1]), pk2(l[2], l[3]));
}

// ================= mma.sync split-fp32 GEMM =================
// C[4096x1024] = sum_pairs A_s[m][k] * B_s[n][k]^T. Block 128x128, BK=32 bf16,
// 8 warps (2m x 4n), warp tile 64x32, double-buffered cp.async.
// smem tile: 128 rows, pitch 40 bf16 (80B) -> conflict-free ldmatrix (stride 5 chunks).
#define GP 40u          // smem pitch in bf16
#define TILE_B 10240u   // 128 * 80 bytes
#define STAGE_B 20480u  // A + B tile
#define ASPLIT 8388608ull   // bytes between A splits (4M bf16)
#define BSPLIT 2097152ull   // bytes between B splits (1M bf16)

__device__ __forceinline__ void gemm_issue(const char* aB, const char* bB, u32 smem_base,
                                           int v, int s, u32 bm, u32 bn, int tid) {
    int p = v >> 5;
    u32 kb = (u32)(v & 31) * 64u;
    const char* srcA = aB + (ull)c_pa[p] * ASPLIT + kb;
    const char* srcB = bB + (ull)c_pb[p] * BSPLIT + kb;
    u32 stA = smem_base + (u32)s * STAGE_B;
    u32 stB = stA + TILE_B;
#pragma unroll
    for (int j = 0; j < 2; j++) {
        u32 c = (u32)tid + (u32)j * 256u;
        u32 row = c >> 2, c16 = (c & 3u) * 16u;
        CP_ASYNC16(stA + row * 80u + c16, srcA + (ull)(bm + row) * 2048ull + c16);
        CP_ASYNC16(stB + row * 80u + c16, srcB + (ull)(bn + row) * 2048ull + c16);
    }
    CP_COMMIT();
}

__global__ void __launch_bounds__(256) gemm_mma_kernel(int mat_base, float* Cout,
                                                       const float* __restrict__ bias) {
    __shared__ __align__(128) char sm_g[2 * STAGE_B];
    const int tid = threadIdx.x, lane = tid & 31, wid = tid >> 5;
    const u32 bm = blockIdx.y << 7, bn = blockIdx.x << 7;
    const int wm = (wid >> 2) << 6, wn = (wid & 3) << 5;
    const int mat = mat_base + blockIdx.z;
    const int npairs = (mat <= 1) ? 6 : 3;

    const char* aB; const char* bB; float* C;
    if (mat < 3) { aB = (const char*)g_as[mat][0]; bB = (const char*)g_bs[mat][0]; C = g_heads[mat]; }
    else         { aB = (const char*)g_cs[0];      bB = (const char*)g_bs[3][0];   C = Cout; }

    u32 smem_base = smem_to_u32(sm_g);

    float acc[4][4][4];
#pragma unroll
    for (int mi = 0; mi < 4; mi++)
#pragma unroll
        for (int ni = 0; ni < 4; ni++)
#pragma unroll
            for (int e = 0; e < 4; e++) acc[mi][ni][e] = 0.f;

    const int NV = npairs * 32;
    gemm_issue(aB, bB, smem_base, 0, 0, bm, bn, tid);

    for (int v = 0; v < NV; v++) {
        if (v + 1 < NV) { gemm_issue(aB, bB, smem_base, v + 1, (v + 1) & 1, bm, bn, tid); CP_WAIT1(); }
        else            { CP_WAIT0(); }
        __syncthreads();

        u32 stA = smem_base + (u32)(v & 1) * STAGE_B;
        u32 stB = stA + TILE_B;
        u32 arow = (u32)(lane & 15) * 80u + (u32)(lane >> 4) * 16u;
#pragma unroll
        for (int ks = 0; ks < 2; ks++) {
            u32 a[4][4], b[2][4];
            u32 abase = stA + (u32)wm * 80u + arow + (u32)ks * 32u;
            u32 bbase = stB + (u32)wn * 80u + arow + (u32)ks * 32u;
#pragma unroll
            for (int mi = 0; mi < 4; mi++) LDMX4(a[mi], abase + (u32)mi * (16u * 80u));
#pragma unroll
            for (int nj = 0; nj < 2; nj++) LDMX4(b[nj], bbase + (u32)nj * (16u * 80u));
#pragma unroll
            for (int mi = 0; mi < 4; mi++)
#pragma unroll
                for (int ni = 0; ni < 4; ni++)
                    mma16816(acc[mi][ni], a[mi], b[ni >> 1][ni & 1], b[ni >> 1][(ni & 1) + 2]);
        }
        __syncthreads();
    }

#pragma unroll
    for (int mi = 0; mi < 4; mi++)
#pragma unroll
        for (int ni = 0; ni < 4; ni++) {
            u32 r0 = bm + (u32)wm + (u32)mi * 16u + (u32)(lane >> 2);
            u32 col = bn + (u32)wn + (u32)ni * 8u + (u32)((lane & 3) << 1);
            float b0 = 0.f, b1 = 0.f;
            if (bias) { b0 = bias[col]; b1 = bias[col + 1]; }
            *(float2*)&C[(ull)r0 * 1024ull + col] =
                make_float2(acc[mi][ni][0] + b0, acc[mi][ni][1] + b1);
            *(float2*)&C[(ull)(r0 + 8) * 1024ull + col] =
                make_float2(acc[mi][ni][2] + b0, acc[mi][ni][3] + b1);
        }
}

// ================= flash attention fp32 (split epilogue) =================
#define QS_LD 132
#define KS_LD 68

__global__ void __launch_bounds__(128) attn_kernel() {
    extern __shared__ float sm[];
    float* Qs = sm;
    float* Ks = sm + 8448;
    float* Vs = sm + 12800;
    float* Ps = sm + 17152;

    const int tid = threadIdx.x;
    const int ty = tid >> 3, tx = tid & 7;
    const int b = blockIdx.y >> 4, h = blockIdx.y & 15;
    const int hoff = h << 6;
    const int m0 = b * 2048 + (blockIdx.x << 7);
    const int kv0 = b * 2048;

    const float* qh = g_heads[0];
    const float* kh = g_heads[1];
    const float* vh = g_heads[2];

#pragma unroll
    for (int i = 0; i < 16; i++) {
        int flat = tid + (i << 7);
        int row = flat >> 4, c4 = (flat & 15) << 2;
        float4 qv = *(const float4*)&qh[(m0 + row) * 1024 + hoff + c4];
        Qs[(c4 + 0) * QS_LD + row] = qv.x * 0.125f;
        Qs[(c4 + 1) * QS_LD + row] = qv.y * 0.125f;
        Qs[(c4 + 2) * QS_LD + row] = qv.z * 0.125f;
        Qs[(c4 + 3) * QS_LD + row] = qv.w * 0.125f;
    }

    ull o2[4][8];
#pragma unroll
    for (int rp = 0; rp < 4; rp++)
#pragma unroll
        for (int c = 0; c < 8; c++) o2[rp][c] = 0ull;
    float mrow[8], lrow[8];
#pragma unroll
    for (int r = 0; r < 8; r++) { mrow[r] = -1e30f; lrow[r] = 0.f; }

    for (int t0 = 0; t0 < 2048; t0 += 64) {
#pragma unroll
        for (int i = 0; i < 8; i++) {
            int flat = tid + (i << 7);
            int row = flat >> 4, c4 = (flat & 15) << 2;
            float4 kv = *(const float4*)&kh[(kv0 + t0 + row) * 1024 + hoff + c4];
            Ks[(c4 + 0) * KS_LD + row] = kv.x;
            Ks[(c4 + 1) * KS_LD + row] = kv.y;
            Ks[(c4 + 2) * KS_LD + row] = kv.z;
            Ks[(c4 + 3) * KS_LD + row] = kv.w;
            float4 vv = *(const float4*)&vh[(kv0 + t0 + row) * 1024 + hoff + c4];
            *(float4*)&Vs[row * KS_LD + c4] = vv;
        }
        __syncthreads();

        ull s2[4][8];
#pragma unroll
        for (int rp = 0; rp < 4; rp++)
#pragma unroll
            for (int c = 0; c < 8; c++) s2[rp][c] = 0ull;

#pragma unroll 8
        for (int kk = 0; kk < 64; kk++) {
            float4 qa = *(const float4*)&Qs[kk * QS_LD + (ty << 3)];
            float4 qb = *(const float4*)&Qs[kk * QS_LD + (ty << 3) + 4];
            float4 ka = *(const float4*)&Ks[kk * KS_LD + (tx << 3)];
            float4 kb = *(const float4*)&Ks[kk * KS_LD + (tx << 3) + 4];
            ull qp[4] = { pack2(qa.x, qa.y), pack2(qa.z, qa.w),
                          pack2(qb.x, qb.y), pack2(qb.z, qb.w) };
            float kvv[8] = { ka.x, ka.y, ka.z, ka.w, kb.x, kb.y, kb.z, kb.w };
#pragma unroll
            for (int c = 0; c < 8; c++) {
                ull kp = pack2(kvv[c], kvv[c]);
#pragma unroll
                for (int rp = 0; rp < 4; rp++) ffma2(s2[rp][c], qp[rp], kp);
            }
        }

        float sv[8][8];
#pragma unroll
        for (int rp = 0; rp < 4; rp++)
#pragma unroll
            for (int c = 0; c < 8; c++) {
                float2 f = unpack2(s2[rp][c]);
                sv[2 * rp][c] = f.x; sv[2 * rp + 1][c] = f.y;
            }
        float corr[8];
#pragma unroll
        for (int r = 0; r < 8; r++) {
            float rm = sv[r][0];
#pragma unroll
            for (int c = 1; c < 8; c++) rm = fmaxf(rm, sv[r][c]);
            rm = fmaxf(rm, __shfl_xor_sync(0xffffffffu, rm, 1));
            rm = fmaxf(rm, __shfl_xor_sync(0xffffffffu, rm, 2));
            rm = fmaxf(rm, __shfl_xor_sync(0xffffffffu, rm, 4));
            float nm = fmaxf(mrow[r], rm);
            corr[r] = __expf(mrow[r] - nm);
            float rs = 0.f;
#pragma unroll
            for (int c = 0; c < 8; c++) {
                float p = __expf(sv[r][c] - nm);
                sv[r][c] = p; rs += p;
            }
            rs += __shfl_xor_sync(0xffffffffu, rs, 1);
            rs += __shfl_xor_sync(0xffffffffu, rs, 2);
            rs += __shfl_xor_sync(0xffffffffu, rs, 4);
            lrow[r] = lrow[r] * corr[r] + rs;
            mrow[r] = nm;
        }
#pragma unroll
        for (int rp = 0; rp < 4; rp++) {
            ull cp = pack2(corr[2 * rp], corr[2 * rp + 1]);
#pragma unroll
            for (int c = 0; c < 8; c++) fmul2(o2[rp][c], cp);
        }
#pragma unroll
        for (int c = 0; c < 8; c++)
#pragma unroll
            for (int rp = 0; rp < 4; rp++)
                *(float2*)&Ps[((tx << 3) + c) * QS_LD + (ty << 3) + (rp << 1)] =
                    make_float2(sv[2 * rp][c], sv[2 * rp + 1][c]);
        __syncthreads();

#pragma unroll 8
        for (int j = 0; j < 64; j++) {
            float4 pa = *(const float4*)&Ps[j * QS_LD + (ty << 3)];
            float4 pb = *(const float4*)&Ps[j * QS_LD + (ty << 3) + 4];
            float4 va = *(const float4*)&Vs[j * KS_LD + (tx << 3)];
            float4 vb = *(const float4*)&Vs[j * KS_LD + (tx << 3) + 4];
            ull pp[4] = { pack2(pa.x, pa.y), pack2(pa.z, pa.w),
                          pack2(pb.x, pb.y), pack2(pb.z, pb.w) };
            float vvv[8] = { va.x, va.y, va.z, va.w, vb.x, vb.y, vb.z, vb.w };
#pragma unroll
            for (int c = 0; c < 8; c++) {
                ull vp = pack2(vvv[c], vvv[c]);
#pragma unroll
                for (int rp = 0; rp < 4; rp++) ffma2(o2[rp][c], pp[rp], vp);
            }
        }
        __syncthreads();
    }

    // epilogue: normalize + write ctx as 2 bf16 splits
#pragma unroll
    for (int r = 0; r < 8; r++) {
        float inv = 1.0f / lrow[r];
        u32 ph[4], pm[4];
#pragma unroll
        for (int c2 = 0; c2 < 4; c2++) {
            float2 fa = unpack2(o2[r >> 1][c2 * 2]);
            float2 fb = unpack2(o2[r >> 1][c2 * 2 + 1]);
            float xa = ((r & 1) ? fa.y : fa.x) * inv;
            float xb = ((r & 1) ? fb.y : fb.x) * inv;
            __nv_bfloat16 ha = __float2bfloat16(xa);
            __nv_bfloat16 ma = __float2bfloat16(xa - __bfloat162float(ha));
            __nv_bfloat16 hb = __float2bfloat16(xb);
            __nv_bfloat16 mb = __float2bfloat16(xb - __bfloat162float(hb));
            ph[c2] = pk2(ha, hb); pm[c2] = pk2(ma, mb);
        }
        u32 off = (u32)(m0 + (ty << 3) + r) * 1024u + hoff + (tx << 3);
        *(uint4*)&g_cs[0][off] = make_uint4(ph[0], ph[1], ph[2], ph[3]);
        *(uint4*)&g_cs[1][off] = make_uint4(pm[0], pm[1], pm[2], pm[3]);
    }
}

// ================= launch =================
extern "C" void kernel_launch(void* const* d_in, const int* in_sizes, int n_in,
                              void* d_out, int out_size) {
    const float* q  = (const float*)d_in[0];
    const float* k  = (const float*)d_in[1];
    const float* v  = (const float*)d_in[2];
    const float* Wq = (const float*)d_in[3];
    const float* Wk = (const float*)d_in[4];
    const float* Wv = (const float*)d_in[5];
    const float* Wo = (const float*)d_in[6];
    const float* bo = (const float*)d_in[7];
    float* out = (float*)d_out;

    split_qkv_kernel<<<dim3(4096, 3), 256>>>(q, k, v);
    split_w3_kernel<<<3072, 256>>>(Wq, Wk, Wv);
    split_wo_kernel<<<1024, 256>>>(Wo);

    gemm_mma_kernel<<<dim3(8, 32, 3), 256>>>(0, nullptr, nullptr);

    cudaFuncSetAttribute(attn_kernel, cudaFuncAttributeMaxDynamicSharedMemorySize, 102400);
    attn_kernel<<<dim3(16, 32), 128, 102400>>>();

    gemm_mma_kernel<<<dim3(8, 32, 1), 256>>>(3, out, bo);
}

// round 6
// speedup vs baseline: 1.6269x; 1.4826x over previous
#include <cuda_runtime.h>
#include <cuda_bf16.h>

typedef unsigned long long ull;
typedef unsigned int u32;

// ================= common helpers =================
__device__ __forceinline__ u32 smem_to_u32(const void* p) {
    u32 a; asm("{ .reg .u64 t; cvta.to.shared.u64 t, %1; cvt.u32.u64 %0, t; }" : "=r"(a) : "l"(p));
    return a;
}
#define CP_ASYNC16(dst, src) asm volatile("cp.async.cg.shared.global [%0], [%1], 16;" :: "r"(dst), "l"(src) : "memory")
#define CP_COMMIT()          asm volatile("cp.async.commit_group;" ::: "memory")
#define CP_WAIT0()           asm volatile("cp.async.wait_group 0;" ::: "memory")
#define CP_WAIT1()           asm volatile("cp.async.wait_group 1;" ::: "memory")

#define LDMX4(r, addr) \
    asm volatile("ldmatrix.sync.aligned.m8n8.x4.shared.b16 {%0,%1,%2,%3}, [%4];" \
        : "=r"((r)[0]), "=r"((r)[1]), "=r"((r)[2]), "=r"((r)[3]) : "r"(addr))
#define LDMX4T(r, addr) \
    asm volatile("ldmatrix.sync.aligned.m8n8.x4.trans.shared.b16 {%0,%1,%2,%3}, [%4];" \
        : "=r"((r)[0]), "=r"((r)[1]), "=r"((r)[2]), "=r"((r)[3]) : "r"(addr))

__device__ __forceinline__ void mma16816(float* c, const u32* a, u32 b0, u32 b1) {
    asm volatile("mma.sync.aligned.m16n8k16.row.col.f32.bf16.bf16.f32 "
        "{%0,%1,%2,%3}, {%4,%5,%6,%7}, {%8,%9}, {%0,%1,%2,%3};"
        : "+f"(c[0]), "+f"(c[1]), "+f"(c[2]), "+f"(c[3])
        : "r"(a[0]), "r"(a[1]), "r"(a[2]), "r"(a[3]), "r"(b0), "r"(b1));
}

// ================= global scratch =================
__device__ __align__(256) __nv_bfloat16 g_as[3][3][4194304];  // input splits [mat][split][m*1024+k]
__device__ __align__(256) __nv_bfloat16 g_bs[4][3][1048576];  // weight splits [mat][split][n*1024+k]
__device__ __align__(256) __nv_bfloat16 g_qs[3][4194304];     // qh 3-split (prescaled 1/8)
__device__ __align__(256) __nv_bfloat16 g_ks[3][4194304];     // kh 3-split
__device__ __align__(256) __nv_bfloat16 g_vs[2][4194304];     // vh 2-split
__device__ __align__(256) __nv_bfloat16 g_cs[2][4194304];     // ctx 2-split

__constant__ int c_pa[6] = { 0, 0, 1, 0, 2, 1 };
__constant__ int c_pb[6] = { 0, 1, 0, 2, 0, 1 };

// ================= split helpers =================
__device__ __forceinline__ void split3(float x, __nv_bfloat16& h, __nv_bfloat16& m, __nv_bfloat16& l) {
    h = __float2bfloat16(x);
    float r1 = x - __bfloat162float(h);
    m = __float2bfloat16(r1);
    float r2 = r1 - __bfloat162float(m);
    l = __float2bfloat16(r2);
}
__device__ __forceinline__ u32 pk2(__nv_bfloat16 a, __nv_bfloat16 b) {
    __nv_bfloat162 t = __halves2bfloat162(a, b);
    return *reinterpret_cast<u32*>(&t);
}
__device__ __forceinline__ void split2pk(float x, float y, u32& hi, u32& lo) {
    __nv_bfloat16 hx = __float2bfloat16(x), hy = __float2bfloat16(y);
    __nv_bfloat16 mx = __float2bfloat16(x - __bfloat162float(hx));
    __nv_bfloat16 my = __float2bfloat16(y - __bfloat162float(hy));
    hi = pk2(hx, hy); lo = pk2(mx, my);
}
__device__ __forceinline__ void split3pk(float x, float y, u32& h, u32& m, u32& l) {
    __nv_bfloat16 hx, mx, lx, hy, my, ly;
    split3(x, hx, mx, lx); split3(y, hy, my, ly);
    h = pk2(hx, hy); m = pk2(mx, my); l = pk2(lx, ly);
}

// ================= input split kernels =================
__global__ void split_qkv_kernel(const float* __restrict__ q, const float* __restrict__ k,
                                 const float* __restrict__ v) {
    u32 idx = blockIdx.x * 256u + threadIdx.x;
    int y = blockIdx.y;
    const float* in = (y == 0) ? q : (y == 1) ? k : v;
    float4 x = ((const float4*)in)[idx];
    float xs[4] = { x.x, x.y, x.z, x.w };
    __nv_bfloat16 h[4], m[4], l[4];
#pragma unroll
    for (int j = 0; j < 4; j++) split3(xs[j], h[j], m[j], l[j]);
    u32 o = idx * 4u;
    *(uint2*)&g_as[y][0][o] = make_uint2(pk2(h[0], h[1]), pk2(h[2], h[3]));
    *(uint2*)&g_as[y][1][o] = make_uint2(pk2(m[0], m[1]), pk2(m[2], m[3]));
    *(uint2*)&g_as[y][2][o] = make_uint2(pk2(l[0], l[1]), pk2(l[2], l[3]));
}

__global__ void split_w3_kernel(const float* __restrict__ Wq, const float* __restrict__ Wk,
                                const float* __restrict__ Wv) {
    u32 idx = blockIdx.x * 256u + threadIdx.x;
    u32 mat = idx >> 18, r = idx & 262143u;
    u32 n = r >> 8, d4 = r & 255u;
    u32 h = n >> 6, kk = n & 63u;
    const float* W = (mat == 0) ? Wq : (mat == 1) ? Wk : Wv;
    __nv_bfloat16 hh[4], mm[4], ll[4];
#pragma unroll
    for (int j = 0; j < 4; j++) {
        float x = W[h * 65536u + (d4 * 4u + j) * 64u + kk];
        split3(x, hh[j], mm[j], ll[j]);
    }
    u32 o = n * 1024u + d4 * 4u;
    *(uint2*)&g_bs[mat][0][o] = make_uint2(pk2(hh[0], hh[1]), pk2(hh[2], hh[3]));
    *(uint2*)&g_bs[mat][1][o] = make_uint2(pk2(mm[0], mm[1]), pk2(mm[2], mm[3]));
    *(uint2*)&g_bs[mat][2][o] = make_uint2(pk2(ll[0], ll[1]), pk2(ll[2], ll[3]));
}

__global__ void split_wo_kernel(const float* __restrict__ Wo) {
    u32 idx = blockIdx.x * 256u + threadIdx.x;
    float4 x = ((const float4*)Wo)[idx];
    float xs[4] = { x.x, x.y, x.z, x.w };
    __nv_bfloat16 h[4], m[4], l[4];
#pragma unroll
    for (int j = 0; j < 4; j++) split3(xs[j], h[j], m[j], l[j]);
    u32 o = idx * 4u;
    *(uint2*)&g_bs[3][0][o] = make_uint2(pk2(h[0], h[1]), pk2(h[2], h[3]));
    *(uint2*)&g_bs[3][1][o] = make_uint2(pk2(m[0], m[1]), pk2(m[2], m[3]));
    *(uint2*)&g_bs[3][2][o] = make_uint2(pk2(l[0], l[1]), pk2(l[2], l[3]));
}

// ================= mma.sync split-fp32 GEMM (BK=64) =================
// Block 128x128, 8 warps (2m x 4n), warp tile 64x32, double-buffered cp.async.
// smem rows pitch 72 bf16 = 144B (9 x 16B chunks, odd -> conflict-free ldmatrix).
#define GPITCH 144u
#define GTILE  18432u        // 128 * 144
#define GSTAGE 36864u        // A + B
#define ASPLIT 8388608ull
#define BSPLIT 2097152ull

__device__ __forceinline__ void gemm_issue(const char* aB, const char* bB, u32 base,
                                           int v, int s, u32 bm, u32 bn, int tid) {
    int p = v >> 4;
    u32 kb = (u32)(v & 15) * 128u;
    const char* srcA = aB + (ull)c_pa[p] * ASPLIT + kb;
    const char* srcB = bB + (ull)c_pb[p] * BSPLIT + kb;
    u32 stA = base + (u32)s * GSTAGE;
    u32 stB = stA + GTILE;
#pragma unroll
    for (int j = 0; j < 4; j++) {
        u32 c = (u32)tid + (u32)j * 256u;
        u32 row = c >> 3, ch = (c & 7u) << 4;
        CP_ASYNC16(stA + row * GPITCH + ch, srcA + (ull)(bm + row) * 2048ull + ch);
        CP_ASYNC16(stB + row * GPITCH + ch, srcB + (ull)(bn + row) * 2048ull + ch);
    }
    CP_COMMIT();
}

__global__ void __launch_bounds__(256) gemm_mma_kernel(int mat_base, float* Cout,
                                                       const float* __restrict__ bias) {
    extern __shared__ char sm_g[];
    u32 base = smem_to_u32(sm_g);
    const int tid = threadIdx.x, lane = tid & 31, wid = tid >> 5;
    const u32 bm = blockIdx.y << 7, bn = blockIdx.x << 7;
    const int wm = (wid >> 2) << 6, wn = (wid & 3) << 5;
    const int mat = mat_base + blockIdx.z;
    const int npairs = (mat <= 1) ? 6 : 3;

    const char* aB; const char* bB;
    if (mat < 3) { aB = (const char*)g_as[mat][0]; bB = (const char*)g_bs[mat][0]; }
    else         { aB = (const char*)g_cs[0];      bB = (const char*)g_bs[3][0]; }

    float acc[4][4][4];
#pragma unroll
    for (int mi = 0; mi < 4; mi++)
#pragma unroll
        for (int ni = 0; ni < 4; ni++)
#pragma unroll
            for (int e = 0; e < 4; e++) acc[mi][ni][e] = 0.f;

    const int NV = npairs * 16;
    gemm_issue(aB, bB, base, 0, 0, bm, bn, tid);

    for (int v = 0; v < NV; v++) {
        if (v + 1 < NV) { gemm_issue(aB, bB, base, v + 1, (v + 1) & 1, bm, bn, tid); CP_WAIT1(); }
        else            { CP_WAIT0(); }
        __syncthreads();

        u32 stA = base + (u32)(v & 1) * GSTAGE;
        u32 stB = stA + GTILE;
        u32 lrow = (u32)(lane & 15) * GPITCH + (u32)(lane >> 4) * 16u;
#pragma unroll
        for (int ks = 0; ks < 4; ks++) {
            u32 a[4][4], b[2][4];
            u32 abase = stA + (u32)wm * GPITCH + lrow + (u32)ks * 32u;
            u32 bbase = stB + (u32)wn * GPITCH + lrow + (u32)ks * 32u;
#pragma unroll
            for (int mi = 0; mi < 4; mi++) LDMX4(a[mi], abase + (u32)mi * (16u * GPITCH));
#pragma unroll
            for (int nj = 0; nj < 2; nj++) LDMX4(b[nj], bbase + (u32)nj * (16u * GPITCH));
#pragma unroll
            for (int mi = 0; mi < 4; mi++)
#pragma unroll
                for (int ni = 0; ni < 4; ni++)
                    mma16816(acc[mi][ni], a[mi], b[ni >> 1][ni & 1], b[ni >> 1][(ni & 1) + 2]);
        }
        __syncthreads();
    }

    const float pre = (mat == 0) ? 0.125f : 1.0f;
#pragma unroll
    for (int mi = 0; mi < 4; mi++)
#pragma unroll
        for (int ni = 0; ni < 4; ni++) {
            u32 r0 = bm + (u32)wm + (u32)mi * 16u + (u32)(lane >> 2);
            u32 col = bn + (u32)wn + (u32)ni * 8u + (u32)((lane & 3) << 1);
            float v0 = acc[mi][ni][0] * pre, v1 = acc[mi][ni][1] * pre;
            float v2 = acc[mi][ni][2] * pre, v3 = acc[mi][ni][3] * pre;
            if (mat == 3) {
                float b0 = bias[col], b1 = bias[col + 1];
                *(float2*)&Cout[(ull)r0 * 1024ull + col] = make_float2(v0 + b0, v1 + b1);
                *(float2*)&Cout[(ull)(r0 + 8) * 1024ull + col] = make_float2(v2 + b0, v3 + b1);
            } else if (mat == 2) {
                u32 h01, m01, h23, m23;
                split2pk(v0, v1, h01, m01); split2pk(v2, v3, h23, m23);
                *(u32*)&g_vs[0][r0 * 1024u + col] = h01;
                *(u32*)&g_vs[1][r0 * 1024u + col] = m01;
                *(u32*)&g_vs[0][(r0 + 8) * 1024u + col] = h23;
                *(u32*)&g_vs[1][(r0 + 8) * 1024u + col] = m23;
            } else {
                __nv_bfloat16* d0 = (mat == 0) ? g_qs[0] : g_ks[0];
                __nv_bfloat16* d1 = (mat == 0) ? g_qs[1] : g_ks[1];
                __nv_bfloat16* d2 = (mat == 0) ? g_qs[2] : g_ks[2];
                u32 h01, m01, l01, h23, m23, l23;
                split3pk(v0, v1, h01, m01, l01); split3pk(v2, v3, h23, m23, l23);
                *(u32*)&d0[r0 * 1024u + col] = h01;
                *(u32*)&d1[r0 * 1024u + col] = m01;
                *(u32*)&d2[r0 * 1024u + col] = l01;
                *(u32*)&d0[(r0 + 8) * 1024u + col] = h23;
                *(u32*)&d1[(r0 + 8) * 1024u + col] = m23;
                *(u32*)&d2[(r0 + 8) * 1024u + col] = l23;
            }
        }
}

// ================= mma.sync flash attention =================
// 8 warps, warp w owns q-rows [16w,16w+16). BQ=128, BKEY=64, 32 chunks.
// smem: Q 3 splits (128x144B) | 2 stages x { K 3 splits (64x144B), V 2 splits (64x144B) }.
#define AP   144u
#define QSZ  18432u     // 128*144 per split
#define KSZ  9216u      // 64*144 per split
#define ASTAGE 46080u   // 5*KSZ
#define ASMEM  147456u  // 3*QSZ + 2*ASTAGE

__device__ __forceinline__ void attn_issue(u32 base, int s, int key0, u32 hb, int tid) {
    u32 st = base + 3u * QSZ + (u32)s * ASTAGE;
#pragma unroll
    for (int i = 0; i < 10; i++) {
        u32 u = (u32)tid + (u32)i * 256u;
        if (u < 1536u) {
            u32 sp = u >> 9, r = (u >> 3) & 63u, ch = (u & 7u) << 4;
            const char* src = (const char*)g_ks[sp] + (ull)(key0 + (int)r) * 2048ull + hb + ch;
            CP_ASYNC16(st + sp * KSZ + r * AP + ch, src);
        } else {
            u32 u2 = u - 1536u;
            u32 sp = u2 >> 9, r = (u2 >> 3) & 63u, ch = (u2 & 7u) << 4;
            const char* src = (const char*)g_vs[sp] + (ull)(key0 + (int)r) * 2048ull + hb + ch;
            CP_ASYNC16(st + 3u * KSZ + sp * KSZ + r * AP + ch, src);
        }
    }
    CP_COMMIT();
}

__global__ void __launch_bounds__(256) attn_mma_kernel() {
    extern __shared__ char sma[];
    u32 base = smem_to_u32(sma);
    const int tid = threadIdx.x, lane = tid & 31, w = tid >> 5;
    const int b = blockIdx.y >> 4, h = blockIdx.y & 15;
    const u32 hb = (u32)h * 128u;
    const int m0 = b * 2048 + (blockIdx.x << 7);
    const int kv0 = b * 2048;

    // Q tile: 3 splits x 128 rows x 8 chunks
#pragma unroll
    for (int i = 0; i < 12; i++) {
        u32 u = (u32)tid + (u32)i * 256u;
        u32 sp = u >> 10, r = (u >> 3) & 127u, ch = (u & 7u) << 4;
        const char* src = (const char*)g_qs[sp] + (ull)(m0 + (int)r) * 2048ull + hb + ch;
        CP_ASYNC16(base + sp * QSZ + r * AP + ch, src);
    }
    CP_COMMIT();
    attn_issue(base, 0, kv0, hb, tid);

    float o[8][4];
#pragma unroll
    for (int i = 0; i < 8; i++)
#pragma unroll
        for (int e = 0; e < 4; e++) o[i][e] = 0.f;
    float mg0 = -1e30f, mg1 = -1e30f, l0 = 0.f, l1 = 0.f;

    const u32 lrow = (u32)(lane & 15) * AP + (u32)(lane >> 4) * 16u;
    const u32 qbase = base + (u32)w * (16u * AP) + lrow;

    for (int c = 0; c < 32; c++) {
        if (c + 1 < 32) { attn_issue(base, (c + 1) & 1, kv0 + (c + 1) * 64, hb, tid); CP_WAIT1(); }
        else            { CP_WAIT0(); }
        __syncthreads();

        u32 stK = base + 3u * QSZ + (u32)(c & 1) * ASTAGE;
        u32 stV = stK + 3u * KSZ;

        // ---- S = QK^T (6 split products) ----
        float sv[8][4];
#pragma unroll
        for (int i = 0; i < 8; i++)
#pragma unroll
            for (int e = 0; e < 4; e++) sv[i][e] = 0.f;

#pragma unroll
        for (int ks = 0; ks < 4; ks++) {
            u32 aq[3][4];
#pragma unroll
            for (int sp = 0; sp < 3; sp++) LDMX4(aq[sp], qbase + sp * QSZ + (u32)ks * 32u);
#pragma unroll
            for (int sb = 0; sb < 3; sb++) {
                u32 bf[4][4];
                u32 bb = stK + (u32)sb * KSZ + lrow + (u32)ks * 32u;
#pragma unroll
                for (int q = 0; q < 4; q++) LDMX4(bf[q], bb + (u32)q * (16u * AP));
                const int na = (sb == 0) ? 3 : (sb == 1) ? 2 : 1;
#pragma unroll
                for (int ai = 0; ai < 3; ai++) {
                    if (ai < na) {
#pragma unroll
                        for (int q = 0; q < 4; q++) {
                            mma16816(sv[2 * q],     aq[ai], bf[q][0], bf[q][2]);
                            mma16816(sv[2 * q + 1], aq[ai], bf[q][1], bf[q][3]);
                        }
                    }
                }
            }
        }

        // ---- online softmax (rows r0 = 16w+(lane>>2), r1 = r0+8) ----
        float cm0 = -1e30f, cm1 = -1e30f;
#pragma unroll
        for (int i = 0; i < 8; i++) {
            cm0 = fmaxf(cm0, fmaxf(sv[i][0], sv[i][1]));
            cm1 = fmaxf(cm1, fmaxf(sv[i][2], sv[i][3]));
        }
        cm0 = fmaxf(cm0, __shfl_xor_sync(0xffffffffu, cm0, 1));
        cm0 = fmaxf(cm0, __shfl_xor_sync(0xffffffffu, cm0, 2));
        cm1 = fmaxf(cm1, __shfl_xor_sync(0xffffffffu, cm1, 1));
        cm1 = fmaxf(cm1, __shfl_xor_sync(0xffffffffu, cm1, 2));
        float nm0 = fmaxf(mg0, cm0), nm1 = fmaxf(mg1, cm1);
        float corr0 = __expf(mg0 - nm0), corr1 = __expf(mg1 - nm1);
        float rs0 = 0.f, rs1 = 0.f;
#pragma unroll
        for (int i = 0; i < 8; i++) {
            sv[i][0] = __expf(sv[i][0] - nm0);
            sv[i][1] = __expf(sv[i][1] - nm0);
            sv[i][2] = __expf(sv[i][2] - nm1);
            sv[i][3] = __expf(sv[i][3] - nm1);
            rs0 += sv[i][0] + sv[i][1];
            rs1 += sv[i][2] + sv[i][3];
        }
        rs0 += __shfl_xor_sync(0xffffffffu, rs0, 1);
        rs0 += __shfl_xor_sync(0xffffffffu, rs0, 2);
        rs1 += __shfl_xor_sync(0xffffffffu, rs1, 1);
        rs1 += __shfl_xor_sync(0xffffffffu, rs1, 2);
        l0 = l0 * corr0 + rs0; l1 = l1 * corr1 + rs1;
        mg0 = nm0; mg1 = nm1;
#pragma unroll
        for (int i = 0; i < 8; i++) {
            o[i][0] *= corr0; o[i][1] *= corr0;
            o[i][2] *= corr1; o[i][3] *= corr1;
        }

        // ---- P -> bf16 2-split A-fragments (in-register) ----
        u32 ph[4][4], pm[4][4];
#pragma unroll
        for (int j = 0; j < 4; j++) {
            split2pk(sv[2 * j][0],     sv[2 * j][1],     ph[j][0], pm[j][0]);
            split2pk(sv[2 * j][2],     sv[2 * j][3],     ph[j][1], pm[j][1]);
            split2pk(sv[2 * j + 1][0], sv[2 * j + 1][1], ph[j][2], pm[j][2]);
            split2pk(sv[2 * j + 1][2], sv[2 * j + 1][3], ph[j][3], pm[j][3]);
        }

        // ---- O += P V (3 products, V via ldmatrix.trans) ----
#pragma unroll
        for (int j = 0; j < 4; j++) {
            u32 vrow = stV + (16u * (u32)j + (u32)(lane & 7) + (u32)((lane >> 4) << 3)) * AP
                       + (u32)(((lane >> 3) & 1) << 4);
            u32 bv[4][4];
#pragma unroll
            for (int q = 0; q < 4; q++) LDMX4T(bv[q], vrow + (u32)q * 32u);
#pragma unroll
            for (int q = 0; q < 4; q++) {
                mma16816(o[2 * q],     ph[j], bv[q][0], bv[q][2]);
                mma16816(o[2 * q + 1], ph[j], bv[q][1], bv[q][3]);
                mma16816(o[2 * q],     pm[j], bv[q][0], bv[q][2]);
                mma16816(o[2 * q + 1], pm[j], bv[q][1], bv[q][3]);
            }
#pragma unroll
            for (int q = 0; q < 4; q++) LDMX4T(bv[q], vrow + KSZ + (u32)q * 32u);
#pragma unroll
            for (int q = 0; q < 4; q++) {
                mma16816(o[2 * q],     ph[j], bv[q][0], bv[q][2]);
                mma16816(o[2 * q + 1], ph[j], bv[q][1], bv[q][3]);
            }
        }
        __syncthreads();
    }

    // ---- epilogue: normalize, write ctx 2-splits ----
    float inv0 = 1.0f / l0, inv1 = 1.0f / l1;
    u32 r0 = (u32)m0 + (u32)w * 16u + (u32)(lane >> 2);
    u32 cb = (u32)h * 64u + (u32)((lane & 3) << 1);
#pragma unroll
    for (int i = 0; i < 8; i++) {
        u32 col = cb + (u32)i * 8u;
        u32 h01, m01, h23, m23;
        split2pk(o[i][0] * inv0, o[i][1] * inv0, h01, m01);
        split2pk(o[i][2] * inv1, o[i][3] * inv1, h23, m23);
        *(u32*)&g_cs[0][r0 * 1024u + col] = h01;
        *(u32*)&g_cs[1][r0 * 1024u + col] = m01;
        *(u32*)&g_cs[0][(r0 + 8u) * 1024u + col] = h23;
        *(u32*)&g_cs[1][(r0 + 8u) * 1024u + col] = m23;
    }
}

// ================= launch =================
extern "C" void kernel_launch(void* const* d_in, const int* in_sizes, int n_in,
                              void* d_out, int out_size) {
    const float* q  = (const float*)d_in[0];
    const float* k  = (const float*)d_in[1];
    const float* v  = (const float*)d_in[2];
    const float* Wq = (const float*)d_in[3];
    const float* Wk = (const float*)d_in[4];
    const float* Wv = (const float*)d_in[5];
    const float* Wo = (const float*)d_in[6];
    const float* bo = (const float*)d_in[7];
    float* out = (float*)d_out;

    split_qkv_kernel<<<dim3(4096, 3), 256>>>(q, k, v);
    split_w3_kernel<<<3072, 256>>>(Wq, Wk, Wv);
    split_wo_kernel<<<1024, 256>>>(Wo);

    cudaFuncSetAttribute(gemm_mma_kernel, cudaFuncAttributeMaxDynamicSharedMemorySize, 2 * GSTAGE);
    gemm_mma_kernel<<<dim3(8, 32, 3), 256, 2 * GSTAGE>>>(0, nullptr, nullptr);

    cudaFuncSetAttribute(attn_mma_kernel, cudaFuncAttributeMaxDynamicSharedMemorySize, ASMEM);
    attn_mma_kernel<<<dim3(16, 32), 256, ASMEM>>>();

    gemm_mma_kernel<<<dim3(8, 32, 1), 256, 2 * GSTAGE>>>(3, out, bo);
}

// round 7
// speedup vs baseline: 1.6448x; 1.0110x over previous
#include <cuda_runtime.h>
#include <cuda_bf16.h>

typedef unsigned long long ull;
typedef unsigned int u32;

// ================= common helpers =================
__device__ __forceinline__ u32 smem_to_u32(const void* p) {
    u32 a; asm("{ .reg .u64 t; cvta.to.shared.u64 t, %1; cvt.u32.u64 %0, t; }" : "=r"(a) : "l"(p));
    return a;
}
#define CP_ASYNC16(dst, src) asm volatile("cp.async.cg.shared.global [%0], [%1], 16;" :: "r"(dst), "l"(src) : "memory")
#define CP_COMMIT()          asm volatile("cp.async.commit_group;" ::: "memory")
#define CP_WAIT0()           asm volatile("cp.async.wait_group 0;" ::: "memory")
#define CP_WAIT1()           asm volatile("cp.async.wait_group 1;" ::: "memory")
#define CP_WAIT2()           asm volatile("cp.async.wait_group 2;" ::: "memory")

#define LDMX4(r, addr) \
    asm volatile("ldmatrix.sync.aligned.m8n8.x4.shared.b16 {%0,%1,%2,%3}, [%4];" \
        : "=r"((r)[0]), "=r"((r)[1]), "=r"((r)[2]), "=r"((r)[3]) : "r"(addr))
#define LDMX4T(r, addr) \
    asm volatile("ldmatrix.sync.aligned.m8n8.x4.trans.shared.b16 {%0,%1,%2,%3}, [%4];" \
        : "=r"((r)[0]), "=r"((r)[1]), "=r"((r)[2]), "=r"((r)[3]) : "r"(addr))

__device__ __forceinline__ void mma16816(float* c, const u32* a, u32 b0, u32 b1) {
    asm volatile("mma.sync.aligned.m16n8k16.row.col.f32.bf16.bf16.f32 "
        "{%0,%1,%2,%3}, {%4,%5,%6,%7}, {%8,%9}, {%0,%1,%2,%3};"
        : "+f"(c[0]), "+f"(c[1]), "+f"(c[2]), "+f"(c[3])
        : "r"(a[0]), "r"(a[1]), "r"(a[2]), "r"(a[3]), "r"(b0), "r"(b1));
}

// ================= global scratch =================
__device__ __align__(256) __nv_bfloat16 g_as[3][3][4194304];  // input splits [mat][split][m*1024+k]
__device__ __align__(256) __nv_bfloat16 g_bs[4][3][1048576];  // weight splits [mat][split][n*1024+k]
__device__ __align__(256) __nv_bfloat16 g_qs[3][4194304];     // qh 3-split (prescaled 1/8)
__device__ __align__(256) __nv_bfloat16 g_ks[3][4194304];     // kh 3-split
__device__ __align__(256) __nv_bfloat16 g_vs[2][4194304];     // vh 2-split
__device__ __align__(256) __nv_bfloat16 g_cs[2][4194304];     // ctx 2-split

__constant__ int c_pa[6] = { 0, 0, 1, 0, 2, 1 };
__constant__ int c_pb[6] = { 0, 1, 0, 2, 0, 1 };

// ================= split helpers =================
__device__ __forceinline__ void split3(float x, __nv_bfloat16& h, __nv_bfloat16& m, __nv_bfloat16& l) {
    h = __float2bfloat16(x);
    float r1 = x - __bfloat162float(h);
    m = __float2bfloat16(r1);
    float r2 = r1 - __bfloat162float(m);
    l = __float2bfloat16(r2);
}
__device__ __forceinline__ u32 pk2(__nv_bfloat16 a, __nv_bfloat16 b) {
    __nv_bfloat162 t = __halves2bfloat162(a, b);
    return *reinterpret_cast<u32*>(&t);
}
__device__ __forceinline__ void split2pk(float x, float y, u32& hi, u32& lo) {
    __nv_bfloat16 hx = __float2bfloat16(x), hy = __float2bfloat16(y);
    __nv_bfloat16 mx = __float2bfloat16(x - __bfloat162float(hx));
    __nv_bfloat16 my = __float2bfloat16(y - __bfloat162float(hy));
    hi = pk2(hx, hy); lo = pk2(mx, my);
}
__device__ __forceinline__ void split3pk(float x, float y, u32& h, u32& m, u32& l) {
    __nv_bfloat16 hx, mx, lx, hy, my, ly;
    split3(x, hx, mx, lx); split3(y, hy, my, ly);
    h = pk2(hx, hy); m = pk2(mx, my); l = pk2(lx, ly);
}

// ================= input split kernels =================
__global__ void split_qkv_kernel(const float* __restrict__ q, const float* __restrict__ k,
                                 const float* __restrict__ v) {
    u32 idx = blockIdx.x * 256u + threadIdx.x;
    int y = blockIdx.y;
    const float* in = (y == 0) ? q : (y == 1) ? k : v;
    float4 x = ((const float4*)in)[idx];
    float xs[4] = { x.x, x.y, x.z, x.w };
    __nv_bfloat16 h[4], m[4], l[4];
#pragma unroll
    for (int j = 0; j < 4; j++) split3(xs[j], h[j], m[j], l[j]);
    u32 o = idx * 4u;
    *(uint2*)&g_as[y][0][o] = make_uint2(pk2(h[0], h[1]), pk2(h[2], h[3]));
    *(uint2*)&g_as[y][1][o] = make_uint2(pk2(m[0], m[1]), pk2(m[2], m[3]));
    *(uint2*)&g_as[y][2][o] = make_uint2(pk2(l[0], l[1]), pk2(l[2], l[3]));
}

__global__ void split_w3_kernel(const float* __restrict__ Wq, const float* __restrict__ Wk,
                                const float* __restrict__ Wv) {
    u32 idx = blockIdx.x * 256u + threadIdx.x;
    u32 mat = idx >> 18, r = idx & 262143u;
    u32 n = r >> 8, d4 = r & 255u;
    u32 h = n >> 6, kk = n & 63u;
    const float* W = (mat == 0) ? Wq : (mat == 1) ? Wk : Wv;
    __nv_bfloat16 hh[4], mm[4], ll[4];
#pragma unroll
    for (int j = 0; j < 4; j++) {
        float x = W[h * 65536u + (d4 * 4u + j) * 64u + kk];
        split3(x, hh[j], mm[j], ll[j]);
    }
    u32 o = n * 1024u + d4 * 4u;
    *(uint2*)&g_bs[mat][0][o] = make_uint2(pk2(hh[0], hh[1]), pk2(hh[2], hh[3]));
    *(uint2*)&g_bs[mat][1][o] = make_uint2(pk2(mm[0], mm[1]), pk2(mm[2], mm[3]));
    *(uint2*)&g_bs[mat][2][o] = make_uint2(pk2(ll[0], ll[1]), pk2(ll[2], ll[3]));
}

__global__ void split_wo_kernel(const float* __restrict__ Wo) {
    u32 idx = blockIdx.x * 256u + threadIdx.x;
    float4 x = ((const float4*)Wo)[idx];
    float xs[4] = { x.x, x.y, x.z, x.w };
    __nv_bfloat16 h[4], m[4], l[4];
#pragma unroll
    for (int j = 0; j < 4; j++) split3(xs[j], h[j], m[j], l[j]);
    u32 o = idx * 4u;
    *(uint2*)&g_bs[3][0][o] = make_uint2(pk2(h[0], h[1]), pk2(h[2], h[3]));
    *(uint2*)&g_bs[3][1][o] = make_uint2(pk2(m[0], m[1]), pk2(m[2], m[3]));
    *(uint2*)&g_bs[3][2][o] = make_uint2(pk2(l[0], l[1]), pk2(l[2], l[3]));
}

// ================= mma.sync split-fp32 GEMM (BK=64, 3-stage, 1 sync/iter) ========
#define GPITCH 144u
#define GTILE  18432u        // 128 * 144
#define GSTAGE 36864u        // A + B
#define GSMEM  110592u       // 3 stages
#define ASPLIT 8388608ull
#define BSPLIT 2097152ull

__device__ __forceinline__ void gemm_issue(const char* aB, const char* bB, u32 base,
                                           int v, int s, u32 bm, u32 bn, int tid) {
    int p = v >> 4;
    u32 kb = (u32)(v & 15) * 128u;
    const char* srcA = aB + (ull)c_pa[p] * ASPLIT + kb;
    const char* srcB = bB + (ull)c_pb[p] * BSPLIT + kb;
    u32 stA = base + (u32)s * GSTAGE;
    u32 stB = stA + GTILE;
#pragma unroll
    for (int j = 0; j < 4; j++) {
        u32 c = (u32)tid + (u32)j * 256u;
        u32 row = c >> 3, ch = (c & 7u) << 4;
        CP_ASYNC16(stA + row * GPITCH + ch, srcA + (ull)(bm + row) * 2048ull + ch);
        CP_ASYNC16(stB + row * GPITCH + ch, srcB + (ull)(bn + row) * 2048ull + ch);
    }
    CP_COMMIT();
}

__global__ void __launch_bounds__(256) gemm_mma_kernel(int mat_base, float* Cout,
                                                       const float* __restrict__ bias) {
    extern __shared__ char sm_g[];
    u32 base = smem_to_u32(sm_g);
    const int tid = threadIdx.x, lane = tid & 31, wid = tid >> 5;
    const u32 bm = blockIdx.y << 7, bn = blockIdx.x << 7;
    const int wm = (wid >> 2) << 6, wn = (wid & 3) << 5;
    const int mat = mat_base + blockIdx.z;
    const int npairs = (mat <= 1) ? 6 : 3;

    const char* aB; const char* bB;
    if (mat < 3) { aB = (const char*)g_as[mat][0]; bB = (const char*)g_bs[mat][0]; }
    else         { aB = (const char*)g_cs[0];      bB = (const char*)g_bs[3][0]; }

    float acc[4][4][4];
#pragma unroll
    for (int mi = 0; mi < 4; mi++)
#pragma unroll
        for (int ni = 0; ni < 4; ni++)
#pragma unroll
            for (int e = 0; e < 4; e++) acc[mi][ni][e] = 0.f;

    const int NV = npairs * 16;
    gemm_issue(aB, bB, base, 0, 0, bm, bn, tid);
    gemm_issue(aB, bB, base, 1, 1, bm, bn, tid);

    int s = 0;      // stage of chunk v
    for (int v = 0; v < NV; v++) {
        if (v == NV - 1) { CP_WAIT0(); } else { CP_WAIT1(); }
        __syncthreads();
        if (v + 2 < NV) {
            int s2 = (s + 2 >= 3) ? s - 1 : s + 2;
            gemm_issue(aB, bB, base, v + 2, s2, bm, bn, tid);
        }

        u32 stA = base + (u32)s * GSTAGE;
        u32 stB = stA + GTILE;
        u32 lrow = (u32)(lane & 15) * GPITCH + (u32)(lane >> 4) * 16u;
#pragma unroll
        for (int ks = 0; ks < 4; ks++) {
            u32 a[4][4], b[2][4];
            u32 abase = stA + (u32)wm * GPITCH + lrow + (u32)ks * 32u;
            u32 bbase = stB + (u32)wn * GPITCH + lrow + (u32)ks * 32u;
#pragma unroll
            for (int mi = 0; mi < 4; mi++) LDMX4(a[mi], abase + (u32)mi * (16u * GPITCH));
#pragma unroll
            for (int nj = 0; nj < 2; nj++) LDMX4(b[nj], bbase + (u32)nj * (16u * GPITCH));
#pragma unroll
            for (int mi = 0; mi < 4; mi++)
#pragma unroll
                for (int ni = 0; ni < 4; ni++)
                    mma16816(acc[mi][ni], a[mi], b[ni >> 1][ni & 1], b[ni >> 1][(ni & 1) + 2]);
        }
        s = (s + 1 == 3) ? 0 : s + 1;
    }

    const float pre = (mat == 0) ? 0.125f : 1.0f;
#pragma unroll
    for (int mi = 0; mi < 4; mi++)
#pragma unroll
        for (int ni = 0; ni < 4; ni++) {
            u32 r0 = bm + (u32)wm + (u32)mi * 16u + (u32)(lane >> 2);
            u32 col = bn + (u32)wn + (u32)ni * 8u + (u32)((lane & 3) << 1);
            float v0 = acc[mi][ni][0] * pre, v1 = acc[mi][ni][1] * pre;
            float v2 = acc[mi][ni][2] * pre, v3 = acc[mi][ni][3] * pre;
            if (mat == 3) {
                float b0 = bias[col], b1 = bias[col + 1];
                *(float2*)&Cout[(ull)r0 * 1024ull + col] = make_float2(v0 + b0, v1 + b1);
                *(float2*)&Cout[(ull)(r0 + 8) * 1024ull + col] = make_float2(v2 + b0, v3 + b1);
            } else if (mat == 2) {
                u32 h01, m01, h23, m23;
                split2pk(v0, v1, h01, m01); split2pk(v2, v3, h23, m23);
                *(u32*)&g_vs[0][r0 * 1024u + col] = h01;
                *(u32*)&g_vs[1][r0 * 1024u + col] = m01;
                *(u32*)&g_vs[0][(r0 + 8) * 1024u + col] = h23;
                *(u32*)&g_vs[1][(r0 + 8) * 1024u + col] = m23;
            } else {
                __nv_bfloat16* d0 = (mat == 0) ? g_qs[0] : g_ks[0];
                __nv_bfloat16* d1 = (mat == 0) ? g_qs[1] : g_ks[1];
                __nv_bfloat16* d2 = (mat == 0) ? g_qs[2] : g_ks[2];
                u32 h01, m01, l01, h23, m23, l23;
                split3pk(v0, v1, h01, m01, l01); split3pk(v2, v3, h23, m23, l23);
                *(u32*)&d0[r0 * 1024u + col] = h01;
                *(u32*)&d1[r0 * 1024u + col] = m01;
                *(u32*)&d2[r0 * 1024u + col] = l01;
                *(u32*)&d0[(r0 + 8) * 1024u + col] = h23;
                *(u32*)&d1[(r0 + 8) * 1024u + col] = m23;
                *(u32*)&d2[(r0 + 8) * 1024u + col] = l23;
            }
        }
}

// ================= mma.sync flash attention (3-stage, 1 sync/chunk) =================
#define AP   144u
#define QSZ  18432u     // 128*144 per split
#define KSZ  9216u      // 64*144 per split
#define ASTAGE 46080u   // 3 K splits + 2 V splits
#define ASMEM  193536u  // 3*QSZ + 3*ASTAGE

__device__ __forceinline__ void attn_issue(u32 base, int s, int key0, u32 hb, int tid) {
    u32 st = base + 3u * QSZ + (u32)s * ASTAGE;
#pragma unroll
    for (int i = 0; i < 10; i++) {
        u32 u = (u32)tid + (u32)i * 256u;
        if (u < 1536u) {
            u32 sp = u >> 9, r = (u >> 3) & 63u, ch = (u & 7u) << 4;
            const char* src = (const char*)g_ks[sp] + (ull)(key0 + (int)r) * 2048ull + hb + ch;
            CP_ASYNC16(st + sp * KSZ + r * AP + ch, src);
        } else {
            u32 u2 = u - 1536u;
            u32 sp = u2 >> 9, r = (u2 >> 3) & 63u, ch = (u2 & 7u) << 4;
            const char* src = (const char*)g_vs[sp] + (ull)(key0 + (int)r) * 2048ull + hb + ch;
            CP_ASYNC16(st + 3u * KSZ + sp * KSZ + r * AP + ch, src);
        }
    }
    CP_COMMIT();
}

__global__ void __launch_bounds__(256) attn_mma_kernel() {
    extern __shared__ char sma[];
    u32 base = smem_to_u32(sma);
    const int tid = threadIdx.x, lane = tid & 31, w = tid >> 5;
    const int b = blockIdx.y >> 4, h = blockIdx.y & 15;
    const u32 hb = (u32)h * 128u;
    const int m0 = b * 2048 + (blockIdx.x << 7);
    const int kv0 = b * 2048;

    // Q tile: 3 splits x 128 rows x 8 chunks (own commit group)
#pragma unroll
    for (int i = 0; i < 12; i++) {
        u32 u = (u32)tid + (u32)i * 256u;
        u32 sp = u >> 10, r = (u >> 3) & 127u, ch = (u & 7u) << 4;
        const char* src = (const char*)g_qs[sp] + (ull)(m0 + (int)r) * 2048ull + hb + ch;
        CP_ASYNC16(base + sp * QSZ + r * AP + ch, src);
    }
    CP_COMMIT();
    attn_issue(base, 0, kv0, hb, tid);
    attn_issue(base, 1, kv0 + 64, hb, tid);
    CP_WAIT2();          // Q group complete
    __syncthreads();

    float o[8][4];
#pragma unroll
    for (int i = 0; i < 8; i++)
#pragma unroll
        for (int e = 0; e < 4; e++) o[i][e] = 0.f;
    float mg0 = -1e30f, mg1 = -1e30f, l0 = 0.f, l1 = 0.f;

    const u32 lrow = (u32)(lane & 15) * AP + (u32)(lane >> 4) * 16u;
    const u32 qbase = base + (u32)w * (16u * AP) + lrow;

    int s = 0;
    for (int c = 0; c < 32; c++) {
        if (c == 31) { CP_WAIT0(); } else { CP_WAIT1(); }
        __syncthreads();
        if (c + 2 < 32) {
            int s2 = (s + 2 >= 3) ? s - 1 : s + 2;
            attn_issue(base, s2, kv0 + (c + 2) * 64, hb, tid);
        }

        u32 stK = base + 3u * QSZ + (u32)s * ASTAGE;
        u32 stV = stK + 3u * KSZ;

        // ---- S = QK^T (6 split products) ----
        float sv[8][4];
#pragma unroll
        for (int i = 0; i < 8; i++)
#pragma unroll
            for (int e = 0; e < 4; e++) sv[i][e] = 0.f;

#pragma unroll
        for (int ks = 0; ks < 4; ks++) {
            u32 aq[3][4];
#pragma unroll
            for (int sp = 0; sp < 3; sp++) LDMX4(aq[sp], qbase + sp * QSZ + (u32)ks * 32u);
#pragma unroll
            for (int sb = 0; sb < 3; sb++) {
                u32 bf[4][4];
                u32 bb = stK + (u32)sb * KSZ + lrow + (u32)ks * 32u;
#pragma unroll
                for (int q = 0; q < 4; q++) LDMX4(bf[q], bb + (u32)q * (16u * AP));
                const int na = (sb == 0) ? 3 : (sb == 1) ? 2 : 1;
#pragma unroll
                for (int ai = 0; ai < 3; ai++) {
                    if (ai < na) {
#pragma unroll
                        for (int q = 0; q < 4; q++) {
                            mma16816(sv[2 * q],     aq[ai], bf[q][0], bf[q][2]);
                            mma16816(sv[2 * q + 1], aq[ai], bf[q][1], bf[q][3]);
                        }
                    }
                }
            }
        }

        // ---- online softmax ----
        float cm0 = -1e30f, cm1 = -1e30f;
#pragma unroll
        for (int i = 0; i < 8; i++) {
            cm0 = fmaxf(cm0, fmaxf(sv[i][0], sv[i][1]));
            cm1 = fmaxf(cm1, fmaxf(sv[i][2], sv[i][3]));
        }
        cm0 = fmaxf(cm0, __shfl_xor_sync(0xffffffffu, cm0, 1));
        cm0 = fmaxf(cm0, __shfl_xor_sync(0xffffffffu, cm0, 2));
        cm1 = fmaxf(cm1, __shfl_xor_sync(0xffffffffu, cm1, 1));
        cm1 = fmaxf(cm1, __shfl_xor_sync(0xffffffffu, cm1, 2));
        float nm0 = fmaxf(mg0, cm0), nm1 = fmaxf(mg1, cm1);
        float corr0 = __expf(mg0 - nm0), corr1 = __expf(mg1 - nm1);
        float rs0 = 0.f, rs1 = 0.f;
#pragma unroll
        for (int i = 0; i < 8; i++) {
            sv[i][0] = __expf(sv[i][0] - nm0);
            sv[i][1] = __expf(sv[i][1] - nm0);
            sv[i][2] = __expf(sv[i][2] - nm1);
            sv[i][3] = __expf(sv[i][3] - nm1);
            rs0 += sv[i][0] + sv[i][1];
            rs1 += sv[i][2] + sv[i][3];
        }
        rs0 += __shfl_xor_sync(0xffffffffu, rs0, 1);
        rs0 += __shfl_xor_sync(0xffffffffu, rs0, 2);
        rs1 += __shfl_xor_sync(0xffffffffu, rs1, 1);
        rs1 += __shfl_xor_sync(0xffffffffu, rs1, 2);
        l0 = l0 * corr0 + rs0; l1 = l1 * corr1 + rs1;
        mg0 = nm0; mg1 = nm1;
#pragma unroll
        for (int i = 0; i < 8; i++) {
            o[i][0] *= corr0; o[i][1] *= corr0;
            o[i][2] *= corr1; o[i][3] *= corr1;
        }

        // ---- P -> bf16 2-split A-fragments ----
        u32 ph[4][4], pm[4][4];
#pragma unroll
        for (int j = 0; j < 4; j++) {
            split2pk(sv[2 * j][0],     sv[2 * j][1],     ph[j][0], pm[j][0]);
            split2pk(sv[2 * j][2],     sv[2 * j][3],     ph[j][1], pm[j][1]);
            split2pk(sv[2 * j + 1][0], sv[2 * j + 1][1], ph[j][2], pm[j][2]);
            split2pk(sv[2 * j + 1][2], sv[2 * j + 1][3], ph[j][3], pm[j][3]);
        }

        // ---- O += P V (3 products, V via ldmatrix.trans) ----
#pragma unroll
        for (int j = 0; j < 4; j++) {
            u32 vrow = stV + (16u * (u32)j + (u32)(lane & 7) + (u32)((lane >> 4) << 3)) * AP
                       + (u32)(((lane >> 3) & 1) << 4);
            u32 bv[4][4];
#pragma unroll
            for (int q = 0; q < 4; q++) LDMX4T(bv[q], vrow + (u32)q * 32u);
#pragma unroll
            for (int q = 0; q < 4; q++) {
                mma16816(o[2 * q],     ph[j], bv[q][0], bv[q][2]);
                mma16816(o[2 * q + 1], ph[j], bv[q][1], bv[q][3]);
                mma16816(o[2 * q],     pm[j], bv[q][0], bv[q][2]);
                mma16816(o[2 * q + 1], pm[j], bv[q][1], bv[q][3]);
            }
#pragma unroll
            for (int q = 0; q < 4; q++) LDMX4T(bv[q], vrow + KSZ + (u32)q * 32u);
#pragma unroll
            for (int q = 0; q < 4; q++) {
                mma16816(o[2 * q],     ph[j], bv[q][0], bv[q][2]);
                mma16816(o[2 * q + 1], ph[j], bv[q][1], bv[q][3]);
            }
        }
        s = (s + 1 == 3) ? 0 : s + 1;
    }

    // ---- epilogue ----
    float inv0 = 1.0f / l0, inv1 = 1.0f / l1;
    u32 r0 = (u32)m0 + (u32)w * 16u + (u32)(lane >> 2);
    u32 cb = (u32)h * 64u + (u32)((lane & 3) << 1);
#pragma unroll
    for (int i = 0; i < 8; i++) {
        u32 col = cb + (u32)i * 8u;
        u32 h01, m01, h23, m23;
        split2pk(o[i][0] * inv0, o[i][1] * inv0, h01, m01);
        split2pk(o[i][2] * inv1, o[i][3] * inv1, h23, m23);
        *(u32*)&g_cs[0][r0 * 1024u + col] = h01;
        *(u32*)&g_cs[1][r0 * 1024u + col] = m01;
        *(u32*)&g_cs[0][(r0 + 8u) * 1024u + col] = h23;
        *(u32*)&g_cs[1][(r0 + 8u) * 1024u + col] = m23;
    }
}

// ================= launch =================
extern "C" void kernel_launch(void* const* d_in, const int* in_sizes, int n_in,
                              void* d_out, int out_size) {
    const float* q  = (const float*)d_in[0];
    const float* k  = (const float*)d_in[1];
    const float* v  = (const float*)d_in[2];
    const float* Wq = (const float*)d_in[3];
    const float* Wk = (const float*)d_in[4];
    const float* Wv = (const float*)d_in[5];
    const float* Wo = (const float*)d_in[6];
    const float* bo = (const float*)d_in[7];
    float* out = (float*)d_out;

    split_qkv_kernel<<<dim3(4096, 3), 256>>>(q, k, v);
    split_w3_kernel<<<3072, 256>>>(Wq, Wk, Wv);
    split_wo_kernel<<<1024, 256>>>(Wo);

    cudaFuncSetAttribute(gemm_mma_kernel, cudaFuncAttributeMaxDynamicSharedMemorySize, GSMEM);
    gemm_mma_kernel<<<dim3(8, 32, 3), 256, GSMEM>>>(0, nullptr, nullptr);

    cudaFuncSetAttribute(attn_mma_kernel, cudaFuncAttributeMaxDynamicSharedMemorySize, ASMEM);
    attn_mma_kernel<<<dim3(16, 32), 256, ASMEM>>>();

    gemm_mma_kernel<<<dim3(8, 32, 1), 256, GSMEM>>>(3, out, bo);
}

// round 8
// speedup vs baseline: 2.1443x; 1.3037x over previous
#include <cuda_runtime.h>
#include <cuda_fp16.h>

typedef unsigned long long ull;
typedef unsigned int u32;

// ================= common helpers =================
__device__ __forceinline__ u32 smem_to_u32(const void* p) {
    u32 a; asm("{ .reg .u64 t; cvta.to.shared.u64 t, %1; cvt.u32.u64 %0, t; }" : "=r"(a) : "l"(p));
    return a;
}
#define CP_ASYNC16(dst, src) asm volatile("cp.async.cg.shared.global [%0], [%1], 16;" :: "r"(dst), "l"(src) : "memory")
#define CP_COMMIT()          asm volatile("cp.async.commit_group;" ::: "memory")
#define CP_WAIT0()           asm volatile("cp.async.wait_group 0;" ::: "memory")
#define CP_WAIT1()           asm volatile("cp.async.wait_group 1;" ::: "memory")
#define CP_WAIT2()           asm volatile("cp.async.wait_group 2;" ::: "memory")

#define LDMX4(r, addr) \
    asm volatile("ldmatrix.sync.aligned.m8n8.x4.shared.b16 {%0,%1,%2,%3}, [%4];" \
        : "=r"((r)[0]), "=r"((r)[1]), "=r"((r)[2]), "=r"((r)[3]) : "r"(addr))
#define LDMX4T(r, addr) \
    asm volatile("ldmatrix.sync.aligned.m8n8.x4.trans.shared.b16 {%0,%1,%2,%3}, [%4];" \
        : "=r"((r)[0]), "=r"((r)[1]), "=r"((r)[2]), "=r"((r)[3]) : "r"(addr))

__device__ __forceinline__ void mma16816(float* c, const u32* a, u32 b0, u32 b1) {
    asm volatile("mma.sync.aligned.m16n8k16.row.col.f32.f16.f16.f32 "
        "{%0,%1,%2,%3}, {%4,%5,%6,%7}, {%8,%9}, {%0,%1,%2,%3};"
        : "+f"(c[0]), "+f"(c[1]), "+f"(c[2]), "+f"(c[3])
        : "r"(a[0]), "r"(a[1]), "r"(a[2]), "r"(a[3]), "r"(b0), "r"(b1));
}

// ================= global scratch (all fp16 2-splits) =================
__device__ __align__(256) __half g_as[3][2][4194304];  // input splits [mat][split][m*1024+k]
__device__ __align__(256) __half g_bs[4][2][1048576];  // weight splits [mat][split][n*1024+k]
__device__ __align__(256) __half g_qs[2][4194304];     // qh 2-split (prescaled 1/8)
__device__ __align__(256) __half g_ks[2][4194304];     // kh 2-split
__device__ __align__(256) __half g_vs[2][4194304];     // vh 2-split
__device__ __align__(256) __half g_cs[2][4194304];     // ctx 2-split

__constant__ int c_pa[3] = { 0, 0, 1 };
__constant__ int c_pb[3] = { 0, 1, 0 };

// ================= split helpers (fp16 h+l) =================
__device__ __forceinline__ u32 pk2h(__half a, __half b) {
    __half2 t = __halves2half2(a, b);
    return *reinterpret_cast<u32*>(&t);
}
__device__ __forceinline__ void split2h(float x, __half& h, __half& l) {
    h = __float2half_rn(x);
    l = __float2half_rn(x - __half2float(h));
}
__device__ __forceinline__ void split2pkh(float x, float y, u32& hi, u32& lo) {
    __half hx, lx, hy, ly;
    split2h(x, hx, lx); split2h(y, hy, ly);
    hi = pk2h(hx, hy); lo = pk2h(lx, ly);
}

// ================= input split kernels =================
__global__ void split_qkv_kernel(const float* __restrict__ q, const float* __restrict__ k,
                                 const float* __restrict__ v) {
    u32 idx = blockIdx.x * 256u + threadIdx.x;
    int y = blockIdx.y;
    const float* in = (y == 0) ? q : (y == 1) ? k : v;
    float4 x = ((const float4*)in)[idx];
    u32 h01, l01, h23, l23;
    split2pkh(x.x, x.y, h01, l01);
    split2pkh(x.z, x.w, h23, l23);
    u32 o = idx * 4u;
    *(uint2*)&g_as[y][0][o] = make_uint2(h01, h23);
    *(uint2*)&g_as[y][1][o] = make_uint2(l01, l23);
}

// Wq/Wk/Wv [h, d, kk] -> B[n=h*64+kk][k=d] splits
__global__ void split_w3_kernel(const float* __restrict__ Wq, const float* __restrict__ Wk,
                                const float* __restrict__ Wv) {
    u32 idx = blockIdx.x * 256u + threadIdx.x;
    u32 mat = idx >> 18, r = idx & 262143u;
    u32 n = r >> 8, d4 = r & 255u;
    u32 h = n >> 6, kk = n & 63u;
    const float* W = (mat == 0) ? Wq : (mat == 1) ? Wk : Wv;
    float xs[4];
#pragma unroll
    for (int j = 0; j < 4; j++) xs[j] = W[h * 65536u + (d4 * 4u + j) * 64u + kk];
    u32 h01, l01, h23, l23;
    split2pkh(xs[0], xs[1], h01, l01);
    split2pkh(xs[2], xs[3], h23, l23);
    u32 o = n * 1024u + d4 * 4u;
    *(uint2*)&g_bs[mat][0][o] = make_uint2(h01, h23);
    *(uint2*)&g_bs[mat][1][o] = make_uint2(l01, l23);
}

__global__ void split_wo_kernel(const float* __restrict__ Wo) {
    u32 idx = blockIdx.x * 256u + threadIdx.x;
    float4 x = ((const float4*)Wo)[idx];
    u32 h01, l01, h23, l23;
    split2pkh(x.x, x.y, h01, l01);
    split2pkh(x.z, x.w, h23, l23);
    u32 o = idx * 4u;
    *(uint2*)&g_bs[3][0][o] = make_uint2(h01, h23);
    *(uint2*)&g_bs[3][1][o] = make_uint2(l01, l23);
}

// ================= mma.sync split-fp32 GEMM (fp16 2-split, 3 products) ========
#define GPITCH 144u
#define GTILE  18432u        // 128 * 144
#define GSTAGE 36864u        // A + B
#define GSMEM  110592u       // 3 stages
#define ASPLIT 8388608ull
#define BSPLIT 2097152ull

__device__ __forceinline__ void gemm_issue(const char* aB, const char* bB, u32 base,
                                           int v, int s, u32 bm, u32 bn, int tid) {
    int p = v >> 4;
    u32 kb = (u32)(v & 15) * 128u;
    const char* srcA = aB + (ull)c_pa[p] * ASPLIT + kb;
    const char* srcB = bB + (ull)c_pb[p] * BSPLIT + kb;
    u32 stA = base + (u32)s * GSTAGE;
    u32 stB = stA + GTILE;
#pragma unroll
    for (int j = 0; j < 4; j++) {
        u32 c = (u32)tid + (u32)j * 256u;
        u32 row = c >> 3, ch = (c & 7u) << 4;
        CP_ASYNC16(stA + row * GPITCH + ch, srcA + (ull)(bm + row) * 2048ull + ch);
        CP_ASYNC16(stB + row * GPITCH + ch, srcB + (ull)(bn + row) * 2048ull + ch);
    }
    CP_COMMIT();
}

__global__ void __launch_bounds__(256) gemm_mma_kernel(int mat_base, float* Cout,
                                                       const float* __restrict__ bias) {
    extern __shared__ char sm_g[];
    u32 base = smem_to_u32(sm_g);
    const int tid = threadIdx.x, lane = tid & 31, wid = tid >> 5;
    const u32 bm = blockIdx.y << 7, bn = blockIdx.x << 7;
    const int wm = (wid >> 2) << 6, wn = (wid & 3) << 5;
    const int mat = mat_base + blockIdx.z;

    const char* aB; const char* bB;
    if (mat < 3) { aB = (const char*)g_as[mat][0]; bB = (const char*)g_bs[mat][0]; }
    else         { aB = (const char*)g_cs[0];      bB = (const char*)g_bs[3][0]; }

    float acc[4][4][4];
#pragma unroll
    for (int mi = 0; mi < 4; mi++)
#pragma unroll
        for (int ni = 0; ni < 4; ni++)
#pragma unroll
            for (int e = 0; e < 4; e++) acc[mi][ni][e] = 0.f;

    const int NV = 48;   // 3 products x 16 chunks
    gemm_issue(aB, bB, base, 0, 0, bm, bn, tid);
    gemm_issue(aB, bB, base, 1, 1, bm, bn, tid);

    int s = 0;
    for (int v = 0; v < NV; v++) {
        if (v == NV - 1) { CP_WAIT0(); } else { CP_WAIT1(); }
        __syncthreads();
        if (v + 2 < NV) {
            int s2 = (s + 2 >= 3) ? s - 1 : s + 2;
            gemm_issue(aB, bB, base, v + 2, s2, bm, bn, tid);
        }

        u32 stA = base + (u32)s * GSTAGE;
        u32 stB = stA + GTILE;
        u32 lrow = (u32)(lane & 15) * GPITCH + (u32)(lane >> 4) * 16u;
#pragma unroll
        for (int ks = 0; ks < 4; ks++) {
            u32 a[4][4], b[2][4];
            u32 abase = stA + (u32)wm * GPITCH + lrow + (u32)ks * 32u;
            u32 bbase = stB + (u32)wn * GPITCH + lrow + (u32)ks * 32u;
#pragma unroll
            for (int mi = 0; mi < 4; mi++) LDMX4(a[mi], abase + (u32)mi * (16u * GPITCH));
#pragma unroll
            for (int nj = 0; nj < 2; nj++) LDMX4(b[nj], bbase + (u32)nj * (16u * GPITCH));
#pragma unroll
            for (int mi = 0; mi < 4; mi++)
#pragma unroll
                for (int ni = 0; ni < 4; ni++)
                    mma16816(acc[mi][ni], a[mi], b[ni >> 1][ni & 1], b[ni >> 1][(ni & 1) + 2]);
        }
        s = (s + 1 == 3) ? 0 : s + 1;
    }

    const float pre = (mat == 0) ? 0.125f : 1.0f;
#pragma unroll
    for (int mi = 0; mi < 4; mi++)
#pragma unroll
        for (int ni = 0; ni < 4; ni++) {
            u32 r0 = bm + (u32)wm + (u32)mi * 16u + (u32)(lane >> 2);
            u32 col = bn + (u32)wn + (u32)ni * 8u + (u32)((lane & 3) << 1);
            float v0 = acc[mi][ni][0] * pre, v1 = acc[mi][ni][1] * pre;
            float v2 = acc[mi][ni][2] * pre, v3 = acc[mi][ni][3] * pre;
            if (mat == 3) {
                float b0 = bias[col], b1 = bias[col + 1];
                *(float2*)&Cout[(ull)r0 * 1024ull + col] = make_float2(v0 + b0, v1 + b1);
                *(float2*)&Cout[(ull)(r0 + 8) * 1024ull + col] = make_float2(v2 + b0, v3 + b1);
            } else {
                __half* d0; __half* d1;
                if (mat == 0)      { d0 = g_qs[0]; d1 = g_qs[1]; }
                else if (mat == 1) { d0 = g_ks[0]; d1 = g_ks[1]; }
                else               { d0 = g_vs[0]; d1 = g_vs[1]; }
                u32 h01, l01, h23, l23;
                split2pkh(v0, v1, h01, l01); split2pkh(v2, v3, h23, l23);
                *(u32*)&d0[r0 * 1024u + col] = h01;
                *(u32*)&d1[r0 * 1024u + col] = l01;
                *(u32*)&d0[(r0 + 8) * 1024u + col] = h23;
                *(u32*)&d1[(r0 + 8) * 1024u + col] = l23;
            }
        }
}

// ================= mma.sync flash attention (fp16 2-split) =================
// QK^T: 4 products (hh,hl,lh,ll); PV: 3 products.
#define AP   144u
#define QSZ  18432u     // 128*144 per split
#define KSZ  9216u      // 64*144 per split
#define ASTAGE 36864u   // 2 K splits + 2 V splits
#define ASMEM  147456u  // 2*QSZ + 3*ASTAGE

__device__ __forceinline__ void attn_issue(u32 base, int s, int key0, u32 hb, int tid) {
    u32 st = base + 2u * QSZ + (u32)s * ASTAGE;
#pragma unroll
    for (int i = 0; i < 8; i++) {
        u32 u = (u32)tid + (u32)i * 256u;
        if (u < 1024u) {
            u32 sp = u >> 9, r = (u >> 3) & 63u, ch = (u & 7u) << 4;
            const char* src = (const char*)g_ks[sp] + (ull)(key0 + (int)r) * 2048ull + hb + ch;
            CP_ASYNC16(st + sp * KSZ + r * AP + ch, src);
        } else {
            u32 u2 = u - 1024u;
            u32 sp = u2 >> 9, r = (u2 >> 3) & 63u, ch = (u2 & 7u) << 4;
            const char* src = (const char*)g_vs[sp] + (ull)(key0 + (int)r) * 2048ull + hb + ch;
            CP_ASYNC16(st + 2u * KSZ + sp * KSZ + r * AP + ch, src);
        }
    }
    CP_COMMIT();
}

__global__ void __launch_bounds__(256) attn_mma_kernel() {
    extern __shared__ char sma[];
    u32 base = smem_to_u32(sma);
    const int tid = threadIdx.x, lane = tid & 31, w = tid >> 5;
    const int b = blockIdx.y >> 4, h = blockIdx.y & 15;
    const u32 hb = (u32)h * 128u;
    const int m0 = b * 2048 + (blockIdx.x << 7);
    const int kv0 = b * 2048;

    // Q tile: 2 splits x 128 rows x 8 chunks (own commit group)
#pragma unroll
    for (int i = 0; i < 8; i++) {
        u32 u = (u32)tid + (u32)i * 256u;
        u32 sp = u >> 10, r = (u >> 3) & 127u, ch = (u & 7u) << 4;
        const char* src = (const char*)g_qs[sp] + (ull)(m0 + (int)r) * 2048ull + hb + ch;
        CP_ASYNC16(base + sp * QSZ + r * AP + ch, src);
    }
    CP_COMMIT();
    attn_issue(base, 0, kv0, hb, tid);
    attn_issue(base, 1, kv0 + 64, hb, tid);
    CP_WAIT2();          // Q group complete
    __syncthreads();

    float o[8][4];
#pragma unroll
    for (int i = 0; i < 8; i++)
#pragma unroll
        for (int e = 0; e < 4; e++) o[i][e] = 0.f;
    float mg0 = -1e30f, mg1 = -1e30f, l0 = 0.f, l1 = 0.f;

    const u32 lrow = (u32)(lane & 15) * AP + (u32)(lane >> 4) * 16u;
    const u32 qbase = base + (u32)w * (16u * AP) + lrow;

    int s = 0;
    for (int c = 0; c < 32; c++) {
        if (c == 31) { CP_WAIT0(); } else { CP_WAIT1(); }
        __syncthreads();
        if (c + 2 < 32) {
            int s2 = (s + 2 >= 3) ? s - 1 : s + 2;
            attn_issue(base, s2, kv0 + (c + 2) * 64, hb, tid);
        }

        u32 stK = base + 2u * QSZ + (u32)s * ASTAGE;
        u32 stV = stK + 2u * KSZ;

        // ---- S = QK^T (4 products: hh, hl, lh, ll) ----
        float sv[8][4];
#pragma unroll
        for (int i = 0; i < 8; i++)
#pragma unroll
            for (int e = 0; e < 4; e++) sv[i][e] = 0.f;

#pragma unroll
        for (int ks = 0; ks < 4; ks++) {
            u32 aq[2][4];
#pragma unroll
            for (int sp = 0; sp < 2; sp++) LDMX4(aq[sp], qbase + sp * QSZ + (u32)ks * 32u);
#pragma unroll
            for (int sb = 0; sb < 2; sb++) {
                u32 bf[4][4];
                u32 bb = stK + (u32)sb * KSZ + lrow + (u32)ks * 32u;
#pragma unroll
                for (int q = 0; q < 4; q++) LDMX4(bf[q], bb + (u32)q * (16u * AP));
#pragma unroll
                for (int ai = 0; ai < 2; ai++)
#pragma unroll
                    for (int q = 0; q < 4; q++) {
                        mma16816(sv[2 * q],     aq[ai], bf[q][0], bf[q][2]);
                        mma16816(sv[2 * q + 1], aq[ai], bf[q][1], bf[q][3]);
                    }
            }
        }

        // ---- online softmax ----
        float cm0 = -1e30f, cm1 = -1e30f;
#pragma unroll
        for (int i = 0; i < 8; i++) {
            cm0 = fmaxf(cm0, fmaxf(sv[i][0], sv[i][1]));
            cm1 = fmaxf(cm1, fmaxf(sv[i][2], sv[i][3]));
        }
        cm0 = fmaxf(cm0, __shfl_xor_sync(0xffffffffu, cm0, 1));
        cm0 = fmaxf(cm0, __shfl_xor_sync(0xffffffffu, cm0, 2));
        cm1 = fmaxf(cm1, __shfl_xor_sync(0xffffffffu, cm1, 1));
        cm1 = fmaxf(cm1, __shfl_xor_sync(0xffffffffu, cm1, 2));
        float nm0 = fmaxf(mg0, cm0), nm1 = fmaxf(mg1, cm1);
        float corr0 = __expf(mg0 - nm0), corr1 = __expf(mg1 - nm1);
        float rs0 = 0.f, rs1 = 0.f;
#pragma unroll
        for (int i = 0; i < 8; i++) {
            sv[i][0] = __expf(sv[i][0] - nm0);
            sv[i][1] = __expf(sv[i][1] - nm0);
            sv[i][2] = __expf(sv[i][2] - nm1);
            sv[i][3] = __expf(sv[i][3] - nm1);
            rs0 += sv[i][0] + sv[i][1];
            rs1 += sv[i][2] + sv[i][3];
        }
        rs0 += __shfl_xor_sync(0xffffffffu, rs0, 1);
        rs0 += __shfl_xor_sync(0xffffffffu, rs0, 2);
        rs1 += __shfl_xor_sync(0xffffffffu, rs1, 1);
        rs1 += __shfl_xor_sync(0xffffffffu, rs1, 2);
        l0 = l0 * corr0 + rs0; l1 = l1 * corr1 + rs1;
        mg0 = nm0; mg1 = nm1;
#pragma unroll
        for (int i = 0; i < 8; i++) {
            o[i][0] *= corr0; o[i][1] *= corr0;
            o[i][2] *= corr1; o[i][3] *= corr1;
        }

        // ---- P -> fp16 2-split A-fragments ----
        u32 ph[4][4], pm[4][4];
#pragma unroll
        for (int j = 0; j < 4; j++) {
            split2pkh(sv[2 * j][0],     sv[2 * j][1],     ph[j][0], pm[j][0]);
            split2pkh(sv[2 * j][2],     sv[2 * j][3],     ph[j][1], pm[j][1]);
            split2pkh(sv[2 * j + 1][0], sv[2 * j + 1][1], ph[j][2], pm[j][2]);
            split2pkh(sv[2 * j + 1][2], sv[2 * j + 1][3], ph[j][3], pm[j][3]);
        }

        // ---- O += P V (3 products: PhVh, PmVh, PhVl) ----
#pragma unroll
        for (int j = 0; j < 4; j++) {
            u32 vrow = stV + (16u * (u32)j + (u32)(lane & 7) + (u32)((lane >> 4) << 3)) * AP
                       + (u32)(((lane >> 3) & 1) << 4);
            u32 bv[4][4];
#pragma unroll
            for (int q = 0; q < 4; q++) LDMX4T(bv[q], vrow + (u32)q * 32u);
#pragma unroll
            for (int q = 0; q < 4; q++) {
                mma16816(o[2 * q],     ph[j], bv[q][0], bv[q][2]);
                mma16816(o[2 * q + 1], ph[j], bv[q][1], bv[q][3]);
                mma16816(o[2 * q],     pm[j], bv[q][0], bv[q][2]);
                mma16816(o[2 * q + 1], pm[j], bv[q][1], bv[q][3]);
            }
#pragma unroll
            for (int q = 0; q < 4; q++) LDMX4T(bv[q], vrow + KSZ + (u32)q * 32u);
#pragma unroll
            for (int q = 0; q < 4; q++) {
                mma16816(o[2 * q],     ph[j], bv[q][0], bv[q][2]);
                mma16816(o[2 * q + 1], ph[j], bv[q][1], bv[q][3]);
            }
        }
        s = (s + 1 == 3) ? 0 : s + 1;
    }

    // ---- epilogue: normalize, write ctx fp16 2-splits ----
    float inv0 = 1.0f / l0, inv1 = 1.0f / l1;
    u32 r0 = (u32)m0 + (u32)w * 16u + (u32)(lane >> 2);
    u32 cb = (u32)h * 64u + (u32)((lane & 3) << 1);
#pragma unroll
    for (int i = 0; i < 8; i++) {
        u32 col = cb + (u32)i * 8u;
        u32 h01, l01, h23, l23;
        split2pkh(o[i][0] * inv0, o[i][1] * inv0, h01, l01);
        split2pkh(o[i][2] * inv1, o[i][3] * inv1, h23, l23);
        *(u32*)&g_cs[0][r0 * 1024u + col] = h01;
        *(u32*)&g_cs[1][r0 * 1024u + col] = l01;
        *(u32*)&g_cs[0][(r0 + 8u) * 1024u + col] = h23;
        *(u32*)&g_cs[1][(r0 + 8u) * 1024u + col] = l23;
    }
}

// ================= launch =================
extern "C" void kernel_launch(void* const* d_in, const int* in_sizes, int n_in,
                              void* d_out, int out_size) {
    const float* q  = (const float*)d_in[0];
    const float* k  = (const float*)d_in[1];
    const float* v  = (const float*)d_in[2];
    const float* Wq = (const float*)d_in[3];
    const float* Wk = (const float*)d_in[4];
    const float* Wv = (const float*)d_in[5];
    const float* Wo = (const float*)d_in[6];
    const float* bo = (const float*)d_in[7];
    float* out = (float*)d_out;

    split_qkv_kernel<<<dim3(4096, 3), 256>>>(q, k, v);
    split_w3_kernel<<<3072, 256>>>(Wq, Wk, Wv);
    split_wo_kernel<<<1024, 256>>>(Wo);

    cudaFuncSetAttribute(gemm_mma_kernel, cudaFuncAttributeMaxDynamicSharedMemorySize, GSMEM);
    gemm_mma_kernel<<<dim3(8, 32, 3), 256, GSMEM>>>(0, nullptr, nullptr);

    cudaFuncSetAttribute(attn_mma_kernel, cudaFuncAttributeMaxDynamicSharedMemorySize, ASMEM);
    attn_mma_kernel<<<dim3(16, 32), 256, ASMEM>>>();

    gemm_mma_kernel<<<dim3(8, 32, 1), 256, GSMEM>>>(3, out, bo);
}

// round 9
// speedup vs baseline: 2.3946x; 1.1167x over previous
#include <cuda_runtime.h>
#include <cuda_fp16.h>

typedef unsigned long long ull;
typedef unsigned int u32;

// ================= common helpers =================
__device__ __forceinline__ u32 smem_to_u32(const void* p) {
    u32 a; asm("{ .reg .u64 t; cvta.to.shared.u64 t, %1; cvt.u32.u64 %0, t; }" : "=r"(a) : "l"(p));
    return a;
}
#define CP_ASYNC16(dst, src) asm volatile("cp.async.cg.shared.global [%0], [%1], 16;" :: "r"(dst), "l"(src) : "memory")
#define CP_COMMIT()          asm volatile("cp.async.commit_group;" ::: "memory")
#define CP_WAIT0()           asm volatile("cp.async.wait_group 0;" ::: "memory")
#define CP_WAIT1()           asm volatile("cp.async.wait_group 1;" ::: "memory")

#define LDMX4(r, addr) \
    asm volatile("ldmatrix.sync.aligned.m8n8.x4.shared.b16 {%0,%1,%2,%3}, [%4];" \
        : "=r"((r)[0]), "=r"((r)[1]), "=r"((r)[2]), "=r"((r)[3]) : "r"(addr))
#define LDMX4T(r, addr) \
    asm volatile("ldmatrix.sync.aligned.m8n8.x4.trans.shared.b16 {%0,%1,%2,%3}, [%4];" \
        : "=r"((r)[0]), "=r"((r)[1]), "=r"((r)[2]), "=r"((r)[3]) : "r"(addr))

__device__ __forceinline__ void mma16816(float* c, const u32* a, u32 b0, u32 b1) {
    asm volatile("mma.sync.aligned.m16n8k16.row.col.f32.f16.f16.f32 "
        "{%0,%1,%2,%3}, {%4,%5,%6,%7}, {%8,%9}, {%0,%1,%2,%3};"
        : "+f"(c[0]), "+f"(c[1]), "+f"(c[2]), "+f"(c[3])
        : "r"(a[0]), "r"(a[1]), "r"(a[2]), "r"(a[3]), "r"(b0), "r"(b1));
}

// ================= global scratch (all fp16 2-splits) =================
__device__ __align__(256) __half g_as[3][2][4194304];  // input splits [mat][split][m*1024+k]
__device__ __align__(256) __half g_bs[4][2][1048576];  // weight splits [mat][split][n*1024+k]
__device__ __align__(256) __half g_qs[2][4194304];     // qh 2-split (prescaled 1/8)
__device__ __align__(256) __half g_ks[2][4194304];     // kh 2-split
__device__ __align__(256) __half g_vs[2][4194304];     // vh 2-split
__device__ __align__(256) __half g_cs[2][4194304];     // ctx 2-split

__constant__ int c_pa[3] = { 0, 0, 1 };
__constant__ int c_pb[3] = { 0, 1, 0 };

// ================= split helpers (fp16 h+l) =================
__device__ __forceinline__ u32 pk2h(__half a, __half b) {
    __half2 t = __halves2half2(a, b);
    return *reinterpret_cast<u32*>(&t);
}
__device__ __forceinline__ void split2h(float x, __half& h, __half& l) {
    h = __float2half_rn(x);
    l = __float2half_rn(x - __half2float(h));
}
__device__ __forceinline__ void split2pkh(float x, float y, u32& hi, u32& lo) {
    __half hx, lx, hy, ly;
    split2h(x, hx, lx); split2h(y, hy, ly);
    hi = pk2h(hx, hy); lo = pk2h(lx, ly);
}

// ================= input split kernels =================
__global__ void split_qkv_kernel(const float* __restrict__ q, const float* __restrict__ k,
                                 const float* __restrict__ v) {
    u32 idx = blockIdx.x * 256u + threadIdx.x;
    int y = blockIdx.y;
    const float* in = (y == 0) ? q : (y == 1) ? k : v;
    float4 x = ((const float4*)in)[idx];
    u32 h01, l01, h23, l23;
    split2pkh(x.x, x.y, h01, l01);
    split2pkh(x.z, x.w, h23, l23);
    u32 o = idx * 4u;
    *(uint2*)&g_as[y][0][o] = make_uint2(h01, h23);
    *(uint2*)&g_as[y][1][o] = make_uint2(l01, l23);
}

// Wq/Wk/Wv [h, d, kk] -> B[n=h*64+kk][k=d] splits
__global__ void split_w3_kernel(const float* __restrict__ Wq, const float* __restrict__ Wk,
                                const float* __restrict__ Wv) {
    u32 idx = blockIdx.x * 256u + threadIdx.x;
    u32 mat = idx >> 18, r = idx & 262143u;
    u32 n = r >> 8, d4 = r & 255u;
    u32 h = n >> 6, kk = n & 63u;
    const float* W = (mat == 0) ? Wq : (mat == 1) ? Wk : Wv;
    float xs[4];
#pragma unroll
    for (int j = 0; j < 4; j++) xs[j] = W[h * 65536u + (d4 * 4u + j) * 64u + kk];
    u32 h01, l01, h23, l23;
    split2pkh(xs[0], xs[1], h01, l01);
    split2pkh(xs[2], xs[3], h23, l23);
    u32 o = n * 1024u + d4 * 4u;
    *(uint2*)&g_bs[mat][0][o] = make_uint2(h01, h23);
    *(uint2*)&g_bs[mat][1][o] = make_uint2(l01, l23);
}

__global__ void split_wo_kernel(const float* __restrict__ Wo) {
    u32 idx = blockIdx.x * 256u + threadIdx.x;
    float4 x = ((const float4*)Wo)[idx];
    u32 h01, l01, h23, l23;
    split2pkh(x.x, x.y, h01, l01);
    split2pkh(x.z, x.w, h23, l23);
    u32 o = idx * 4u;
    *(uint2*)&g_bs[3][0][o] = make_uint2(h01, h23);
    *(uint2*)&g_bs[3][1][o] = make_uint2(l01, l23);
}

// ================= mma.sync split-fp32 GEMM (fp16 2-split, 3 products) ========
#define GPITCH 144u
#define GTILE  18432u        // 128 * 144
#define GSTAGE 36864u        // A + B
#define GSMEM  110592u       // 3 stages
#define ASPLIT 8388608ull
#define BSPLIT 2097152ull

__device__ __forceinline__ void gemm_issue(const char* aB, const char* bB, u32 base,
                                           int v, int s, u32 bm, u32 bn, int tid) {
    int p = v >> 4;
    u32 kb = (u32)(v & 15) * 128u;
    const char* srcA = aB + (ull)c_pa[p] * ASPLIT + kb;
    const char* srcB = bB + (ull)c_pb[p] * BSPLIT + kb;
    u32 stA = base + (u32)s * GSTAGE;
    u32 stB = stA + GTILE;
#pragma unroll
    for (int j = 0; j < 4; j++) {
        u32 c = (u32)tid + (u32)j * 256u;
        u32 row = c >> 3, ch = (c & 7u) << 4;
        CP_ASYNC16(stA + row * GPITCH + ch, srcA + (ull)(bm + row) * 2048ull + ch);
        CP_ASYNC16(stB + row * GPITCH + ch, srcB + (ull)(bn + row) * 2048ull + ch);
    }
    CP_COMMIT();
}

__global__ void __launch_bounds__(256) gemm_mma_kernel(int mat_base, float* Cout,
                                                       const float* __restrict__ bias) {
    extern __shared__ char sm_g[];
    u32 base = smem_to_u32(sm_g);
    const int tid = threadIdx.x, lane = tid & 31, wid = tid >> 5;
    const u32 bm = blockIdx.y << 7, bn = blockIdx.x << 7;
    const int wm = (wid >> 2) << 6, wn = (wid & 3) << 5;
    const int mat = mat_base + blockIdx.z;

    const char* aB; const char* bB;
    if (mat < 3) { aB = (const char*)g_as[mat][0]; bB = (const char*)g_bs[mat][0]; }
    else         { aB = (const char*)g_cs[0];      bB = (const char*)g_bs[3][0]; }

    float acc[4][4][4];
#pragma unroll
    for (int mi = 0; mi < 4; mi++)
#pragma unroll
        for (int ni = 0; ni < 4; ni++)
#pragma unroll
            for (int e = 0; e < 4; e++) acc[mi][ni][e] = 0.f;

    const int NV = 48;   // 3 products x 16 chunks
    gemm_issue(aB, bB, base, 0, 0, bm, bn, tid);
    gemm_issue(aB, bB, base, 1, 1, bm, bn, tid);

    int s = 0;
    for (int v = 0; v < NV; v++) {
        if (v == NV - 1) { CP_WAIT0(); } else { CP_WAIT1(); }
        __syncthreads();
        if (v + 2 < NV) {
            int s2 = (s + 2 >= 3) ? s - 1 : s + 2;
            gemm_issue(aB, bB, base, v + 2, s2, bm, bn, tid);
        }

        u32 stA = base + (u32)s * GSTAGE;
        u32 stB = stA + GTILE;
        u32 lrow = (u32)(lane & 15) * GPITCH + (u32)(lane >> 4) * 16u;
#pragma unroll
        for (int ks = 0; ks < 4; ks++) {
            u32 a[4][4], b[2][4];
            u32 abase = stA + (u32)wm * GPITCH + lrow + (u32)ks * 32u;
            u32 bbase = stB + (u32)wn * GPITCH + lrow + (u32)ks * 32u;
#pragma unroll
            for (int mi = 0; mi < 4; mi++) LDMX4(a[mi], abase + (u32)mi * (16u * GPITCH));
#pragma unroll
            for (int nj = 0; nj < 2; nj++) LDMX4(b[nj], bbase + (u32)nj * (16u * GPITCH));
#pragma unroll
            for (int mi = 0; mi < 4; mi++)
#pragma unroll
                for (int ni = 0; ni < 4; ni++)
                    mma16816(acc[mi][ni], a[mi], b[ni >> 1][ni & 1], b[ni >> 1][(ni & 1) + 2]);
        }
        s = (s + 1 == 3) ? 0 : s + 1;
    }

    const float pre = (mat == 0) ? 0.125f : 1.0f;
#pragma unroll
    for (int mi = 0; mi < 4; mi++)
#pragma unroll
        for (int ni = 0; ni < 4; ni++) {
            u32 r0 = bm + (u32)wm + (u32)mi * 16u + (u32)(lane >> 2);
            u32 col = bn + (u32)wn + (u32)ni * 8u + (u32)((lane & 3) << 1);
            float v0 = acc[mi][ni][0] * pre, v1 = acc[mi][ni][1] * pre;
            float v2 = acc[mi][ni][2] * pre, v3 = acc[mi][ni][3] * pre;
            if (mat == 3) {
                float b0 = bias[col], b1 = bias[col + 1];
                *(float2*)&Cout[(ull)r0 * 1024ull + col] = make_float2(v0 + b0, v1 + b1);
                *(float2*)&Cout[(ull)(r0 + 8) * 1024ull + col] = make_float2(v2 + b0, v3 + b1);
            } else {
                __half* d0; __half* d1;
                if (mat == 0)      { d0 = g_qs[0]; d1 = g_qs[1]; }
                else if (mat == 1) { d0 = g_ks[0]; d1 = g_ks[1]; }
                else               { d0 = g_vs[0]; d1 = g_vs[1]; }
                u32 h01, l01, h23, l23;
                split2pkh(v0, v1, h01, l01); split2pkh(v2, v3, h23, l23);
                *(u32*)&d0[r0 * 1024u + col] = h01;
                *(u32*)&d1[r0 * 1024u + col] = l01;
                *(u32*)&d0[(r0 + 8) * 1024u + col] = h23;
                *(u32*)&d1[(r0 + 8) * 1024u + col] = l23;
            }
        }
}

// ================= mma.sync flash attention (fp16 2-split, 2-stage, 2 CTA/SM) ======
// QK^T: 3 products (hh, hl, lh); PV: 3 products (PhVh, PlVh, PhVl).
#define AP   144u
#define QSZ  18432u     // 128*144 per split
#define KSZ  9216u      // 64*144 per split
#define ASTAGE 36864u   // 2 K splits + 2 V splits
#define ASMEM  110592u  // 2*QSZ + 2*ASTAGE

__device__ __forceinline__ void attn_issue(u32 base, int s, int key0, u32 hb, int tid) {
    u32 st = base + 2u * QSZ + (u32)s * ASTAGE;
#pragma unroll
    for (int i = 0; i < 8; i++) {
        u32 u = (u32)tid + (u32)i * 256u;
        if (u < 1024u) {
            u32 sp = u >> 9, r = (u >> 3) & 63u, ch = (u & 7u) << 4;
            const char* src = (const char*)g_ks[sp] + (ull)(key0 + (int)r) * 2048ull + hb + ch;
            CP_ASYNC16(st + sp * KSZ + r * AP + ch, src);
        } else {
            u32 u2 = u - 1024u;
            u32 sp = u2 >> 9, r = (u2 >> 3) & 63u, ch = (u2 & 7u) << 4;
            const char* src = (const char*)g_vs[sp] + (ull)(key0 + (int)r) * 2048ull + hb + ch;
            CP_ASYNC16(st + 2u * KSZ + sp * KSZ + r * AP + ch, src);
        }
    }
    CP_COMMIT();
}

__global__ void __launch_bounds__(256, 2) attn_mma_kernel() {
    extern __shared__ char sma[];
    u32 base = smem_to_u32(sma);
    const int tid = threadIdx.x, lane = tid & 31, w = tid >> 5;
    const int b = blockIdx.y >> 4, h = blockIdx.y & 15;
    const u32 hb = (u32)h * 128u;
    const int m0 = b * 2048 + (blockIdx.x << 7);
    const int kv0 = b * 2048;

    // Q tile: 2 splits x 128 rows x 8 chunks (own commit group)
#pragma unroll
    for (int i = 0; i < 8; i++) {
        u32 u = (u32)tid + (u32)i * 256u;
        u32 sp = u >> 10, r = (u >> 3) & 127u, ch = (u & 7u) << 4;
        const char* src = (const char*)g_qs[sp] + (ull)(m0 + (int)r) * 2048ull + hb + ch;
        CP_ASYNC16(base + sp * QSZ + r * AP + ch, src);
    }
    CP_COMMIT();
    attn_issue(base, 0, kv0, hb, tid);

    float o[8][4];
#pragma unroll
    for (int i = 0; i < 8; i++)
#pragma unroll
        for (int e = 0; e < 4; e++) o[i][e] = 0.f;
    float mg0 = -1e30f, mg1 = -1e30f, l0 = 0.f, l1 = 0.f;

    const u32 lrow = (u32)(lane & 15) * AP + (u32)(lane >> 4) * 16u;
    const u32 qbase = base + (u32)w * (16u * AP) + lrow;

    for (int c = 0; c < 32; c++) {
        if (c + 1 < 32) { attn_issue(base, (c + 1) & 1, kv0 + (c + 1) * 64, hb, tid); CP_WAIT1(); }
        else            { CP_WAIT0(); }
        __syncthreads();

        u32 stK = base + 2u * QSZ + (u32)(c & 1) * ASTAGE;
        u32 stV = stK + 2u * KSZ;

        // ---- S = QK^T (3 products: hh, hl, lh) ----
        float sv[8][4];
#pragma unroll
        for (int i = 0; i < 8; i++)
#pragma unroll
            for (int e = 0; e < 4; e++) sv[i][e] = 0.f;

#pragma unroll
        for (int ks = 0; ks < 4; ks++) {
            u32 aq[2][4];
#pragma unroll
            for (int sp = 0; sp < 2; sp++) LDMX4(aq[sp], qbase + sp * QSZ + (u32)ks * 32u);
#pragma unroll
            for (int sb = 0; sb < 2; sb++) {
                u32 bf[4][4];
                u32 bb = stK + (u32)sb * KSZ + lrow + (u32)ks * 32u;
#pragma unroll
                for (int q = 0; q < 4; q++) LDMX4(bf[q], bb + (u32)q * (16u * AP));
                const int na = (sb == 0) ? 2 : 1;   // drop ll
#pragma unroll
                for (int ai = 0; ai < 2; ai++) {
                    if (ai < na) {
#pragma unroll
                        for (int q = 0; q < 4; q++) {
                            mma16816(sv[2 * q],     aq[ai], bf[q][0], bf[q][2]);
                            mma16816(sv[2 * q + 1], aq[ai], bf[q][1], bf[q][3]);
                        }
                    }
                }
            }
        }

        // ---- online softmax ----
        float cm0 = -1e30f, cm1 = -1e30f;
#pragma unroll
        for (int i = 0; i < 8; i++) {
            cm0 = fmaxf(cm0, fmaxf(sv[i][0], sv[i][1]));
            cm1 = fmaxf(cm1, fmaxf(sv[i][2], sv[i][3]));
        }
        cm0 = fmaxf(cm0, __shfl_xor_sync(0xffffffffu, cm0, 1));
        cm0 = fmaxf(cm0, __shfl_xor_sync(0xffffffffu, cm0, 2));
        cm1 = fmaxf(cm1, __shfl_xor_sync(0xffffffffu, cm1, 1));
        cm1 = fmaxf(cm1, __shfl_xor_sync(0xffffffffu, cm1, 2));
        float nm0 = fmaxf(mg0, cm0), nm1 = fmaxf(mg1, cm1);
        float corr0 = __expf(mg0 - nm0), corr1 = __expf(mg1 - nm1);
        float rs0 = 0.f, rs1 = 0.f;
#pragma unroll
        for (int i = 0; i < 8; i++) {
            sv[i][0] = __expf(sv[i][0] - nm0);
            sv[i][1] = __expf(sv[i][1] - nm0);
            sv[i][2] = __expf(sv[i][2] - nm1);
            sv[i][3] = __expf(sv[i][3] - nm1);
            rs0 += sv[i][0] + sv[i][1];
            rs1 += sv[i][2] + sv[i][3];
        }
        rs0 += __shfl_xor_sync(0xffffffffu, rs0, 1);
        rs0 += __shfl_xor_sync(0xffffffffu, rs0, 2);
        rs1 += __shfl_xor_sync(0xffffffffu, rs1, 1);
        rs1 += __shfl_xor_sync(0xffffffffu, rs1, 2);
        l0 = l0 * corr0 + rs0; l1 = l1 * corr1 + rs1;
        mg0 = nm0; mg1 = nm1;
#pragma unroll
        for (int i = 0; i < 8; i++) {
            o[i][0] *= corr0; o[i][1] *= corr0;
            o[i][2] *= corr1; o[i][3] *= corr1;
        }

        // ---- P -> fp16 2-split A-fragments ----
        u32 ph[4][4], pm[4][4];
#pragma unroll
        for (int j = 0; j < 4; j++) {
            split2pkh(sv[2 * j][0],     sv[2 * j][1],     ph[j][0], pm[j][0]);
            split2pkh(sv[2 * j][2],     sv[2 * j][3],     ph[j][1], pm[j][1]);
            split2pkh(sv[2 * j + 1][0], sv[2 * j + 1][1], ph[j][2], pm[j][2]);
            split2pkh(sv[2 * j + 1][2], sv[2 * j + 1][3], ph[j][3], pm[j][3]);
        }

        // ---- O += P V (3 products: PhVh, PlVh, PhVl) ----
#pragma unroll
        for (int j = 0; j < 4; j++) {
            u32 vrow = stV + (16u * (u32)j + (u32)(lane & 7) + (u32)((lane >> 4) << 3)) * AP
                       + (u32)(((lane >> 3) & 1) << 4);
            u32 bv[4][4];
#pragma unroll
            for (int q = 0; q < 4; q++) LDMX4T(bv[q], vrow + (u32)q * 32u);
#pragma unroll
            for (int q = 0; q < 4; q++) {
                mma16816(o[2 * q],     ph[j], bv[q][0], bv[q][2]);
                mma16816(o[2 * q + 1], ph[j], bv[q][1], bv[q][3]);
                mma16816(o[2 * q],     pm[j], bv[q][0], bv[q][2]);
                mma16816(o[2 * q + 1], pm[j], bv[q][1], bv[q][3]);
            }
#pragma unroll
            for (int q = 0; q < 4; q++) LDMX4T(bv[q], vrow + KSZ + (u32)q * 32u);
#pragma unroll
            for (int q = 0; q < 4; q++) {
                mma16816(o[2 * q],     ph[j], bv[q][0], bv[q][2]);
                mma16816(o[2 * q + 1], ph[j], bv[q][1], bv[q][3]);
            }
        }
        __syncthreads();
    }

    // ---- epilogue: normalize, write ctx fp16 2-splits ----
    float inv0 = 1.0f / l0, inv1 = 1.0f / l1;
    u32 r0 = (u32)m0 + (u32)w * 16u + (u32)(lane >> 2);
    u32 cb = (u32)h * 64u + (u32)((lane & 3) << 1);
#pragma unroll
    for (int i = 0; i < 8; i++) {
        u32 col = cb + (u32)i * 8u;
        u32 h01, l01, h23, l23;
        split2pkh(o[i][0] * inv0, o[i][1] * inv0, h01, l01);
        split2pkh(o[i][2] * inv1, o[i][3] * inv1, h23, l23);
        *(u32*)&g_cs[0][r0 * 1024u + col] = h01;
        *(u32*)&g_cs[1][r0 * 1024u + col] = l01;
        *(u32*)&g_cs[0][(r0 + 8u) * 1024u + col] = h23;
        *(u32*)&g_cs[1][(r0 + 8u) * 1024u + col] = l23;
    }
}

// ================= launch =================
extern "C" void kernel_launch(void* const* d_in, const int* in_sizes, int n_in,
                              void* d_out, int out_size) {
    const float* q  = (const float*)d_in[0];
    const float* k  = (const float*)d_in[1];
    const float* v  = (const float*)d_in[2];
    const float* Wq = (const float*)d_in[3];
    const float* Wk = (const float*)d_in[4];
    const float* Wv = (const float*)d_in[5];
    const float* Wo = (const float*)d_in[6];
    const float* bo = (const float*)d_in[7];
    float* out = (float*)d_out;

    split_qkv_kernel<<<dim3(4096, 3), 256>>>(q, k, v);
    split_w3_kernel<<<3072, 256>>>(Wq, Wk, Wv);
    split_wo_kernel<<<1024, 256>>>(Wo);

    cudaFuncSetAttribute(gemm_mma_kernel, cudaFuncAttributeMaxDynamicSharedMemorySize, GSMEM);
    gemm_mma_kernel<<<dim3(8, 32, 3), 256, GSMEM>>>(0, nullptr, nullptr);

    cudaFuncSetAttribute(attn_mma_kernel, cudaFuncAttributeMaxDynamicSharedMemorySize, ASMEM);
    attn_mma_kernel<<<dim3(16, 32), 256, ASMEM>>>();

    gemm_mma_kernel<<<dim3(8, 32, 1), 256, GSMEM>>>(3, out, bo);
}

// round 10
// speedup vs baseline: 2.6605x; 1.1111x over previous
#include <cuda_runtime.h>
#include <cuda_fp16.h>

typedef unsigned long long ull;
typedef unsigned int u32;

// ================= common helpers =================
__device__ __forceinline__ u32 smem_to_u32(const void* p) {
    u32 a; asm("{ .reg .u64 t; cvta.to.shared.u64 t, %1; cvt.u32.u64 %0, t; }" : "=r"(a) : "l"(p));
    return a;
}
#define CP_ASYNC16(dst, src) asm volatile("cp.async.cg.shared.global [%0], [%1], 16;" :: "r"(dst), "l"(src) : "memory")
#define CP_COMMIT()          asm volatile("cp.async.commit_group;" ::: "memory")
#define CP_WAIT0()           asm volatile("cp.async.wait_group 0;" ::: "memory")
#define CP_WAIT1()           asm volatile("cp.async.wait_group 1;" ::: "memory")

#define LDMX4(r, addr) \
    asm volatile("ldmatrix.sync.aligned.m8n8.x4.shared.b16 {%0,%1,%2,%3}, [%4];" \
        : "=r"((r)[0]), "=r"((r)[1]), "=r"((r)[2]), "=r"((r)[3]) : "r"(addr))
#define LDMX4T(r, addr) \
    asm volatile("ldmatrix.sync.aligned.m8n8.x4.trans.shared.b16 {%0,%1,%2,%3}, [%4];" \
        : "=r"((r)[0]), "=r"((r)[1]), "=r"((r)[2]), "=r"((r)[3]) : "r"(addr))

__device__ __forceinline__ void mma16816(float* c, const u32* a, u32 b0, u32 b1) {
    asm volatile("mma.sync.aligned.m16n8k16.row.col.f32.f16.f16.f32 "
        "{%0,%1,%2,%3}, {%4,%5,%6,%7}, {%8,%9}, {%0,%1,%2,%3};"
        : "+f"(c[0]), "+f"(c[1]), "+f"(c[2]), "+f"(c[3])
        : "r"(a[0]), "r"(a[1]), "r"(a[2]), "r"(a[3]), "r"(b0), "r"(b1));
}

// ================= global scratch =================
__device__ __align__(256) __half g_as[3][2][4194304];  // input splits [mat][split][m*1024+k]
__device__ __align__(256) __half g_bs[4][2][1048576];  // weight splits [mat][split][n*1024+k]
__device__ __align__(256) __half g_qs[2][4194304];     // qh 2-split (prescaled 1/8)
__device__ __align__(256) __half g_ks[2][4194304];     // kh 2-split
__device__ __align__(256) __half g_vs[4194304];        // vh single fp16
__device__ __align__(256) __half g_cs[4194304];        // ctx single fp16

__constant__ int c_pa[3] = { 0, 0, 1 };
__constant__ int c_pb[3] = { 0, 1, 0 };

// ================= split helpers (fp16 h+l) =================
__device__ __forceinline__ u32 pk2h(__half a, __half b) {
    __half2 t = __halves2half2(a, b);
    return *reinterpret_cast<u32*>(&t);
}
__device__ __forceinline__ void split2h(float x, __half& h, __half& l) {
    h = __float2half_rn(x);
    l = __float2half_rn(x - __half2float(h));
}
__device__ __forceinline__ void split2pkh(float x, float y, u32& hi, u32& lo) {
    __half hx, lx, hy, ly;
    split2h(x, hx, lx); split2h(y, hy, ly);
    hi = pk2h(hx, hy); lo = pk2h(lx, ly);
}

// ================= input split kernels =================
__global__ void split_qkv_kernel(const float* __restrict__ q, const float* __restrict__ k,
                                 const float* __restrict__ v) {
    u32 idx = blockIdx.x * 256u + threadIdx.x;
    int y = blockIdx.y;
    const float* in = (y == 0) ? q : (y == 1) ? k : v;
    float4 x = ((const float4*)in)[idx];
    u32 h01, l01, h23, l23;
    split2pkh(x.x, x.y, h01, l01);
    split2pkh(x.z, x.w, h23, l23);
    u32 o = idx * 4u;
    *(uint2*)&g_as[y][0][o] = make_uint2(h01, h23);
    *(uint2*)&g_as[y][1][o] = make_uint2(l01, l23);
}

// Wq/Wk/Wv [h, d, kk] -> B[n=h*64+kk][k=d] splits
__global__ void split_w3_kernel(const float* __restrict__ Wq, const float* __restrict__ Wk,
                                const float* __restrict__ Wv) {
    u32 idx = blockIdx.x * 256u + threadIdx.x;
    u32 mat = idx >> 18, r = idx & 262143u;
    u32 n = r >> 8, d4 = r & 255u;
    u32 h = n >> 6, kk = n & 63u;
    const float* W = (mat == 0) ? Wq : (mat == 1) ? Wk : Wv;
    float xs[4];
#pragma unroll
    for (int j = 0; j < 4; j++) xs[j] = W[h * 65536u + (d4 * 4u + j) * 64u + kk];
    u32 h01, l01, h23, l23;
    split2pkh(xs[0], xs[1], h01, l01);
    split2pkh(xs[2], xs[3], h23, l23);
    u32 o = n * 1024u + d4 * 4u;
    *(uint2*)&g_bs[mat][0][o] = make_uint2(h01, h23);
    *(uint2*)&g_bs[mat][1][o] = make_uint2(l01, l23);
}

__global__ void split_wo_kernel(const float* __restrict__ Wo) {
    u32 idx = blockIdx.x * 256u + threadIdx.x;
    float4 x = ((const float4*)Wo)[idx];
    u32 h01, l01, h23, l23;
    split2pkh(x.x, x.y, h01, l01);
    split2pkh(x.z, x.w, h23, l23);
    u32 o = idx * 4u;
    *(uint2*)&g_bs[3][0][o] = make_uint2(h01, h23);
    *(uint2*)&g_bs[3][1][o] = make_uint2(l01, l23);
}

// ================= mma.sync split-fp32 GEMM =================
// mats 0..2: A 2-split x W 2-split, 3 products. mat 3: A single x Wo 2-split, 2 products.
#define GPITCH 144u
#define GTILE  18432u        // 128 * 144
#define GSTAGE 36864u        // A + B
#define GSMEM  110592u       // 3 stages
#define BSPLIT 2097152ull

__device__ __forceinline__ void gemm_issue(const char* aB, const char* bB, ull asplit,
                                           u32 base, int v, int s, u32 bm, u32 bn, int tid) {
    int p = v >> 4;
    u32 kb = (u32)(v & 15) * 128u;
    const char* srcA = aB + (ull)c_pa[p] * asplit + kb;
    const char* srcB = bB + (ull)c_pb[p] * BSPLIT + kb;
    u32 stA = base + (u32)s * GSTAGE;
    u32 stB = stA + GTILE;
#pragma unroll
    for (int j = 0; j < 4; j++) {
        u32 c = (u32)tid + (u32)j * 256u;
        u32 row = c >> 3, ch = (c & 7u) << 4;
        CP_ASYNC16(stA + row * GPITCH + ch, srcA + (ull)(bm + row) * 2048ull + ch);
        CP_ASYNC16(stB + row * GPITCH + ch, srcB + (ull)(bn + row) * 2048ull + ch);
    }
    CP_COMMIT();
}

__global__ void __launch_bounds__(256) gemm_mma_kernel(int mat_base, float* Cout,
                                                       const float* __restrict__ bias) {
    extern __shared__ char sm_g[];
    u32 base = smem_to_u32(sm_g);
    const int tid = threadIdx.x, lane = tid & 31, wid = tid >> 5;
    const u32 bm = blockIdx.y << 7, bn = blockIdx.x << 7;
    const int wm = (wid >> 2) << 6, wn = (wid & 3) << 5;
    const int mat = mat_base + blockIdx.z;

    const char* aB; const char* bB; ull asplit;
    if (mat < 3) { aB = (const char*)g_as[mat][0]; bB = (const char*)g_bs[mat][0]; asplit = 8388608ull; }
    else         { aB = (const char*)g_cs;         bB = (const char*)g_bs[3][0];   asplit = 0ull; }

    float acc[4][4][4];
#pragma unroll
    for (int mi = 0; mi < 4; mi++)
#pragma unroll
        for (int ni = 0; ni < 4; ni++)
#pragma unroll
            for (int e = 0; e < 4; e++) acc[mi][ni][e] = 0.f;

    const int NV = (mat == 3) ? 32 : 48;
    gemm_issue(aB, bB, asplit, base, 0, 0, bm, bn, tid);
    gemm_issue(aB, bB, asplit, base, 1, 1, bm, bn, tid);

    int s = 0;
    for (int v = 0; v < NV; v++) {
        if (v == NV - 1) { CP_WAIT0(); } else { CP_WAIT1(); }
        __syncthreads();
        if (v + 2 < NV) {
            int s2 = (s + 2 >= 3) ? s - 1 : s + 2;
            gemm_issue(aB, bB, asplit, base, v + 2, s2, bm, bn, tid);
        }

        u32 stA = base + (u32)s * GSTAGE;
        u32 stB = stA + GTILE;
        u32 lrow = (u32)(lane & 15) * GPITCH + (u32)(lane >> 4) * 16u;
#pragma unroll
        for (int ks = 0; ks < 4; ks++) {
            u32 a[4][4], b[2][4];
            u32 abase = stA + (u32)wm * GPITCH + lrow + (u32)ks * 32u;
            u32 bbase = stB + (u32)wn * GPITCH + lrow + (u32)ks * 32u;
#pragma unroll
            for (int mi = 0; mi < 4; mi++) LDMX4(a[mi], abase + (u32)mi * (16u * GPITCH));
#pragma unroll
            for (int nj = 0; nj < 2; nj++) LDMX4(b[nj], bbase + (u32)nj * (16u * GPITCH));
#pragma unroll
            for (int mi = 0; mi < 4; mi++)
#pragma unroll
                for (int ni = 0; ni < 4; ni++)
                    mma16816(acc[mi][ni], a[mi], b[ni >> 1][ni & 1], b[ni >> 1][(ni & 1) + 2]);
        }
        s = (s + 1 == 3) ? 0 : s + 1;
    }

    const float pre = (mat == 0) ? 0.125f : 1.0f;
#pragma unroll
    for (int mi = 0; mi < 4; mi++)
#pragma unroll
        for (int ni = 0; ni < 4; ni++) {
            u32 r0 = bm + (u32)wm + (u32)mi * 16u + (u32)(lane >> 2);
            u32 col = bn + (u32)wn + (u32)ni * 8u + (u32)((lane & 3) << 1);
            float v0 = acc[mi][ni][0] * pre, v1 = acc[mi][ni][1] * pre;
            float v2 = acc[mi][ni][2] * pre, v3 = acc[mi][ni][3] * pre;
            if (mat == 3) {
                float b0 = bias[col], b1 = bias[col + 1];
                *(float2*)&Cout[(ull)r0 * 1024ull + col] = make_float2(v0 + b0, v1 + b1);
                *(float2*)&Cout[(ull)(r0 + 8) * 1024ull + col] = make_float2(v2 + b0, v3 + b1);
            } else if (mat == 2) {
                *(u32*)&g_vs[r0 * 1024u + col] =
                    pk2h(__float2half_rn(v0), __float2half_rn(v1));
                *(u32*)&g_vs[(r0 + 8) * 1024u + col] =
                    pk2h(__float2half_rn(v2), __float2half_rn(v3));
            } else {
                __half* d0 = (mat == 0) ? g_qs[0] : g_ks[0];
                __half* d1 = (mat == 0) ? g_qs[1] : g_ks[1];
                u32 h01, l01, h23, l23;
                split2pkh(v0, v1, h01, l01); split2pkh(v2, v3, h23, l23);
                *(u32*)&d0[r0 * 1024u + col] = h01;
                *(u32*)&d1[r0 * 1024u + col] = l01;
                *(u32*)&d0[(r0 + 8) * 1024u + col] = h23;
                *(u32*)&d1[(r0 + 8) * 1024u + col] = l23;
            }
        }
}

// ================= mma.sync flash attention =================
// QK^T: 3 products (hh, hl, lh); PV: 2 products (PhV, PlV), V single fp16.
#define AP   144u
#define QSZ  18432u     // 128*144 per split
#define KSZ  9216u      // 64*144 per split
#define ASTAGE 27648u   // 2 K splits + 1 V
#define ASMEM  92160u   // 2*QSZ + 2*ASTAGE

__device__ __forceinline__ void attn_issue(u32 base, int s, int key0, u32 hb, int tid) {
    u32 st = base + 2u * QSZ + (u32)s * ASTAGE;
#pragma unroll
    for (int i = 0; i < 6; i++) {
        u32 u = (u32)tid + (u32)i * 256u;
        if (u < 1024u) {
            u32 sp = u >> 9, r = (u >> 3) & 63u, ch = (u & 7u) << 4;
            const char* src = (const char*)g_ks[sp] + (ull)(key0 + (int)r) * 2048ull + hb + ch;
            CP_ASYNC16(st + sp * KSZ + r * AP + ch, src);
        } else {
            u32 u2 = u - 1024u;
            u32 r = u2 >> 3, ch = (u2 & 7u) << 4;
            const char* src = (const char*)g_vs + (ull)(key0 + (int)r) * 2048ull + hb + ch;
            CP_ASYNC16(st + 2u * KSZ + r * AP + ch, src);
        }
    }
    CP_COMMIT();
}

__global__ void __launch_bounds__(256, 2) attn_mma_kernel() {
    extern __shared__ char sma[];
    u32 base = smem_to_u32(sma);
    const int tid = threadIdx.x, lane = tid & 31, w = tid >> 5;
    const int b = blockIdx.y >> 4, h = blockIdx.y & 15;
    const u32 hb = (u32)h * 128u;
    const int m0 = b * 2048 + (blockIdx.x << 7);
    const int kv0 = b * 2048;

    // Q tile: 2 splits x 128 rows x 8 chunks (own commit group)
#pragma unroll
    for (int i = 0; i < 8; i++) {
        u32 u = (u32)tid + (u32)i * 256u;
        u32 sp = u >> 10, r = (u >> 3) & 127u, ch = (u & 7u) << 4;
        const char* src = (const char*)g_qs[sp] + (ull)(m0 + (int)r) * 2048ull + hb + ch;
        CP_ASYNC16(base + sp * QSZ + r * AP + ch, src);
    }
    CP_COMMIT();
    attn_issue(base, 0, kv0, hb, tid);

    float o[8][4];
#pragma unroll
    for (int i = 0; i < 8; i++)
#pragma unroll
        for (int e = 0; e < 4; e++) o[i][e] = 0.f;
    float mg0 = -1e30f, mg1 = -1e30f, l0 = 0.f, l1 = 0.f;

    const u32 lrow = (u32)(lane & 15) * AP + (u32)(lane >> 4) * 16u;
    const u32 qbase = base + (u32)w * (16u * AP) + lrow;

    for (int c = 0; c < 32; c++) {
        if (c + 1 < 32) { attn_issue(base, (c + 1) & 1, kv0 + (c + 1) * 64, hb, tid); CP_WAIT1(); }
        else            { CP_WAIT0(); }
        __syncthreads();

        u32 stK = base + 2u * QSZ + (u32)(c & 1) * ASTAGE;
        u32 stV = stK + 2u * KSZ;

        // ---- S = QK^T (3 products: hh, hl, lh) ----
        float sv[8][4];
#pragma unroll
        for (int i = 0; i < 8; i++)
#pragma unroll
            for (int e = 0; e < 4; e++) sv[i][e] = 0.f;

#pragma unroll
        for (int ks = 0; ks < 4; ks++) {
            u32 aq[2][4];
#pragma unroll
            for (int sp = 0; sp < 2; sp++) LDMX4(aq[sp], qbase + sp * QSZ + (u32)ks * 32u);
#pragma unroll
            for (int sb = 0; sb < 2; sb++) {
                u32 bf[4][4];
                u32 bb = stK + (u32)sb * KSZ + lrow + (u32)ks * 32u;
#pragma unroll
                for (int q = 0; q < 4; q++) LDMX4(bf[q], bb + (u32)q * (16u * AP));
                const int na = (sb == 0) ? 2 : 1;   // hh, lh | hl
#pragma unroll
                for (int ai = 0; ai < 2; ai++) {
                    if (ai < na) {
#pragma unroll
                        for (int q = 0; q < 4; q++) {
                            mma16816(sv[2 * q],     aq[ai], bf[q][0], bf[q][2]);
                            mma16816(sv[2 * q + 1], aq[ai], bf[q][1], bf[q][3]);
                        }
                    }
                }
            }
        }

        // ---- online softmax ----
        float cm0 = -1e30f, cm1 = -1e30f;
#pragma unroll
        for (int i = 0; i < 8; i++) {
            cm0 = fmaxf(cm0, fmaxf(sv[i][0], sv[i][1]));
            cm1 = fmaxf(cm1, fmaxf(sv[i][2], sv[i][3]));
        }
        cm0 = fmaxf(cm0, __shfl_xor_sync(0xffffffffu, cm0, 1));
        cm0 = fmaxf(cm0, __shfl_xor_sync(0xffffffffu, cm0, 2));
        cm1 = fmaxf(cm1, __shfl_xor_sync(0xffffffffu, cm1, 1));
        cm1 = fmaxf(cm1, __shfl_xor_sync(0xffffffffu, cm1, 2));
        float nm0 = fmaxf(mg0, cm0), nm1 = fmaxf(mg1, cm1);
        float corr0 = __expf(mg0 - nm0), corr1 = __expf(mg1 - nm1);
        float rs0 = 0.f, rs1 = 0.f;
#pragma unroll
        for (int i = 0; i < 8; i++) {
            sv[i][0] = __expf(sv[i][0] - nm0);
            sv[i][1] = __expf(sv[i][1] - nm0);
            sv[i][2] = __expf(sv[i][2] - nm1);
            sv[i][3] = __expf(sv[i][3] - nm1);
            rs0 += sv[i][0] + sv[i][1];
            rs1 += sv[i][2] + sv[i][3];
        }
        rs0 += __shfl_xor_sync(0xffffffffu, rs0, 1);
        rs0 += __shfl_xor_sync(0xffffffffu, rs0, 2);
        rs1 += __shfl_xor_sync(0xffffffffu, rs1, 1);
        rs1 += __shfl_xor_sync(0xffffffffu, rs1, 2);
        l0 = l0 * corr0 + rs0; l1 = l1 * corr1 + rs1;
        mg0 = nm0; mg1 = nm1;
#pragma unroll
        for (int i = 0; i < 8; i++) {
            o[i][0] *= corr0; o[i][1] *= corr0;
            o[i][2] *= corr1; o[i][3] *= corr1;
        }

        // ---- P -> fp16 2-split A-fragments ----
        u32 ph[4][4], pm[4][4];
#pragma unroll
        for (int j = 0; j < 4; j++) {
            split2pkh(sv[2 * j][0],     sv[2 * j][1],     ph[j][0], pm[j][0]);
            split2pkh(sv[2 * j][2],     sv[2 * j][3],     ph[j][1], pm[j][1]);
            split2pkh(sv[2 * j + 1][0], sv[2 * j + 1][1], ph[j][2], pm[j][2]);
            split2pkh(sv[2 * j + 1][2], sv[2 * j + 1][3], ph[j][3], pm[j][3]);
        }

        // ---- O += P V (2 products: PhV, PlV; V single fp16) ----
#pragma unroll
        for (int j = 0; j < 4; j++) {
            u32 vrow = stV + (16u * (u32)j + (u32)(lane & 7) + (u32)((lane >> 4) << 3)) * AP
                       + (u32)(((lane >> 3) & 1) << 4);
            u32 bv[4][4];
#pragma unroll
            for (int q = 0; q < 4; q++) LDMX4T(bv[q], vrow + (u32)q * 32u);
#pragma unroll
            for (int q = 0; q < 4; q++) {
                mma16816(o[2 * q],     ph[j], bv[q][0], bv[q][2]);
                mma16816(o[2 * q + 1], ph[j], bv[q][1], bv[q][3]);
                mma16816(o[2 * q],     pm[j], bv[q][0], bv[q][2]);
                mma16816(o[2 * q + 1], pm[j], bv[q][1], bv[q][3]);
            }
        }
        __syncthreads();
    }

    // ---- epilogue: normalize, write ctx single fp16 ----
    float inv0 = 1.0f / l0, inv1 = 1.0f / l1;
    u32 r0 = (u32)m0 + (u32)w * 16u + (u32)(lane >> 2);
    u32 cb = (u32)h * 64u + (u32)((lane & 3) << 1);
#pragma unroll
    for (int i = 0; i < 8; i++) {
        u32 col = cb + (u32)i * 8u;
        *(u32*)&g_cs[r0 * 1024u + col] =
            pk2h(__float2half_rn(o[i][0] * inv0), __float2half_rn(o[i][1] * inv0));
        *(u32*)&g_cs[(r0 + 8u) * 1024u + col] =
            pk2h(__float2half_rn(o[i][2] * inv1), __float2half_rn(o[i][3] * inv1));
    }
}

// ================= launch =================
extern "C" void kernel_launch(void* const* d_in, const int* in_sizes, int n_in,
                              void* d_out, int out_size) {
    const float* q  = (const float*)d_in[0];
    const float* k  = (const float*)d_in[1];
    const float* v  = (const float*)d_in[2];
    const float* Wq = (const float*)d_in[3];
    const float* Wk = (const float*)d_in[4];
    const float* Wv = (const float*)d_in[5];
    const float* Wo = (const float*)d_in[6];
    const float* bo = (const float*)d_in[7];
    float* out = (float*)d_out;

    split_qkv_kernel<<<dim3(4096, 3), 256>>>(q, k, v);
    split_w3_kernel<<<3072, 256>>>(Wq, Wk, Wv);
    split_wo_kernel<<<1024, 256>>>(Wo);

    cudaFuncSetAttribute(gemm_mma_kernel, cudaFuncAttributeMaxDynamicSharedMemorySize, GSMEM);
    gemm_mma_kernel<<<dim3(8, 32, 3), 256, GSMEM>>>(0, nullptr, nullptr);

    cudaFuncSetAttribute(attn_mma_kernel, cudaFuncAttributeMaxDynamicSharedMemorySize, ASMEM);
    attn_mma_kernel<<<dim3(16, 32), 256, ASMEM>>>();

    gemm_mma_kernel<<<dim3(8, 32, 1), 256, GSMEM>>>(3, out, bo);
}

// round 11
// speedup vs baseline: 3.3071x; 1.2430x over previous
#include <cuda_runtime.h>
#include <cuda_fp16.h>

typedef unsigned long long ull;
typedef unsigned int u32;

// ================= common helpers =================
__device__ __forceinline__ u32 smem_to_u32(const void* p) {
    u32 a; asm("{ .reg .u64 t; cvta.to.shared.u64 t, %1; cvt.u32.u64 %0, t; }" : "=r"(a) : "l"(p));
    return a;
}
#define CP_ASYNC16(dst, src) asm volatile("cp.async.cg.shared.global [%0], [%1], 16;" :: "r"(dst), "l"(src) : "memory")
#define CP_COMMIT()          asm volatile("cp.async.commit_group;" ::: "memory")
#define CP_WAIT0()           asm volatile("cp.async.wait_group 0;" ::: "memory")
#define CP_WAIT1()           asm volatile("cp.async.wait_group 1;" ::: "memory")

#define LDMX4(r, addr) \
    asm volatile("ldmatrix.sync.aligned.m8n8.x4.shared.b16 {%0,%1,%2,%3}, [%4];" \
        : "=r"((r)[0]), "=r"((r)[1]), "=r"((r)[2]), "=r"((r)[3]) : "r"(addr))
#define LDMX4T(r, addr) \
    asm volatile("ldmatrix.sync.aligned.m8n8.x4.trans.shared.b16 {%0,%1,%2,%3}, [%4];" \
        : "=r"((r)[0]), "=r"((r)[1]), "=r"((r)[2]), "=r"((r)[3]) : "r"(addr))

__device__ __forceinline__ void mma16816(float* c, const u32* a, u32 b0, u32 b1) {
    asm volatile("mma.sync.aligned.m16n8k16.row.col.f32.f16.f16.f32 "
        "{%0,%1,%2,%3}, {%4,%5,%6,%7}, {%8,%9}, {%0,%1,%2,%3};"
        : "+f"(c[0]), "+f"(c[1]), "+f"(c[2]), "+f"(c[3])
        : "r"(a[0]), "r"(a[1]), "r"(a[2]), "r"(a[3]), "r"(b0), "r"(b1));
}

// ================= global scratch =================
__device__ __align__(256) __half g_as[3][2][4194304];  // input splits [mat][split][m*1024+k]
__device__ __align__(256) __half g_bs[4][2][1048576];  // weight splits [mat][split][n*1024+k]
__device__ __align__(256) __half g_qs[2][4194304];     // qh 2-split (prescaled 1/8)
__device__ __align__(256) __half g_ks[2][4194304];     // kh 2-split
__device__ __align__(256) __half g_vs[4194304];        // vh single fp16
__device__ __align__(256) __half g_cs[4194304];        // ctx single fp16

__constant__ int c_pa[3] = { 0, 0, 1 };
__constant__ int c_pb[3] = { 0, 1, 0 };

// ================= split helpers (fp16 h+l) =================
__device__ __forceinline__ u32 pk2h(__half a, __half b) {
    __half2 t = __halves2half2(a, b);
    return *reinterpret_cast<u32*>(&t);
}
__device__ __forceinline__ void split2h(float x, __half& h, __half& l) {
    h = __float2half_rn(x);
    l = __float2half_rn(x - __half2float(h));
}
__device__ __forceinline__ void split2pkh(float x, float y, u32& hi, u32& lo) {
    __half hx, lx, hy, ly;
    split2h(x, hx, lx); split2h(y, hy, ly);
    hi = pk2h(hx, hy); lo = pk2h(lx, ly);
}

// ================= input split kernels =================
__global__ void split_qkv_kernel(const float* __restrict__ q, const float* __restrict__ k,
                                 const float* __restrict__ v) {
    u32 idx = blockIdx.x * 256u + threadIdx.x;
    int y = blockIdx.y;
    const float* in = (y == 0) ? q : (y == 1) ? k : v;
    float4 x = ((const float4*)in)[idx];
    u32 h01, l01, h23, l23;
    split2pkh(x.x, x.y, h01, l01);
    split2pkh(x.z, x.w, h23, l23);
    u32 o = idx * 4u;
    *(uint2*)&g_as[y][0][o] = make_uint2(h01, h23);
    if (y < 2)   // v projection uses single-fp16 inputs; low split dead
        *(uint2*)&g_as[y][1][o] = make_uint2(l01, l23);
}

// Wq/Wk/Wv [h, d, kk] -> B[n=h*64+kk][k=d] splits
__global__ void split_w3_kernel(const float* __restrict__ Wq, const float* __restrict__ Wk,
                                const float* __restrict__ Wv) {
    u32 idx = blockIdx.x * 256u + threadIdx.x;
    u32 mat = idx >> 18, r = idx & 262143u;
    u32 n = r >> 8, d4 = r & 255u;
    u32 h = n >> 6, kk = n & 63u;
    const float* W = (mat == 0) ? Wq : (mat == 1) ? Wk : Wv;
    float xs[4];
#pragma unroll
    for (int j = 0; j < 4; j++) xs[j] = W[h * 65536u + (d4 * 4u + j) * 64u + kk];
    u32 h01, l01, h23, l23;
    split2pkh(xs[0], xs[1], h01, l01);
    split2pkh(xs[2], xs[3], h23, l23);
    u32 o = n * 1024u + d4 * 4u;
    *(uint2*)&g_bs[mat][0][o] = make_uint2(h01, h23);
    if (mat < 2)
        *(uint2*)&g_bs[mat][1][o] = make_uint2(l01, l23);
}

__global__ void split_wo_kernel(const float* __restrict__ Wo) {
    u32 idx = blockIdx.x * 256u + threadIdx.x;
    float4 x = ((const float4*)Wo)[idx];
    u32 h01, l01, h23, l23;
    split2pkh(x.x, x.y, h01, l01);
    split2pkh(x.z, x.w, h23, l23);
    u32 o = idx * 4u;
    *(uint2*)&g_bs[3][0][o] = make_uint2(h01, h23);
    *(uint2*)&g_bs[3][1][o] = make_uint2(l01, l23);
}

// ================= mma.sync split-fp32 GEMM =================
// mats 0,1: A 2-split x W 2-split, 3 products. mat 2: single x single, 1 product.
// mat 3: A single x Wo 2-split, 2 products.
#define GPITCH 144u
#define GTILE  18432u        // 128 * 144
#define GSTAGE 36864u        // A + B
#define GSMEM  110592u       // 3 stages
#define BSPLIT 2097152ull

__device__ __forceinline__ void gemm_issue(const char* aB, const char* bB, ull asplit,
                                           u32 base, int v, int s, u32 bm, u32 bn, int tid) {
    int p = v >> 4;
    u32 kb = (u32)(v & 15) * 128u;
    const char* srcA = aB + (ull)c_pa[p] * asplit + kb;
    const char* srcB = bB + (ull)c_pb[p] * BSPLIT + kb;
    u32 stA = base + (u32)s * GSTAGE;
    u32 stB = stA + GTILE;
#pragma unroll
    for (int j = 0; j < 4; j++) {
        u32 c = (u32)tid + (u32)j * 256u;
        u32 row = c >> 3, ch = (c & 7u) << 4;
        CP_ASYNC16(stA + row * GPITCH + ch, srcA + (ull)(bm + row) * 2048ull + ch);
        CP_ASYNC16(stB + row * GPITCH + ch, srcB + (ull)(bn + row) * 2048ull + ch);
    }
    CP_COMMIT();
}

__global__ void __launch_bounds__(256) gemm_mma_kernel(int mat_base, float* Cout,
                                                       const float* __restrict__ bias) {
    extern __shared__ char sm_g[];
    u32 base = smem_to_u32(sm_g);
    const int tid = threadIdx.x, lane = tid & 31, wid = tid >> 5;
    const u32 bm = blockIdx.y << 7, bn = blockIdx.x << 7;
    const int wm = (wid >> 2) << 6, wn = (wid & 3) << 5;
    const int mat = mat_base + blockIdx.z;

    const char* aB; const char* bB; ull asplit;
    if (mat < 3) { aB = (const char*)g_as[mat][0]; bB = (const char*)g_bs[mat][0]; asplit = 8388608ull; }
    else         { aB = (const char*)g_cs;         bB = (const char*)g_bs[3][0];   asplit = 0ull; }

    float acc[4][4][4];
#pragma unroll
    for (int mi = 0; mi < 4; mi++)
#pragma unroll
        for (int ni = 0; ni < 4; ni++)
#pragma unroll
            for (int e = 0; e < 4; e++) acc[mi][ni][e] = 0.f;

    const int NV = (mat == 2) ? 16 : (mat == 3) ? 32 : 48;
    gemm_issue(aB, bB, asplit, base, 0, 0, bm, bn, tid);
    gemm_issue(aB, bB, asplit, base, 1, 1, bm, bn, tid);

    int s = 0;
    for (int v = 0; v < NV; v++) {
        if (v == NV - 1) { CP_WAIT0(); } else { CP_WAIT1(); }
        __syncthreads();
        if (v + 2 < NV) {
            int s2 = (s + 2 >= 3) ? s - 1 : s + 2;
            gemm_issue(aB, bB, asplit, base, v + 2, s2, bm, bn, tid);
        }

        u32 stA = base + (u32)s * GSTAGE;
        u32 stB = stA + GTILE;
        u32 lrow = (u32)(lane & 15) * GPITCH + (u32)(lane >> 4) * 16u;
#pragma unroll
        for (int ks = 0; ks < 4; ks++) {
            u32 a[4][4], b[2][4];
            u32 abase = stA + (u32)wm * GPITCH + lrow + (u32)ks * 32u;
            u32 bbase = stB + (u32)wn * GPITCH + lrow + (u32)ks * 32u;
#pragma unroll
            for (int mi = 0; mi < 4; mi++) LDMX4(a[mi], abase + (u32)mi * (16u * GPITCH));
#pragma unroll
            for (int nj = 0; nj < 2; nj++) LDMX4(b[nj], bbase + (u32)nj * (16u * GPITCH));
#pragma unroll
            for (int mi = 0; mi < 4; mi++)
#pragma unroll
                for (int ni = 0; ni < 4; ni++)
                    mma16816(acc[mi][ni], a[mi], b[ni >> 1][ni & 1], b[ni >> 1][(ni & 1) + 2]);
        }
        s = (s + 1 == 3) ? 0 : s + 1;
    }

    const float pre = (mat == 0) ? 0.125f : 1.0f;
#pragma unroll
    for (int mi = 0; mi < 4; mi++)
#pragma unroll
        for (int ni = 0; ni < 4; ni++) {
            u32 r0 = bm + (u32)wm + (u32)mi * 16u + (u32)(lane >> 2);
            u32 col = bn + (u32)wn + (u32)ni * 8u + (u32)((lane & 3) << 1);
            float v0 = acc[mi][ni][0] * pre, v1 = acc[mi][ni][1] * pre;
            float v2 = acc[mi][ni][2] * pre, v3 = acc[mi][ni][3] * pre;
            if (mat == 3) {
                float b0 = bias[col], b1 = bias[col + 1];
                *(float2*)&Cout[(ull)r0 * 1024ull + col] = make_float2(v0 + b0, v1 + b1);
                *(float2*)&Cout[(ull)(r0 + 8) * 1024ull + col] = make_float2(v2 + b0, v3 + b1);
            } else if (mat == 2) {
                *(u32*)&g_vs[r0 * 1024u + col] =
                    pk2h(__float2half_rn(v0), __float2half_rn(v1));
                *(u32*)&g_vs[(r0 + 8) * 1024u + col] =
                    pk2h(__float2half_rn(v2), __float2half_rn(v3));
            } else {
                __half* d0 = (mat == 0) ? g_qs[0] : g_ks[0];
                __half* d1 = (mat == 0) ? g_qs[1] : g_ks[1];
                u32 h01, l01, h23, l23;
                split2pkh(v0, v1, h01, l01); split2pkh(v2, v3, h23, l23);
                *(u32*)&d0[r0 * 1024u + col] = h01;
                *(u32*)&d1[r0 * 1024u + col] = l01;
                *(u32*)&d0[(r0 + 8) * 1024u + col] = h23;
                *(u32*)&d1[(r0 + 8) * 1024u + col] = l23;
            }
        }
}

// ================= mma.sync flash attention =================
// QK^T: 3 products (hh, hl, lh); PV: 1 product (P fp16 unsplit, V single fp16).
#define AP   144u
#define QSZ  18432u     // 128*144 per split
#define KSZ  9216u      // 64*144 per split
#define ASTAGE 27648u   // 2 K splits + 1 V
#define ASMEM  92160u   // 2*QSZ + 2*ASTAGE

__device__ __forceinline__ void attn_issue(u32 base, int s, int key0, u32 hb, int tid) {
    u32 st = base + 2u * QSZ + (u32)s * ASTAGE;
#pragma unroll
    for (int i = 0; i < 6; i++) {
        u32 u = (u32)tid + (u32)i * 256u;
        if (u < 1024u) {
            u32 sp = u >> 9, r = (u >> 3) & 63u, ch = (u & 7u) << 4;
            const char* src = (const char*)g_ks[sp] + (ull)(key0 + (int)r) * 2048ull + hb + ch;
            CP_ASYNC16(st + sp * KSZ + r * AP + ch, src);
        } else {
            u32 u2 = u - 1024u;
            u32 r = u2 >> 3, ch = (u2 & 7u) << 4;
            const char* src = (const char*)g_vs + (ull)(key0 + (int)r) * 2048ull + hb + ch;
            CP_ASYNC16(st + 2u * KSZ + r * AP + ch, src);
        }
    }
    CP_COMMIT();
}

__global__ void __launch_bounds__(256, 2) attn_mma_kernel() {
    extern __shared__ char sma[];
    u32 base = smem_to_u32(sma);
    const int tid = threadIdx.x, lane = tid & 31, w = tid >> 5;
    const int b = blockIdx.y >> 4, h = blockIdx.y & 15;
    const u32 hb = (u32)h * 128u;
    const int m0 = b * 2048 + (blockIdx.x << 7);
    const int kv0 = b * 2048;

    // Q tile: 2 splits x 128 rows x 8 chunks (own commit group)
#pragma unroll
    for (int i = 0; i < 8; i++) {
        u32 u = (u32)tid + (u32)i * 256u;
        u32 sp = u >> 10, r = (u >> 3) & 127u, ch = (u & 7u) << 4;
        const char* src = (const char*)g_qs[sp] + (ull)(m0 + (int)r) * 2048ull + hb + ch;
        CP_ASYNC16(base + sp * QSZ + r * AP + ch, src);
    }
    CP_COMMIT();
    attn_issue(base, 0, kv0, hb, tid);

    float o[8][4];
#pragma unroll
    for (int i = 0; i < 8; i++)
#pragma unroll
        for (int e = 0; e < 4; e++) o[i][e] = 0.f;
    float mg0 = -1e30f, mg1 = -1e30f, l0 = 0.f, l1 = 0.f;

    const u32 lrow = (u32)(lane & 15) * AP + (u32)(lane >> 4) * 16u;
    const u32 qbase = base + (u32)w * (16u * AP) + lrow;

    for (int c = 0; c < 32; c++) {
        if (c + 1 < 32) { attn_issue(base, (c + 1) & 1, kv0 + (c + 1) * 64, hb, tid); CP_WAIT1(); }
        else            { CP_WAIT0(); }
        __syncthreads();

        u32 stK = base + 2u * QSZ + (u32)(c & 1) * ASTAGE;
        u32 stV = stK + 2u * KSZ;

        // ---- S = QK^T (3 products: hh, hl, lh) ----
        float sv[8][4];
#pragma unroll
        for (int i = 0; i < 8; i++)
#pragma unroll
            for (int e = 0; e < 4; e++) sv[i][e] = 0.f;

#pragma unroll
        for (int ks = 0; ks < 4; ks++) {
            u32 aq[2][4];
#pragma unroll
            for (int sp = 0; sp < 2; sp++) LDMX4(aq[sp], qbase + sp * QSZ + (u32)ks * 32u);
#pragma unroll
            for (int sb = 0; sb < 2; sb++) {
                u32 bf[4][4];
                u32 bb = stK + (u32)sb * KSZ + lrow + (u32)ks * 32u;
#pragma unroll
                for (int q = 0; q < 4; q++) LDMX4(bf[q], bb + (u32)q * (16u * AP));
                const int na = (sb == 0) ? 2 : 1;   // hh, lh | hl
#pragma unroll
                for (int ai = 0; ai < 2; ai++) {
                    if (ai < na) {
#pragma unroll
                        for (int q = 0; q < 4; q++) {
                            mma16816(sv[2 * q],     aq[ai], bf[q][0], bf[q][2]);
                            mma16816(sv[2 * q + 1], aq[ai], bf[q][1], bf[q][3]);
                        }
                    }
                }
            }
        }

        // ---- online softmax ----
        float cm0 = -1e30f, cm1 = -1e30f;
#pragma unroll
        for (int i = 0; i < 8; i++) {
            cm0 = fmaxf(cm0, fmaxf(sv[i][0], sv[i][1]));
            cm1 = fmaxf(cm1, fmaxf(sv[i][2], sv[i][3]));
        }
        cm0 = fmaxf(cm0, __shfl_xor_sync(0xffffffffu, cm0, 1));
        cm0 = fmaxf(cm0, __shfl_xor_sync(0xffffffffu, cm0, 2));
        cm1 = fmaxf(cm1, __shfl_xor_sync(0xffffffffu, cm1, 1));
        cm1 = fmaxf(cm1, __shfl_xor_sync(0xffffffffu, cm1, 2));
        float nm0 = fmaxf(mg0, cm0), nm1 = fmaxf(mg1, cm1);
        float corr0 = __expf(mg0 - nm0), corr1 = __expf(mg1 - nm1);
        float rs0 = 0.f, rs1 = 0.f;
#pragma unroll
        for (int i = 0; i < 8; i++) {
            sv[i][0] = __expf(sv[i][0] - nm0);
            sv[i][1] = __expf(sv[i][1] - nm0);
            sv[i][2] = __expf(sv[i][2] - nm1);
            sv[i][3] = __expf(sv[i][3] - nm1);
            rs0 += sv[i][0] + sv[i][1];
            rs1 += sv[i][2] + sv[i][3];
        }
        rs0 += __shfl_xor_sync(0xffffffffu, rs0, 1);
        rs0 += __shfl_xor_sync(0xffffffffu, rs0, 2);
        rs1 += __shfl_xor_sync(0xffffffffu, rs1, 1);
        rs1 += __shfl_xor_sync(0xffffffffu, rs1, 2);
        l0 = l0 * corr0 + rs0; l1 = l1 * corr1 + rs1;
        mg0 = nm0; mg1 = nm1;
#pragma unroll
        for (int i = 0; i < 8; i++) {
            o[i][0] *= corr0; o[i][1] *= corr0;
            o[i][2] *= corr1; o[i][3] *= corr1;
        }

        // ---- P -> fp16 A-fragments (unsplit) ----
        u32 ph[4][4];
#pragma unroll
        for (int j = 0; j < 4; j++) {
            ph[j][0] = pk2h(__float2half_rn(sv[2 * j][0]),     __float2half_rn(sv[2 * j][1]));
            ph[j][1] = pk2h(__float2half_rn(sv[2 * j][2]),     __float2half_rn(sv[2 * j][3]));
            ph[j][2] = pk2h(__float2half_rn(sv[2 * j + 1][0]), __float2half_rn(sv[2 * j + 1][1]));
            ph[j][3] = pk2h(__float2half_rn(sv[2 * j + 1][2]), __float2half_rn(sv[2 * j + 1][3]));
        }

        // ---- O += P V (1 product; V single fp16 via ldmatrix.trans) ----
#pragma unroll
        for (int j = 0; j < 4; j++) {
            u32 vrow = stV + (16u * (u32)j + (u32)(lane & 7) + (u32)((lane >> 4) << 3)) * AP
                       + (u32)(((lane >> 3) & 1) << 4);
            u32 bv[4][4];
#pragma unroll
            for (int q = 0; q < 4; q++) LDMX4T(bv[q], vrow + (u32)q * 32u);
#pragma unroll
            for (int q = 0; q < 4; q++) {
                mma16816(o[2 * q],     ph[j], bv[q][0], bv[q][2]);
                mma16816(o[2 * q + 1], ph[j], bv[q][1], bv[q][3]);
            }
        }
        __syncthreads();
    }

    // ---- epilogue: normalize, write ctx single fp16 ----
    float inv0 = 1.0f / l0, inv1 = 1.0f / l1;
    u32 r0 = (u32)m0 + (u32)w * 16u + (u32)(lane >> 2);
    u32 cb = (u32)h * 64u + (u32)((lane & 3) << 1);
#pragma unroll
    for (int i = 0; i < 8; i++) {
        u32 col = cb + (u32)i * 8u;
        *(u32*)&g_cs[r0 * 1024u + col] =
            pk2h(__float2half_rn(o[i][0] * inv0), __float2half_rn(o[i][1] * inv0));
        *(u32*)&g_cs[(r0 + 8u) * 1024u + col] =
            pk2h(__float2half_rn(o[i][2] * inv1), __float2half_rn(o[i][3] * inv1));
    }
}

// ================= launch =================
extern "C" void kernel_launch(void* const* d_in, const int* in_sizes, int n_in,
                              void* d_out, int out_size) {
    const float* q  = (const float*)d_in[0];
    const float* k  = (const float*)d_in[1];
    const float* v  = (const float*)d_in[2];
    const float* Wq = (const float*)d_in[3];
    const float* Wk = (const float*)d_in[4];
    const float* Wv = (const float*)d_in[5];
    const float* Wo = (const float*)d_in[6];
    const float* bo = (const float*)d_in[7];
    float* out = (float*)d_out;

    split_qkv_kernel<<<dim3(4096, 3), 256>>>(q, k, v);
    split_w3_kernel<<<3072, 256>>>(Wq, Wk, Wv);
    split_wo_kernel<<<1024, 256>>>(Wo);

    cudaFuncSetAttribute(gemm_mma_kernel, cudaFuncAttributeMaxDynamicSharedMemorySize, GSMEM);
    gemm_mma_kernel<<<dim3(8, 32, 3), 256, GSMEM>>>(0, nullptr, nullptr);

    cudaFuncSetAttribute(attn_mma_kernel, cudaFuncAttributeMaxDynamicSharedMemorySize, ASMEM);
    attn_mma_kernel<<<dim3(16, 32), 256, ASMEM>>>();

    gemm_mma_kernel<<<dim3(8, 32, 1), 256, GSMEM>>>(3, out, bo);
}

// round 12
// speedup vs baseline: 3.3300x; 1.0069x over previous
#include <cuda_runtime.h>
#include <cuda_fp16.h>

typedef unsigned long long ull;
typedef unsigned int u32;

// ================= common helpers =================
__device__ __forceinline__ u32 smem_to_u32(const void* p) {
    u32 a; asm("{ .reg .u64 t; cvta.to.shared.u64 t, %1; cvt.u32.u64 %0, t; }" : "=r"(a) : "l"(p));
    return a;
}
#define CP_ASYNC16(dst, src) asm volatile("cp.async.cg.shared.global [%0], [%1], 16;" :: "r"(dst), "l"(src) : "memory")
#define CP_COMMIT()          asm volatile("cp.async.commit_group;" ::: "memory")
#define CP_WAIT0()           asm volatile("cp.async.wait_group 0;" ::: "memory")
#define CP_WAIT1()           asm volatile("cp.async.wait_group 1;" ::: "memory")

#define LDMX4(r, addr) \
    asm volatile("ldmatrix.sync.aligned.m8n8.x4.shared.b16 {%0,%1,%2,%3}, [%4];" \
        : "=r"((r)[0]), "=r"((r)[1]), "=r"((r)[2]), "=r"((r)[3]) : "r"(addr))
#define LDMX4T(r, addr) \
    asm volatile("ldmatrix.sync.aligned.m8n8.x4.trans.shared.b16 {%0,%1,%2,%3}, [%4];" \
        : "=r"((r)[0]), "=r"((r)[1]), "=r"((r)[2]), "=r"((r)[3]) : "r"(addr))

__device__ __forceinline__ void mma16816(float* c, const u32* a, u32 b0, u32 b1) {
    asm volatile("mma.sync.aligned.m16n8k16.row.col.f32.f16.f16.f32 "
        "{%0,%1,%2,%3}, {%4,%5,%6,%7}, {%8,%9}, {%0,%1,%2,%3};"
        : "+f"(c[0]), "+f"(c[1]), "+f"(c[2]), "+f"(c[3])
        : "r"(a[0]), "r"(a[1]), "r"(a[2]), "r"(a[3]), "r"(b0), "r"(b1));
}

// ================= global scratch =================
__device__ __align__(256) __half g_as[3][2][4194304];  // input splits [mat][split][m*1024+k]
__device__ __align__(256) __half g_bs[4][2][1048576];  // weight splits [mat][split][n*1024+k]
__device__ __align__(256) __half g_qs[2][4194304];     // qh 2-split (prescaled 1/8)
__device__ __align__(256) __half g_ks[2][4194304];     // kh 2-split
__device__ __align__(256) __half g_vs[4194304];        // vh single fp16
__device__ __align__(256) __half g_cs[4194304];        // ctx single fp16

__constant__ int c_pa[3] = { 0, 0, 1 };
__constant__ int c_pb[3] = { 0, 1, 0 };

// ================= split helpers (fp16 h+l) =================
__device__ __forceinline__ u32 pk2h(__half a, __half b) {
    __half2 t = __halves2half2(a, b);
    return *reinterpret_cast<u32*>(&t);
}
__device__ __forceinline__ void split2h(float x, __half& h, __half& l) {
    h = __float2half_rn(x);
    l = __float2half_rn(x - __half2float(h));
}
__device__ __forceinline__ void split2pkh(float x, float y, u32& hi, u32& lo) {
    __half hx, lx, hy, ly;
    split2h(x, hx, lx); split2h(y, hy, ly);
    hi = pk2h(hx, hy); lo = pk2h(lx, ly);
}

// ================= merged input split kernel =================
// blocks [0,12288): q/k/v inputs; [12288,15360): Wq/Wk/Wv; [15360,16384): Wo
__global__ void split_all_kernel(const float* __restrict__ q, const float* __restrict__ k,
                                 const float* __restrict__ v,
                                 const float* __restrict__ Wq, const float* __restrict__ Wk,
                                 const float* __restrict__ Wv, const float* __restrict__ Wo) {
    u32 bid = blockIdx.x;
    if (bid < 12288u) {
        int y = bid / 4096u;
        u32 idx = (bid % 4096u) * 256u + threadIdx.x;
        const float* in = (y == 0) ? q : (y == 1) ? k : v;
        float4 x = ((const float4*)in)[idx];
        u32 h01, l01, h23, l23;
        split2pkh(x.x, x.y, h01, l01);
        split2pkh(x.z, x.w, h23, l23);
        u32 o = idx * 4u;
        *(uint2*)&g_as[y][0][o] = make_uint2(h01, h23);
        if (y < 2)
            *(uint2*)&g_as[y][1][o] = make_uint2(l01, l23);
    } else if (bid < 15360u) {
        u32 idx = (bid - 12288u) * 256u + threadIdx.x;
        u32 mat = idx >> 18, r = idx & 262143u;
        u32 n = r >> 8, d4 = r & 255u;
        u32 h = n >> 6, kk = n & 63u;
        const float* W = (mat == 0) ? Wq : (mat == 1) ? Wk : Wv;
        float xs[4];
#pragma unroll
        for (int j = 0; j < 4; j++) xs[j] = W[h * 65536u + (d4 * 4u + j) * 64u + kk];
        u32 h01, l01, h23, l23;
        split2pkh(xs[0], xs[1], h01, l01);
        split2pkh(xs[2], xs[3], h23, l23);
        u32 o = n * 1024u + d4 * 4u;
        *(uint2*)&g_bs[mat][0][o] = make_uint2(h01, h23);
        if (mat < 2)
            *(uint2*)&g_bs[mat][1][o] = make_uint2(l01, l23);
    } else {
        u32 idx = (bid - 15360u) * 256u + threadIdx.x;
        float4 x = ((const float4*)Wo)[idx];
        u32 h01, l01, h23, l23;
        split2pkh(x.x, x.y, h01, l01);
        split2pkh(x.z, x.w, h23, l23);
        u32 o = idx * 4u;
        *(uint2*)&g_bs[3][0][o] = make_uint2(h01, h23);
        *(uint2*)&g_bs[3][1][o] = make_uint2(l01, l23);
    }
}

// ================= mma.sync split-fp32 GEMM (4 warps, 64x64 warp tile) ========
// mats 0,1: A 2-split x W 2-split, 3 products. mat 2: single x single, 1 product.
// mat 3: A single x Wo 2-split, 2 products.
#define GPITCH 144u
#define GTILE  18432u        // 128 * 144
#define GSTAGE 36864u        // A + B
#define GSMEM  110592u       // 3 stages
#define BSPLIT 2097152ull

__device__ __forceinline__ void gemm_issue(const char* aB, const char* bB, ull asplit,
                                           u32 base, int v, int s, u32 bm, u32 bn, int tid) {
    int p = v >> 4;
    u32 kb = (u32)(v & 15) * 128u;
    const char* srcA = aB + (ull)c_pa[p] * asplit + kb;
    const char* srcB = bB + (ull)c_pb[p] * BSPLIT + kb;
    u32 stA = base + (u32)s * GSTAGE;
    u32 stB = stA + GTILE;
#pragma unroll
    for (int j = 0; j < 8; j++) {
        u32 c = (u32)tid + (u32)j * 128u;
        u32 row = c >> 3, ch = (c & 7u) << 4;
        CP_ASYNC16(stA + row * GPITCH + ch, srcA + (ull)(bm + row) * 2048ull + ch);
        CP_ASYNC16(stB + row * GPITCH + ch, srcB + (ull)(bn + row) * 2048ull + ch);
    }
    CP_COMMIT();
}

__global__ void __launch_bounds__(128, 2) gemm_mma_kernel(int mat_base, float* Cout,
                                                          const float* __restrict__ bias) {
    extern __shared__ char sm_g[];
    u32 base = smem_to_u32(sm_g);
    const int tid = threadIdx.x, lane = tid & 31, wid = tid >> 5;
    const u32 bm = blockIdx.y << 7, bn = blockIdx.x << 7;
    const int wm = (wid >> 1) << 6, wn = (wid & 1) << 6;   // 2x2 warps, 64x64 tiles
    const int mat = mat_base + blockIdx.z;

    const char* aB; const char* bB; ull asplit;
    if (mat < 3) { aB = (const char*)g_as[mat][0]; bB = (const char*)g_bs[mat][0]; asplit = 8388608ull; }
    else         { aB = (const char*)g_cs;         bB = (const char*)g_bs[3][0];   asplit = 0ull; }

    float acc[4][8][4];
#pragma unroll
    for (int mi = 0; mi < 4; mi++)
#pragma unroll
        for (int ni = 0; ni < 8; ni++)
#pragma unroll
            for (int e = 0; e < 4; e++) acc[mi][ni][e] = 0.f;

    const int NV = (mat == 2) ? 16 : (mat == 3) ? 32 : 48;
    gemm_issue(aB, bB, asplit, base, 0, 0, bm, bn, tid);
    gemm_issue(aB, bB, asplit, base, 1, 1, bm, bn, tid);

    int s = 0;
    for (int v = 0; v < NV; v++) {
        if (v == NV - 1) { CP_WAIT0(); } else { CP_WAIT1(); }
        __syncthreads();
        if (v + 2 < NV) {
            int s2 = (s + 2 >= 3) ? s - 1 : s + 2;
            gemm_issue(aB, bB, asplit, base, v + 2, s2, bm, bn, tid);
        }

        u32 stA = base + (u32)s * GSTAGE;
        u32 stB = stA + GTILE;
        u32 lrow = (u32)(lane & 15) * GPITCH + (u32)(lane >> 4) * 16u;
#pragma unroll
        for (int ks = 0; ks < 4; ks++) {
            u32 a[4][4], b[4][4];
            u32 abase = stA + (u32)wm * GPITCH + lrow + (u32)ks * 32u;
            u32 bbase = stB + (u32)wn * GPITCH + lrow + (u32)ks * 32u;
#pragma unroll
            for (int mi = 0; mi < 4; mi++) LDMX4(a[mi], abase + (u32)mi * (16u * GPITCH));
#pragma unroll
            for (int nj = 0; nj < 4; nj++) LDMX4(b[nj], bbase + (u32)nj * (16u * GPITCH));
#pragma unroll
            for (int mi = 0; mi < 4; mi++)
#pragma unroll
                for (int ni = 0; ni < 8; ni++)
                    mma16816(acc[mi][ni], a[mi], b[ni >> 1][ni & 1], b[ni >> 1][(ni & 1) + 2]);
        }
        s = (s + 1 == 3) ? 0 : s + 1;
    }

    const float pre = (mat == 0) ? 0.125f : 1.0f;
#pragma unroll
    for (int mi = 0; mi < 4; mi++)
#pragma unroll
        for (int ni = 0; ni < 8; ni++) {
            u32 r0 = bm + (u32)wm + (u32)mi * 16u + (u32)(lane >> 2);
            u32 col = bn + (u32)wn + (u32)ni * 8u + (u32)((lane & 3) << 1);
            float v0 = acc[mi][ni][0] * pre, v1 = acc[mi][ni][1] * pre;
            float v2 = acc[mi][ni][2] * pre, v3 = acc[mi][ni][3] * pre;
            if (mat == 3) {
                float b0 = bias[col], b1 = bias[col + 1];
                *(float2*)&Cout[(ull)r0 * 1024ull + col] = make_float2(v0 + b0, v1 + b1);
                *(float2*)&Cout[(ull)(r0 + 8) * 1024ull + col] = make_float2(v2 + b0, v3 + b1);
            } else if (mat == 2) {
                *(u32*)&g_vs[r0 * 1024u + col] =
                    pk2h(__float2half_rn(v0), __float2half_rn(v1));
                *(u32*)&g_vs[(r0 + 8) * 1024u + col] =
                    pk2h(__float2half_rn(v2), __float2half_rn(v3));
            } else {
                __half* d0 = (mat == 0) ? g_qs[0] : g_ks[0];
                __half* d1 = (mat == 0) ? g_qs[1] : g_ks[1];
                u32 h01, l01, h23, l23;
                split2pkh(v0, v1, h01, l01); split2pkh(v2, v3, h23, l23);
                *(u32*)&d0[r0 * 1024u + col] = h01;
                *(u32*)&d1[r0 * 1024u + col] = l01;
                *(u32*)&d0[(r0 + 8) * 1024u + col] = h23;
                *(u32*)&d1[(r0 + 8) * 1024u + col] = l23;
            }
        }
}

// ================= mma.sync flash attention =================
// QK^T: 3 products (hh, hl, lh); PV: 1 product (P fp16 unsplit, V single fp16).
#define AP   144u
#define QSZ  18432u     // 128*144 per split
#define KSZ  9216u      // 64*144 per split
#define ASTAGE 27648u   // 2 K splits + 1 V
#define ASMEM  92160u   // 2*QSZ + 2*ASTAGE

__device__ __forceinline__ void attn_issue(u32 base, int s, int key0, u32 hb, int tid) {
    u32 st = base + 2u * QSZ + (u32)s * ASTAGE;
#pragma unroll
    for (int i = 0; i < 6; i++) {
        u32 u = (u32)tid + (u32)i * 256u;
        if (u < 1024u) {
            u32 sp = u >> 9, r = (u >> 3) & 63u, ch = (u & 7u) << 4;
            const char* src = (const char*)g_ks[sp] + (ull)(key0 + (int)r) * 2048ull + hb + ch;
            CP_ASYNC16(st + sp * KSZ + r * AP + ch, src);
        } else {
            u32 u2 = u - 1024u;
            u32 r = u2 >> 3, ch = (u2 & 7u) << 4;
            const char* src = (const char*)g_vs + (ull)(key0 + (int)r) * 2048ull + hb + ch;
            CP_ASYNC16(st + 2u * KSZ + r * AP + ch, src);
        }
    }
    CP_COMMIT();
}

__global__ void __launch_bounds__(256, 2) attn_mma_kernel() {
    extern __shared__ char sma[];
    u32 base = smem_to_u32(sma);
    const int tid = threadIdx.x, lane = tid & 31, w = tid >> 5;
    const int b = blockIdx.y >> 4, h = blockIdx.y & 15;
    const u32 hb = (u32)h * 128u;
    const int m0 = b * 2048 + (blockIdx.x << 7);
    const int kv0 = b * 2048;

    // Q tile: 2 splits x 128 rows x 8 chunks (own commit group)
#pragma unroll
    for (int i = 0; i < 8; i++) {
        u32 u = (u32)tid + (u32)i * 256u;
        u32 sp = u >> 10, r = (u >> 3) & 127u, ch = (u & 7u) << 4;
        const char* src = (const char*)g_qs[sp] + (ull)(m0 + (int)r) * 2048ull + hb + ch;
        CP_ASYNC16(base + sp * QSZ + r * AP + ch, src);
    }
    CP_COMMIT();
    attn_issue(base, 0, kv0, hb, tid);

    float o[8][4];
#pragma unroll
    for (int i = 0; i < 8; i++)
#pragma unroll
        for (int e = 0; e < 4; e++) o[i][e] = 0.f;
    float mg0 = -1e30f, mg1 = -1e30f, l0 = 0.f, l1 = 0.f;

    const u32 lrow = (u32)(lane & 15) * AP + (u32)(lane >> 4) * 16u;
    const u32 qbase = base + (u32)w * (16u * AP) + lrow;

    for (int c = 0; c < 32; c++) {
        if (c + 1 < 32) { attn_issue(base, (c + 1) & 1, kv0 + (c + 1) * 64, hb, tid); CP_WAIT1(); }
        else            { CP_WAIT0(); }
        __syncthreads();

        u32 stK = base + 2u * QSZ + (u32)(c & 1) * ASTAGE;
        u32 stV = stK + 2u * KSZ;

        // ---- S = QK^T (3 products: hh, hl, lh) ----
        float sv[8][4];
#pragma unroll
        for (int i = 0; i < 8; i++)
#pragma unroll
            for (int e = 0; e < 4; e++) sv[i][e] = 0.f;

#pragma unroll
        for (int ks = 0; ks < 4; ks++) {
            u32 aq[2][4];
#pragma unroll
            for (int sp = 0; sp < 2; sp++) LDMX4(aq[sp], qbase + sp * QSZ + (u32)ks * 32u);
#pragma unroll
            for (int sb = 0; sb < 2; sb++) {
                u32 bf[4][4];
                u32 bb = stK + (u32)sb * KSZ + lrow + (u32)ks * 32u;
#pragma unroll
                for (int q = 0; q < 4; q++) LDMX4(bf[q], bb + (u32)q * (16u * AP));
                const int na = (sb == 0) ? 2 : 1;   // hh, lh | hl
#pragma unroll
                for (int ai = 0; ai < 2; ai++) {
                    if (ai < na) {
#pragma unroll
                        for (int q = 0; q < 4; q++) {
                            mma16816(sv[2 * q],     aq[ai], bf[q][0], bf[q][2]);
                            mma16816(sv[2 * q + 1], aq[ai], bf[q][1], bf[q][3]);
                        }
                    }
                }
            }
        }

        // ---- online softmax ----
        float cm0 = -1e30f, cm1 = -1e30f;
#pragma unroll
        for (int i = 0; i < 8; i++) {
            cm0 = fmaxf(cm0, fmaxf(sv[i][0], sv[i][1]));
            cm1 = fmaxf(cm1, fmaxf(sv[i][2], sv[i][3]));
        }
        cm0 = fmaxf(cm0, __shfl_xor_sync(0xffffffffu, cm0, 1));
        cm0 = fmaxf(cm0, __shfl_xor_sync(0xffffffffu, cm0, 2));
        cm1 = fmaxf(cm1, __shfl_xor_sync(0xffffffffu, cm1, 1));
        cm1 = fmaxf(cm1, __shfl_xor_sync(0xffffffffu, cm1, 2));
        float nm0 = fmaxf(mg0, cm0), nm1 = fmaxf(mg1, cm1);
        float corr0 = __expf(mg0 - nm0), corr1 = __expf(mg1 - nm1);
        float rs0 = 0.f, rs1 = 0.f;
#pragma unroll
        for (int i = 0; i < 8; i++) {
            sv[i][0] = __expf(sv[i][0] - nm0);
            sv[i][1] = __expf(sv[i][1] - nm0);
            sv[i][2] = __expf(sv[i][2] - nm1);
            sv[i][3] = __expf(sv[i][3] - nm1);
            rs0 += sv[i][0] + sv[i][1];
            rs1 += sv[i][2] + sv[i][3];
        }
        rs0 += __shfl_xor_sync(0xffffffffu, rs0, 1);
        rs0 += __shfl_xor_sync(0xffffffffu, rs0, 2);
        rs1 += __shfl_xor_sync(0xffffffffu, rs1, 1);
        rs1 += __shfl_xor_sync(0xffffffffu, rs1, 2);
        l0 = l0 * corr0 + rs0; l1 = l1 * corr1 + rs1;
        mg0 = nm0; mg1 = nm1;
#pragma unroll
        for (int i = 0; i < 8; i++) {
            o[i][0] *= corr0; o[i][1] *= corr0;
            o[i][2] *= corr1; o[i][3] *= corr1;
        }

        // ---- P -> fp16 A-fragments (unsplit) ----
        u32 ph[4][4];
#pragma unroll
        for (int j = 0; j < 4; j++) {
            ph[j][0] = pk2h(__float2half_rn(sv[2 * j][0]),     __float2half_rn(sv[2 * j][1]));
            ph[j][1] = pk2h(__float2half_rn(sv[2 * j][2]),     __float2half_rn(sv[2 * j][3]));
            ph[j][2] = pk2h(__float2half_rn(sv[2 * j + 1][0]), __float2half_rn(sv[2 * j + 1][1]));
            ph[j][3] = pk2h(__float2half_rn(sv[2 * j + 1][2]), __float2half_rn(sv[2 * j + 1][3]));
        }

        // ---- O += P V (1 product; V single fp16 via ldmatrix.trans) ----
#pragma unroll
        for (int j = 0; j < 4; j++) {
            u32 vrow = stV + (16u * (u32)j + (u32)(lane & 7) + (u32)((lane >> 4) << 3)) * AP
                       + (u32)(((lane >> 3) & 1) << 4);
            u32 bv[4][4];
#pragma unroll
            for (int q = 0; q < 4; q++) LDMX4T(bv[q], vrow + (u32)q * 32u);
#pragma unroll
            for (int q = 0; q < 4; q++) {
                mma16816(o[2 * q],     ph[j], bv[q][0], bv[q][2]);
                mma16816(o[2 * q + 1], ph[j], bv[q][1], bv[q][3]);
            }
        }
        __syncthreads();
    }

    // ---- epilogue: normalize, write ctx single fp16 ----
    float inv0 = 1.0f / l0, inv1 = 1.0f / l1;
    u32 r0 = (u32)m0 + (u32)w * 16u + (u32)(lane >> 2);
    u32 cb = (u32)h * 64u + (u32)((lane & 3) << 1);
#pragma unroll
    for (int i = 0; i < 8; i++) {
        u32 col = cb + (u32)i * 8u;
        *(u32*)&g_cs[r0 * 1024u + col] =
            pk2h(__float2half_rn(o[i][0] * inv0), __float2half_rn(o[i][1] * inv0));
        *(u32*)&g_cs[(r0 + 8u) * 1024u + col] =
            pk2h(__float2half_rn(o[i][2] * inv1), __float2half_rn(o[i][3] * inv1));
    }
}

// ================= launch =================
extern "C" void kernel_launch(void* const* d_in, const int* in_sizes, int n_in,
                              void* d_out, int out_size) {
    const float* q  = (const float*)d_in[0];
    const float* k  = (const float*)d_in[1];
    const float* v  = (const float*)d_in[2];
    const float* Wq = (const float*)d_in[3];
    const float* Wk = (const float*)d_in[4];
    const float* Wv = (const float*)d_in[5];
    const float* Wo = (const float*)d_in[6];
    const float* bo = (const float*)d_in[7];
    float* out = (float*)d_out;

    split_all_kernel<<<16384, 256>>>(q, k, v, Wq, Wk, Wv, Wo);

    cudaFuncSetAttribute(gemm_mma_kernel, cudaFuncAttributeMaxDynamicSharedMemorySize, GSMEM);
    gemm_mma_kernel<<<dim3(8, 32, 3), 128, GSMEM>>>(0, nullptr, nullptr);

    cudaFuncSetAttribute(attn_mma_kernel, cudaFuncAttributeMaxDynamicSharedMemorySize, ASMEM);
    attn_mma_kernel<<<dim3(16, 32), 256, ASMEM>>>();

    gemm_mma_kernel<<<dim3(8, 32, 1), 128, GSMEM>>>(3, out, bo);
}

// round 13
// speedup vs baseline: 3.5574x; 1.0683x over previous
#include <cuda_runtime.h>
#include <cuda_fp16.h>

typedef unsigned long long ull;
typedef unsigned int u32;

// ================= common helpers =================
__device__ __forceinline__ u32 smem_to_u32(const void* p) {
    u32 a; asm("{ .reg .u64 t; cvta.to.shared.u64 t, %1; cvt.u32.u64 %0, t; }" : "=r"(a) : "l"(p));
    return a;
}
#define CP_ASYNC16(dst, src) asm volatile("cp.async.cg.shared.global [%0], [%1], 16;" :: "r"(dst), "l"(src) : "memory")
#define CP_COMMIT()          asm volatile("cp.async.commit_group;" ::: "memory")
#define CP_WAIT0()           asm volatile("cp.async.wait_group 0;" ::: "memory")
#define CP_WAIT1()           asm volatile("cp.async.wait_group 1;" ::: "memory")

#define LDMX4(r, addr) \
    asm volatile("ldmatrix.sync.aligned.m8n8.x4.shared.b16 {%0,%1,%2,%3}, [%4];" \
        : "=r"((r)[0]), "=r"((r)[1]), "=r"((r)[2]), "=r"((r)[3]) : "r"(addr))
#define LDMX4T(r, addr) \
    asm volatile("ldmatrix.sync.aligned.m8n8.x4.trans.shared.b16 {%0,%1,%2,%3}, [%4];" \
        : "=r"((r)[0]), "=r"((r)[1]), "=r"((r)[2]), "=r"((r)[3]) : "r"(addr))

__device__ __forceinline__ void mma16816(float* c, const u32* a, u32 b0, u32 b1) {
    asm volatile("mma.sync.aligned.m16n8k16.row.col.f32.f16.f16.f32 "
        "{%0,%1,%2,%3}, {%4,%5,%6,%7}, {%8,%9}, {%0,%1,%2,%3};"
        : "+f"(c[0]), "+f"(c[1]), "+f"(c[2]), "+f"(c[3])
        : "r"(a[0]), "r"(a[1]), "r"(a[2]), "r"(a[3]), "r"(b0), "r"(b1));
}

// ================= global scratch =================
__device__ __align__(256) __half g_as[3][2][4194304];  // input splits [mat][split][m*1024+k]
__device__ __align__(256) __half g_bs[4][2][1048576];  // weight splits [mat][split][n*1024+k]
__device__ __align__(256) __half g_qs[2][4194304];     // qh 2-split (prescaled 1/8)
__device__ __align__(256) __half g_ks[2][4194304];     // kh 2-split
__device__ __align__(256) __half g_vs[4194304];        // vh single fp16
__device__ __align__(256) __half g_cs[4194304];        // ctx single fp16

__constant__ int c_pa[3] = { 0, 0, 1 };
__constant__ int c_pb[3] = { 0, 1, 0 };

// ================= split helpers (fp16 h+l) =================
__device__ __forceinline__ u32 pk2h(__half a, __half b) {
    __half2 t = __halves2half2(a, b);
    return *reinterpret_cast<u32*>(&t);
}
__device__ __forceinline__ void split2h(float x, __half& h, __half& l) {
    h = __float2half_rn(x);
    l = __float2half_rn(x - __half2float(h));
}
__device__ __forceinline__ void split2pkh(float x, float y, u32& hi, u32& lo) {
    __half hx, lx, hy, ly;
    split2h(x, hx, lx); split2h(y, hy, ly);
    hi = pk2h(hx, hy); lo = pk2h(lx, ly);
}

// ================= merged input split kernel =================
// blocks [0,12288): q/k/v inputs; [12288,15360): Wq/Wk/Wv; [15360,16384): Wo (h only)
__global__ void split_all_kernel(const float* __restrict__ q, const float* __restrict__ k,
                                 const float* __restrict__ v,
                                 const float* __restrict__ Wq, const float* __restrict__ Wk,
                                 const float* __restrict__ Wv, const float* __restrict__ Wo) {
    u32 bid = blockIdx.x;
    if (bid < 12288u) {
        int y = bid / 4096u;
        u32 idx = (bid % 4096u) * 256u + threadIdx.x;
        const float* in = (y == 0) ? q : (y == 1) ? k : v;
        float4 x = ((const float4*)in)[idx];
        u32 h01, l01, h23, l23;
        split2pkh(x.x, x.y, h01, l01);
        split2pkh(x.z, x.w, h23, l23);
        u32 o = idx * 4u;
        *(uint2*)&g_as[y][0][o] = make_uint2(h01, h23);
        if (y < 2)
            *(uint2*)&g_as[y][1][o] = make_uint2(l01, l23);
    } else if (bid < 15360u) {
        u32 idx = (bid - 12288u) * 256u + threadIdx.x;
        u32 mat = idx >> 18, r = idx & 262143u;
        u32 n = r >> 8, d4 = r & 255u;
        u32 h = n >> 6, kk = n & 63u;
        const float* W = (mat == 0) ? Wq : (mat == 1) ? Wk : Wv;
        float xs[4];
#pragma unroll
        for (int j = 0; j < 4; j++) xs[j] = W[h * 65536u + (d4 * 4u + j) * 64u + kk];
        u32 h01, l01, h23, l23;
        split2pkh(xs[0], xs[1], h01, l01);
        split2pkh(xs[2], xs[3], h23, l23);
        u32 o = n * 1024u + d4 * 4u;
        *(uint2*)&g_bs[mat][0][o] = make_uint2(h01, h23);
        if (mat < 2)
            *(uint2*)&g_bs[mat][1][o] = make_uint2(l01, l23);
    } else {
        u32 idx = (bid - 15360u) * 256u + threadIdx.x;
        float4 x = ((const float4*)Wo)[idx];
        u32 o = idx * 4u;
        *(uint2*)&g_bs[3][0][o] = make_uint2(
            pk2h(__float2half_rn(x.x), __float2half_rn(x.y)),
            pk2h(__float2half_rn(x.z), __float2half_rn(x.w)));
    }
}

// ================= mma.sync split-fp32 GEMM (8 warps, 64x32 warp tile) ========
// mats 0,1: 3 products. mat 2: 1 product. mat 3 (outproj): 1 product.
#define GPITCH 144u
#define GTILE  18432u        // 128 * 144
#define GSTAGE 36864u        // A + B
#define GSMEM  110592u       // 3 stages
#define BSPLIT 2097152ull

__device__ __forceinline__ void gemm_issue(const char* aB, const char* bB, ull asplit,
                                           u32 base, int v, int s, u32 bm, u32 bn, int tid) {
    int p = v >> 4;
    u32 kb = (u32)(v & 15) * 128u;
    const char* srcA = aB + (ull)c_pa[p] * asplit + kb;
    const char* srcB = bB + (ull)c_pb[p] * BSPLIT + kb;
    u32 stA = base + (u32)s * GSTAGE;
    u32 stB = stA + GTILE;
#pragma unroll
    for (int j = 0; j < 4; j++) {
        u32 c = (u32)tid + (u32)j * 256u;
        u32 row = c >> 3, ch = (c & 7u) << 4;
        CP_ASYNC16(stA + row * GPITCH + ch, srcA + (ull)(bm + row) * 2048ull + ch);
        CP_ASYNC16(stB + row * GPITCH + ch, srcB + (ull)(bn + row) * 2048ull + ch);
    }
    CP_COMMIT();
}

__global__ void __launch_bounds__(256) gemm_mma_kernel(int mat_base, float* Cout,
                                                       const float* __restrict__ bias) {
    extern __shared__ char sm_g[];
    u32 base = smem_to_u32(sm_g);
    const int tid = threadIdx.x, lane = tid & 31, wid = tid >> 5;
    const u32 bm = blockIdx.y << 7, bn = blockIdx.x << 7;
    const int wm = (wid >> 2) << 6, wn = (wid & 3) << 5;
    const int mat = mat_base + blockIdx.z;

    const char* aB; const char* bB; ull asplit;
    if (mat < 3) { aB = (const char*)g_as[mat][0]; bB = (const char*)g_bs[mat][0]; asplit = 8388608ull; }
    else         { aB = (const char*)g_cs;         bB = (const char*)g_bs[3][0];   asplit = 0ull; }

    float acc[4][4][4];
#pragma unroll
    for (int mi = 0; mi < 4; mi++)
#pragma unroll
        for (int ni = 0; ni < 4; ni++)
#pragma unroll
            for (int e = 0; e < 4; e++) acc[mi][ni][e] = 0.f;

    const int NV = (mat >= 2) ? 16 : 48;
    gemm_issue(aB, bB, asplit, base, 0, 0, bm, bn, tid);
    gemm_issue(aB, bB, asplit, base, 1, 1, bm, bn, tid);

    int s = 0;
    for (int v = 0; v < NV; v++) {
        if (v == NV - 1) { CP_WAIT0(); } else { CP_WAIT1(); }
        __syncthreads();
        if (v + 2 < NV) {
            int s2 = (s + 2 >= 3) ? s - 1 : s + 2;
            gemm_issue(aB, bB, asplit, base, v + 2, s2, bm, bn, tid);
        }

        u32 stA = base + (u32)s * GSTAGE;
        u32 stB = stA + GTILE;
        u32 lrow = (u32)(lane & 15) * GPITCH + (u32)(lane >> 4) * 16u;
#pragma unroll
        for (int ks = 0; ks < 4; ks++) {
            u32 a[4][4], b[2][4];
            u32 abase = stA + (u32)wm * GPITCH + lrow + (u32)ks * 32u;
            u32 bbase = stB + (u32)wn * GPITCH + lrow + (u32)ks * 32u;
#pragma unroll
            for (int mi = 0; mi < 4; mi++) LDMX4(a[mi], abase + (u32)mi * (16u * GPITCH));
#pragma unroll
            for (int nj = 0; nj < 2; nj++) LDMX4(b[nj], bbase + (u32)nj * (16u * GPITCH));
#pragma unroll
            for (int mi = 0; mi < 4; mi++)
#pragma unroll
                for (int ni = 0; ni < 4; ni++)
                    mma16816(acc[mi][ni], a[mi], b[ni >> 1][ni & 1], b[ni >> 1][(ni & 1) + 2]);
        }
        s = (s + 1 == 3) ? 0 : s + 1;
    }

    const float pre = (mat == 0) ? 0.125f : 1.0f;
#pragma unroll
    for (int mi = 0; mi < 4; mi++)
#pragma unroll
        for (int ni = 0; ni < 4; ni++) {
            u32 r0 = bm + (u32)wm + (u32)mi * 16u + (u32)(lane >> 2);
            u32 col = bn + (u32)wn + (u32)ni * 8u + (u32)((lane & 3) << 1);
            float v0 = acc[mi][ni][0] * pre, v1 = acc[mi][ni][1] * pre;
            float v2 = acc[mi][ni][2] * pre, v3 = acc[mi][ni][3] * pre;
            if (mat == 3) {
                float b0 = bias[col], b1 = bias[col + 1];
                *(float2*)&Cout[(ull)r0 * 1024ull + col] = make_float2(v0 + b0, v1 + b1);
                *(float2*)&Cout[(ull)(r0 + 8) * 1024ull + col] = make_float2(v2 + b0, v3 + b1);
            } else if (mat == 2) {
                *(u32*)&g_vs[r0 * 1024u + col] =
                    pk2h(__float2half_rn(v0), __float2half_rn(v1));
                *(u32*)&g_vs[(r0 + 8) * 1024u + col] =
                    pk2h(__float2half_rn(v2), __float2half_rn(v3));
            } else {
                __half* d0 = (mat == 0) ? g_qs[0] : g_ks[0];
                __half* d1 = (mat == 0) ? g_qs[1] : g_ks[1];
                u32 h01, l01, h23, l23;
                split2pkh(v0, v1, h01, l01); split2pkh(v2, v3, h23, l23);
                *(u32*)&d0[r0 * 1024u + col] = h01;
                *(u32*)&d1[r0 * 1024u + col] = l01;
                *(u32*)&d0[(r0 + 8) * 1024u + col] = h23;
                *(u32*)&d1[(r0 + 8) * 1024u + col] = l23;
            }
        }
}

// ================= mma.sync flash attention =================
// QK^T: 3 products (hh, hl, lh); PV: 1 product (P fp16 unsplit, V single fp16).
#define AP   144u
#define QSZ  18432u     // 128*144 per split
#define KSZ  9216u      // 64*144 per split
#define ASTAGE 27648u   // 2 K splits + 1 V
#define ASMEM  92160u   // 2*QSZ + 2*ASTAGE

__device__ __forceinline__ void attn_issue(u32 base, int s, int key0, u32 hb, int tid) {
    u32 st = base + 2u * QSZ + (u32)s * ASTAGE;
#pragma unroll
    for (int i = 0; i < 6; i++) {
        u32 u = (u32)tid + (u32)i * 256u;
        if (u < 1024u) {
            u32 sp = u >> 9, r = (u >> 3) & 63u, ch = (u & 7u) << 4;
            const char* src = (const char*)g_ks[sp] + (ull)(key0 + (int)r) * 2048ull + hb + ch;
            CP_ASYNC16(st + sp * KSZ + r * AP + ch, src);
        } else {
            u32 u2 = u - 1024u;
            u32 r = u2 >> 3, ch = (u2 & 7u) << 4;
            const char* src = (const char*)g_vs + (ull)(key0 + (int)r) * 2048ull + hb + ch;
            CP_ASYNC16(st + 2u * KSZ + r * AP + ch, src);
        }
    }
    CP_COMMIT();
}

__global__ void __launch_bounds__(256, 2) attn_mma_kernel() {
    extern __shared__ char sma[];
    u32 base = smem_to_u32(sma);
    const int tid = threadIdx.x, lane = tid & 31, w = tid >> 5;
    const int b = blockIdx.y >> 4, h = blockIdx.y & 15;
    const u32 hb = (u32)h * 128u;
    const int m0 = b * 2048 + (blockIdx.x << 7);
    const int kv0 = b * 2048;

#pragma unroll
    for (int i = 0; i < 8; i++) {
        u32 u = (u32)tid + (u32)i * 256u;
        u32 sp = u >> 10, r = (u >> 3) & 127u, ch = (u & 7u) << 4;
        const char* src = (const char*)g_qs[sp] + (ull)(m0 + (int)r) * 2048ull + hb + ch;
        CP_ASYNC16(base + sp * QSZ + r * AP + ch, src);
    }
    CP_COMMIT();
    attn_issue(base, 0, kv0, hb, tid);

    float o[8][4];
#pragma unroll
    for (int i = 0; i < 8; i++)
#pragma unroll
        for (int e = 0; e < 4; e++) o[i][e] = 0.f;
    float mg0 = -1e30f, mg1 = -1e30f, l0 = 0.f, l1 = 0.f;

    const u32 lrow = (u32)(lane & 15) * AP + (u32)(lane >> 4) * 16u;
    const u32 qbase = base + (u32)w * (16u * AP) + lrow;

    for (int c = 0; c < 32; c++) {
        if (c + 1 < 32) { attn_issue(base, (c + 1) & 1, kv0 + (c + 1) * 64, hb, tid); CP_WAIT1(); }
        else            { CP_WAIT0(); }
        __syncthreads();

        u32 stK = base + 2u * QSZ + (u32)(c & 1) * ASTAGE;
        u32 stV = stK + 2u * KSZ;

        float sv[8][4];
#pragma unroll
        for (int i = 0; i < 8; i++)
#pragma unroll
            for (int e = 0; e < 4; e++) sv[i][e] = 0.f;

#pragma unroll
        for (int ks = 0; ks < 4; ks++) {
            u32 aq[2][4];
#pragma unroll
            for (int sp = 0; sp < 2; sp++) LDMX4(aq[sp], qbase + sp * QSZ + (u32)ks * 32u);
#pragma unroll
            for (int sb = 0; sb < 2; sb++) {
                u32 bf[4][4];
                u32 bb = stK + (u32)sb * KSZ + lrow + (u32)ks * 32u;
#pragma unroll
                for (int q = 0; q < 4; q++) LDMX4(bf[q], bb + (u32)q * (16u * AP));
                const int na = (sb == 0) ? 2 : 1;   // hh, lh | hl
#pragma unroll
                for (int ai = 0; ai < 2; ai++) {
                    if (ai < na) {
#pragma unroll
                        for (int q = 0; q < 4; q++) {
                            mma16816(sv[2 * q],     aq[ai], bf[q][0], bf[q][2]);
                            mma16816(sv[2 * q + 1], aq[ai], bf[q][1], bf[q][3]);
                        }
                    }
                }
            }
        }

        float cm0 = -1e30f, cm1 = -1e30f;
#pragma unroll
        for (int i = 0; i < 8; i++) {
            cm0 = fmaxf(cm0, fmaxf(sv[i][0], sv[i][1]));
            cm1 = fmaxf(cm1, fmaxf(sv[i][2], sv[i][3]));
        }
        cm0 = fmaxf(cm0, __shfl_xor_sync(0xffffffffu, cm0, 1));
        cm0 = fmaxf(cm0, __shfl_xor_sync(0xffffffffu, cm0, 2));
        cm1 = fmaxf(cm1, __shfl_xor_sync(0xffffffffu, cm1, 1));
        cm1 = fmaxf(cm1, __shfl_xor_sync(0xffffffffu, cm1, 2));
        float nm0 = fmaxf(mg0, cm0), nm1 = fmaxf(mg1, cm1);
        float corr0 = __expf(mg0 - nm0), corr1 = __expf(mg1 - nm1);
        float rs0 = 0.f, rs1 = 0.f;
#pragma unroll
        for (int i = 0; i < 8; i++) {
            sv[i][0] = __expf(sv[i][0] - nm0);
            sv[i][1] = __expf(sv[i][1] - nm0);
            sv[i][2] = __expf(sv[i][2] - nm1);
            sv[i][3] = __expf(sv[i][3] - nm1);
            rs0 += sv[i][0] + sv[i][1];
            rs1 += sv[i][2] + sv[i][3];
        }
        rs0 += __shfl_xor_sync(0xffffffffu, rs0, 1);
        rs0 += __shfl_xor_sync(0xffffffffu, rs0, 2);
        rs1 += __shfl_xor_sync(0xffffffffu, rs1, 1);
        rs1 += __shfl_xor_sync(0xffffffffu, rs1, 2);
        l0 = l0 * corr0 + rs0; l1 = l1 * corr1 + rs1;
        mg0 = nm0; mg1 = nm1;
#pragma unroll
        for (int i = 0; i < 8; i++) {
            o[i][0] *= corr0; o[i][1] *= corr0;
            o[i][2] *= corr1; o[i][3] *= corr1;
        }

        u32 ph[4][4];
#pragma unroll
        for (int j = 0; j < 4; j++) {
            ph[j][0] = pk2h(__float2half_rn(sv[2 * j][0]),     __float2half_rn(sv[2 * j][1]));
            ph[j][1] = pk2h(__float2half_rn(sv[2 * j][2]),     __float2half_rn(sv[2 * j][3]));
            ph[j][2] = pk2h(__float2half_rn(sv[2 * j + 1][0]), __float2half_rn(sv[2 * j + 1][1]));
            ph[j][3] = pk2h(__float2half_rn(sv[2 * j + 1][2]), __float2half_rn(sv[2 * j + 1][3]));
        }

#pragma unroll
        for (int j = 0; j < 4; j++) {
            u32 vrow = stV + (16u * (u32)j + (u32)(lane & 7) + (u32)((lane >> 4) << 3)) * AP
                       + (u32)(((lane >> 3) & 1) << 4);
            u32 bv[4][4];
#pragma unroll
            for (int q = 0; q < 4; q++) LDMX4T(bv[q], vrow + (u32)q * 32u);
#pragma unroll
            for (int q = 0; q < 4; q++) {
                mma16816(o[2 * q],     ph[j], bv[q][0], bv[q][2]);
                mma16816(o[2 * q + 1], ph[j], bv[q][1], bv[q][3]);
            }
        }
        __syncthreads();
    }

    float inv0 = 1.0f / l0, inv1 = 1.0f / l1;
    u32 r0 = (u32)m0 + (u32)w * 16u + (u32)(lane >> 2);
    u32 cb = (u32)h * 64u + (u32)((lane & 3) << 1);
#pragma unroll
    for (int i = 0; i < 8; i++) {
        u32 col = cb + (u32)i * 8u;
        *(u32*)&g_cs[r0 * 1024u + col] =
            pk2h(__float2half_rn(o[i][0] * inv0), __float2half_rn(o[i][1] * inv0));
        *(u32*)&g_cs[(r0 + 8u) * 1024u + col] =
            pk2h(__float2half_rn(o[i][2] * inv1), __float2half_rn(o[i][3] * inv1));
    }
}

// ================= launch =================
extern "C" void kernel_launch(void* const* d_in, const int* in_sizes, int n_in,
                              void* d_out, int out_size) {
    const float* q  = (const float*)d_in[0];
    const float* k  = (const float*)d_in[1];
    const float* v  = (const float*)d_in[2];
    const float* Wq = (const float*)d_in[3];
    const float* Wk = (const float*)d_in[4];
    const float* Wv = (const float*)d_in[5];
    const float* Wo = (const float*)d_in[6];
    const float* bo = (const float*)d_in[7];
    float* out = (float*)d_out;

    split_all_kernel<<<16384, 256>>>(q, k, v, Wq, Wk, Wv, Wo);

    cudaFuncSetAttribute(gemm_mma_kernel, cudaFuncAttributeMaxDynamicSharedMemorySize, GSMEM);
    gemm_mma_kernel<<<dim3(8, 32, 3), 256, GSMEM>>>(0, nullptr, nullptr);

    cudaFuncSetAttribute(attn_mma_kernel, cudaFuncAttributeMaxDynamicSharedMemorySize, ASMEM);
    attn_mma_kernel<<<dim3(16, 32), 256, ASMEM>>>();

    gemm_mma_kernel<<<dim3(8, 32, 1), 256, GSMEM>>>(3, out, bo);
}

// round 14
// speedup vs baseline: 3.5713x; 1.0039x over previous
#include <cuda_runtime.h>
#include <cuda_fp16.h>

typedef unsigned long long ull;
typedef unsigned int u32;

// ================= common helpers =================
__device__ __forceinline__ u32 smem_to_u32(const void* p) {
    u32 a; asm("{ .reg .u64 t; cvta.to.shared.u64 t, %1; cvt.u32.u64 %0, t; }" : "=r"(a) : "l"(p));
    return a;
}
#define CP_ASYNC16(dst, src) asm volatile("cp.async.cg.shared.global [%0], [%1], 16;" :: "r"(dst), "l"(src) : "memory")
#define CP_COMMIT()          asm volatile("cp.async.commit_group;" ::: "memory")
#define CP_WAIT0()           asm volatile("cp.async.wait_group 0;" ::: "memory")
#define CP_WAIT1()           asm volatile("cp.async.wait_group 1;" ::: "memory")

#define LDMX4(r, addr) \
    asm volatile("ldmatrix.sync.aligned.m8n8.x4.shared.b16 {%0,%1,%2,%3}, [%4];" \
        : "=r"((r)[0]), "=r"((r)[1]), "=r"((r)[2]), "=r"((r)[3]) : "r"(addr))
#define LDMX4T(r, addr) \
    asm volatile("ldmatrix.sync.aligned.m8n8.x4.trans.shared.b16 {%0,%1,%2,%3}, [%4];" \
        : "=r"((r)[0]), "=r"((r)[1]), "=r"((r)[2]), "=r"((r)[3]) : "r"(addr))

__device__ __forceinline__ void mma16816(float* c, const u32* a, u32 b0, u32 b1) {
    asm volatile("mma.sync.aligned.m16n8k16.row.col.f32.f16.f16.f32 "
        "{%0,%1,%2,%3}, {%4,%5,%6,%7}, {%8,%9}, {%0,%1,%2,%3};"
        : "+f"(c[0]), "+f"(c[1]), "+f"(c[2]), "+f"(c[3])
        : "r"(a[0]), "r"(a[1]), "r"(a[2]), "r"(a[3]), "r"(b0), "r"(b1));
}

// ================= global scratch =================
__device__ __align__(256) __half g_as[3][2][4194304];  // input splits [mat][split][m*1024+k]
__device__ __align__(256) __half g_bs[4][2][1048576];  // weight splits [mat][split][n*1024+k]
__device__ __align__(256) __half g_qs[2][4194304];     // qh 2-split (prescaled 1/8)
__device__ __align__(256) __half g_ks[2][4194304];     // kh 2-split
__device__ __align__(256) __half g_vs[4194304];        // vh single fp16
__device__ __align__(256) __half g_cs[4194304];        // ctx single fp16

__constant__ int c_pa[3] = { 0, 0, 1 };
__constant__ int c_pb[3] = { 0, 1, 0 };

// ================= split helpers (fp16 h+l) =================
__device__ __forceinline__ u32 pk2h(__half a, __half b) {
    __half2 t = __halves2half2(a, b);
    return *reinterpret_cast<u32*>(&t);
}
__device__ __forceinline__ void split2h(float x, __half& h, __half& l) {
    h = __float2half_rn(x);
    l = __float2half_rn(x - __half2float(h));
}
__device__ __forceinline__ void split2pkh(float x, float y, u32& hi, u32& lo) {
    __half hx, lx, hy, ly;
    split2h(x, hx, lx); split2h(y, hy, ly);
    hi = pk2h(hx, hy); lo = pk2h(lx, ly);
}

// ================= split kernel 1: q/k/v inputs + Wo (all coalesced) =========
// blocks [0,12288): q/k/v inputs; [12288,13312): Wo (h only)
__global__ void split_io_kernel(const float* __restrict__ q, const float* __restrict__ k,
                                const float* __restrict__ v, const float* __restrict__ Wo) {
    u32 bid = blockIdx.x;
    if (bid < 12288u) {
        int y = bid / 4096u;
        u32 idx = (bid % 4096u) * 256u + threadIdx.x;
        const float* in = (y == 0) ? q : (y == 1) ? k : v;
        float4 x = ((const float4*)in)[idx];
        u32 o = idx * 4u;
        if (y < 2) {
            u32 h01, l01, h23, l23;
            split2pkh(x.x, x.y, h01, l01);
            split2pkh(x.z, x.w, h23, l23);
            *(uint2*)&g_as[y][0][o] = make_uint2(h01, h23);
            *(uint2*)&g_as[y][1][o] = make_uint2(l01, l23);
        } else {
            *(uint2*)&g_as[2][0][o] = make_uint2(
                pk2h(__float2half_rn(x.x), __float2half_rn(x.y)),
                pk2h(__float2half_rn(x.z), __float2half_rn(x.w)));
        }
    } else {
        u32 idx = (bid - 12288u) * 256u + threadIdx.x;
        float4 x = ((const float4*)Wo)[idx];
        u32 o = idx * 4u;
        *(uint2*)&g_bs[3][0][o] = make_uint2(
            pk2h(__float2half_rn(x.x), __float2half_rn(x.y)),
            pk2h(__float2half_rn(x.z), __float2half_rn(x.w)));
    }
}

// ================= split kernel 2: Wq/Wk/Wv transpose-through-smem ==========
// 384 blocks: mat = bid>>7, h = (bid&127)>>3, dt = bid&7. Tile: d in [dt*128, +128), kk in [0,64).
// In:  W[h*65536 + d*64 + kk]  (coalesced 256B rows)
// Out: g_bs[mat][s][(h*64+kk)*1024 + d]  (coalesced u32 stores along d)
__global__ void split_w3t_kernel(const float* __restrict__ Wq, const float* __restrict__ Wk,
                                 const float* __restrict__ Wv) {
    __shared__ float ts[128 * 65];
    u32 bid = blockIdx.x;
    u32 mat = bid >> 7, r = bid & 127u;
    u32 h = r >> 3, dt = r & 7u;
    const float* W = (mat == 0) ? Wq : (mat == 1) ? Wk : Wv;
    const u32 d0 = dt * 128u;
    const int tid = threadIdx.x;

    u32 kk = (u32)tid & 63u, dl = (u32)tid >> 6;
#pragma unroll
    for (int it = 0; it < 32; it++) {
        u32 d = dl + (u32)it * 4u;
        ts[d * 65u + kk] = W[h * 65536u + (d0 + d) * 64u + kk];
    }
    __syncthreads();

    u32 kk2 = (u32)tid >> 6, dc = ((u32)tid & 63u) * 2u;
#pragma unroll
    for (int it = 0; it < 16; it++) {
        u32 kkr = kk2 + (u32)it * 4u;
        float x0 = ts[dc * 65u + kkr];
        float x1 = ts[(dc + 1u) * 65u + kkr];
        u32 o = (h * 64u + kkr) * 1024u + d0 + dc;
        if (mat < 2u) {
            u32 hi, lo;
            split2pkh(x0, x1, hi, lo);
            *(u32*)&g_bs[mat][0][o] = hi;
            *(u32*)&g_bs[mat][1][o] = lo;
        } else {
            *(u32*)&g_bs[2][0][o] = pk2h(__float2half_rn(x0), __float2half_rn(x1));
        }
    }
}

// ================= mma.sync split-fp32 GEMM (8 warps, 64x32 warp tile) ========
// mats 0,1: 3 products. mat 2: 1 product. mat 3 (outproj): 1 product.
#define GPITCH 144u
#define GTILE  18432u        // 128 * 144
#define GSTAGE 36864u        // A + B
#define GSMEM  110592u       // 3 stages
#define BSPLIT 2097152ull

__device__ __forceinline__ void gemm_issue(const char* aB, const char* bB, ull asplit,
                                           u32 base, int v, int s, u32 bm, u32 bn, int tid) {
    int p = v >> 4;
    u32 kb = (u32)(v & 15) * 128u;
    const char* srcA = aB + (ull)c_pa[p] * asplit + kb;
    const char* srcB = bB + (ull)c_pb[p] * BSPLIT + kb;
    u32 stA = base + (u32)s * GSTAGE;
    u32 stB = stA + GTILE;
#pragma unroll
    for (int j = 0; j < 4; j++) {
        u32 c = (u32)tid + (u32)j * 256u;
        u32 row = c >> 3, ch = (c & 7u) << 4;
        CP_ASYNC16(stA + row * GPITCH + ch, srcA + (ull)(bm + row) * 2048ull + ch);
        CP_ASYNC16(stB + row * GPITCH + ch, srcB + (ull)(bn + row) * 2048ull + ch);
    }
    CP_COMMIT();
}

__global__ void __launch_bounds__(256) gemm_mma_kernel(int mat_base, float* Cout,
                                                       const float* __restrict__ bias) {
    extern __shared__ char sm_g[];
    u32 base = smem_to_u32(sm_g);
    const int tid = threadIdx.x, lane = tid & 31, wid = tid >> 5;
    const u32 bm = blockIdx.y << 7, bn = blockIdx.x << 7;
    const int wm = (wid >> 2) << 6, wn = (wid & 3) << 5;
    const int mat = mat_base + blockIdx.z;

    const char* aB; const char* bB; ull asplit;
    if (mat < 3) { aB = (const char*)g_as[mat][0]; bB = (const char*)g_bs[mat][0]; asplit = 8388608ull; }
    else         { aB = (const char*)g_cs;         bB = (const char*)g_bs[3][0];   asplit = 0ull; }

    float acc[4][4][4];
#pragma unroll
    for (int mi = 0; mi < 4; mi++)
#pragma unroll
        for (int ni = 0; ni < 4; ni++)
#pragma unroll
            for (int e = 0; e < 4; e++) acc[mi][ni][e] = 0.f;

    const int NV = (mat >= 2) ? 16 : 48;
    gemm_issue(aB, bB, asplit, base, 0, 0, bm, bn, tid);
    gemm_issue(aB, bB, asplit, base, 1, 1, bm, bn, tid);

    int s = 0;
    for (int v = 0; v < NV; v++) {
        if (v == NV - 1) { CP_WAIT0(); } else { CP_WAIT1(); }
        __syncthreads();
        if (v + 2 < NV) {
            int s2 = (s + 2 >= 3) ? s - 1 : s + 2;
            gemm_issue(aB, bB, asplit, base, v + 2, s2, bm, bn, tid);
        }

        u32 stA = base + (u32)s * GSTAGE;
        u32 stB = stA + GTILE;
        u32 lrow = (u32)(lane & 15) * GPITCH + (u32)(lane >> 4) * 16u;
#pragma unroll
        for (int ks = 0; ks < 4; ks++) {
            u32 a[4][4], b[2][4];
            u32 abase = stA + (u32)wm * GPITCH + lrow + (u32)ks * 32u;
            u32 bbase = stB + (u32)wn * GPITCH + lrow + (u32)ks * 32u;
#pragma unroll
            for (int mi = 0; mi < 4; mi++) LDMX4(a[mi], abase + (u32)mi * (16u * GPITCH));
#pragma unroll
            for (int nj = 0; nj < 2; nj++) LDMX4(b[nj], bbase + (u32)nj * (16u * GPITCH));
#pragma unroll
            for (int mi = 0; mi < 4; mi++)
#pragma unroll
                for (int ni = 0; ni < 4; ni++)
                    mma16816(acc[mi][ni], a[mi], b[ni >> 1][ni & 1], b[ni >> 1][(ni & 1) + 2]);
        }
        s = (s + 1 == 3) ? 0 : s + 1;
    }

    const float pre = (mat == 0) ? 0.125f : 1.0f;
#pragma unroll
    for (int mi = 0; mi < 4; mi++)
#pragma unroll
        for (int ni = 0; ni < 4; ni++) {
            u32 r0 = bm + (u32)wm + (u32)mi * 16u + (u32)(lane >> 2);
            u32 col = bn + (u32)wn + (u32)ni * 8u + (u32)((lane & 3) << 1);
            float v0 = acc[mi][ni][0] * pre, v1 = acc[mi][ni][1] * pre;
            float v2 = acc[mi][ni][2] * pre, v3 = acc[mi][ni][3] * pre;
            if (mat == 3) {
                float b0 = bias[col], b1 = bias[col + 1];
                *(float2*)&Cout[(ull)r0 * 1024ull + col] = make_float2(v0 + b0, v1 + b1);
                *(float2*)&Cout[(ull)(r0 + 8) * 1024ull + col] = make_float2(v2 + b0, v3 + b1);
            } else if (mat == 2) {
                *(u32*)&g_vs[r0 * 1024u + col] =
                    pk2h(__float2half_rn(v0), __float2half_rn(v1));
                *(u32*)&g_vs[(r0 + 8) * 1024u + col] =
                    pk2h(__float2half_rn(v2), __float2half_rn(v3));
            } else {
                __half* d0 = (mat == 0) ? g_qs[0] : g_ks[0];
                __half* d1 = (mat == 0) ? g_qs[1] : g_ks[1];
                u32 h01, l01, h23, l23;
                split2pkh(v0, v1, h01, l01); split2pkh(v2, v3, h23, l23);
                *(u32*)&d0[r0 * 1024u + col] = h01;
                *(u32*)&d1[r0 * 1024u + col] = l01;
                *(u32*)&d0[(r0 + 8) * 1024u + col] = h23;
                *(u32*)&d1[(r0 + 8) * 1024u + col] = l23;
            }
        }
}

// ================= mma.sync flash attention =================
// QK^T: 3 products (hh, hl, lh); PV: 1 product (P fp16 unsplit, V single fp16).
#define AP   144u
#define QSZ  18432u     // 128*144 per split
#define KSZ  9216u      // 64*144 per split
#define ASTAGE 27648u   // 2 K splits + 1 V
#define ASMEM  92160u   // 2*QSZ + 2*ASTAGE

__device__ __forceinline__ void attn_issue(u32 base, int s, int key0, u32 hb, int tid) {
    u32 st = base + 2u * QSZ + (u32)s * ASTAGE;
#pragma unroll
    for (int i = 0; i < 6; i++) {
        u32 u = (u32)tid + (u32)i * 256u;
        if (u < 1024u) {
            u32 sp = u >> 9, r = (u >> 3) & 63u, ch = (u & 7u) << 4;
            const char* src = (const char*)g_ks[sp] + (ull)(key0 + (int)r) * 2048ull + hb + ch;
            CP_ASYNC16(st + sp * KSZ + r * AP + ch, src);
        } else {
            u32 u2 = u - 1024u;
            u32 r = u2 >> 3, ch = (u2 & 7u) << 4;
            const char* src = (const char*)g_vs + (ull)(key0 + (int)r) * 2048ull + hb + ch;
            CP_ASYNC16(st + 2u * KSZ + r * AP + ch, src);
        }
    }
    CP_COMMIT();
}

__global__ void __launch_bounds__(256, 2) attn_mma_kernel() {
    extern __shared__ char sma[];
    u32 base = smem_to_u32(sma);
    const int tid = threadIdx.x, lane = tid & 31, w = tid >> 5;
    const int b = blockIdx.y >> 4, h = blockIdx.y & 15;
    const u32 hb = (u32)h * 128u;
    const int m0 = b * 2048 + (blockIdx.x << 7);
    const int kv0 = b * 2048;

#pragma unroll
    for (int i = 0; i < 8; i++) {
        u32 u = (u32)tid + (u32)i * 256u;
        u32 sp = u >> 10, r = (u >> 3) & 127u, ch = (u & 7u) << 4;
        const char* src = (const char*)g_qs[sp] + (ull)(m0 + (int)r) * 2048ull + hb + ch;
        CP_ASYNC16(base + sp * QSZ + r * AP + ch, src);
    }
    CP_COMMIT();
    attn_issue(base, 0, kv0, hb, tid);

    float o[8][4];
#pragma unroll
    for (int i = 0; i < 8; i++)
#pragma unroll
        for (int e = 0; e < 4; e++) o[i][e] = 0.f;
    float mg0 = -1e30f, mg1 = -1e30f, l0 = 0.f, l1 = 0.f;

    const u32 lrow = (u32)(lane & 15) * AP + (u32)(lane >> 4) * 16u;
    const u32 qbase = base + (u32)w * (16u * AP) + lrow;

    for (int c = 0; c < 32; c++) {
        if (c + 1 < 32) { attn_issue(base, (c + 1) & 1, kv0 + (c + 1) * 64, hb, tid); CP_WAIT1(); }
        else            { CP_WAIT0(); }
        __syncthreads();

        u32 stK = base + 2u * QSZ + (u32)(c & 1) * ASTAGE;
        u32 stV = stK + 2u * KSZ;

        float sv[8][4];
#pragma unroll
        for (int i = 0; i < 8; i++)
#pragma unroll
            for (int e = 0; e < 4; e++) sv[i][e] = 0.f;

#pragma unroll
        for (int ks = 0; ks < 4; ks++) {
            u32 aq[2][4];
#pragma unroll
            for (int sp = 0; sp < 2; sp++) LDMX4(aq[sp], qbase + sp * QSZ + (u32)ks * 32u);
#pragma unroll
            for (int sb = 0; sb < 2; sb++) {
                u32 bf[4][4];
                u32 bb = stK + (u32)sb * KSZ + lrow + (u32)ks * 32u;
#pragma unroll
                for (int q = 0; q < 4; q++) LDMX4(bf[q], bb + (u32)q * (16u * AP));
                const int na = (sb == 0) ? 2 : 1;   // hh, lh | hl
#pragma unroll
                for (int ai = 0; ai < 2; ai++) {
                    if (ai < na) {
#pragma unroll
                        for (int q = 0; q < 4; q++) {
                            mma16816(sv[2 * q],     aq[ai], bf[q][0], bf[q][2]);
                            mma16816(sv[2 * q + 1], aq[ai], bf[q][1], bf[q][3]);
                        }
                    }
                }
            }
        }

        float cm0 = -1e30f, cm1 = -1e30f;
#pragma unroll
        for (int i = 0; i < 8; i++) {
            cm0 = fmaxf(cm0, fmaxf(sv[i][0], sv[i][1]));
            cm1 = fmaxf(cm1, fmaxf(sv[i][2], sv[i][3]));
        }
        cm0 = fmaxf(cm0, __shfl_xor_sync(0xffffffffu, cm0, 1));
        cm0 = fmaxf(cm0, __shfl_xor_sync(0xffffffffu, cm0, 2));
        cm1 = fmaxf(cm1, __shfl_xor_sync(0xffffffffu, cm1, 1));
        cm1 = fmaxf(cm1, __shfl_xor_sync(0xffffffffu, cm1, 2));
        float nm0 = fmaxf(mg0, cm0), nm1 = fmaxf(mg1, cm1);
        float corr0 = __expf(mg0 - nm0), corr1 = __expf(mg1 - nm1);
        float rs0 = 0.f, rs1 = 0.f;
#pragma unroll
        for (int i = 0; i < 8; i++) {
            sv[i][0] = __expf(sv[i][0] - nm0);
            sv[i][1] = __expf(sv[i][1] - nm0);
            sv[i][2] = __expf(sv[i][2] - nm1);
            sv[i][3] = __expf(sv[i][3] - nm1);
            rs0 += sv[i][0] + sv[i][1];
            rs1 += sv[i][2] + sv[i][3];
        }
        rs0 += __shfl_xor_sync(0xffffffffu, rs0, 1);
        rs0 += __shfl_xor_sync(0xffffffffu, rs0, 2);
        rs1 += __shfl_xor_sync(0xffffffffu, rs1, 1);
        rs1 += __shfl_xor_sync(0xffffffffu, rs1, 2);
        l0 = l0 * corr0 + rs0; l1 = l1 * corr1 + rs1;
        mg0 = nm0; mg1 = nm1;
#pragma unroll
        for (int i = 0; i < 8; i++) {
            o[i][0] *= corr0; o[i][1] *= corr0;
            o[i][2] *= corr1; o[i][3] *= corr1;
        }

        u32 ph[4][4];
#pragma unroll
        for (int j = 0; j < 4; j++) {
            ph[j][0] = pk2h(__float2half_rn(sv[2 * j][0]),     __float2half_rn(sv[2 * j][1]));
            ph[j][1] = pk2h(__float2half_rn(sv[2 * j][2]),     __float2half_rn(sv[2 * j][3]));
            ph[j][2] = pk2h(__float2half_rn(sv[2 * j + 1][0]), __float2half_rn(sv[2 * j + 1][1]));
            ph[j][3] = pk2h(__float2half_rn(sv[2 * j + 1][2]), __float2half_rn(sv[2 * j + 1][3]));
        }

#pragma unroll
        for (int j = 0; j < 4; j++) {
            u32 vrow = stV + (16u * (u32)j + (u32)(lane & 7) + (u32)((lane >> 4) << 3)) * AP
                       + (u32)(((lane >> 3) & 1) << 4);
            u32 bv[4][4];
#pragma unroll
            for (int q = 0; q < 4; q++) LDMX4T(bv[q], vrow + (u32)q * 32u);
#pragma unroll
            for (int q = 0; q < 4; q++) {
                mma16816(o[2 * q],     ph[j], bv[q][0], bv[q][2]);
                mma16816(o[2 * q + 1], ph[j], bv[q][1], bv[q][3]);
            }
        }
        __syncthreads();
    }

    float inv0 = 1.0f / l0, inv1 = 1.0f / l1;
    u32 r0 = (u32)m0 + (u32)w * 16u + (u32)(lane >> 2);
    u32 cb = (u32)h * 64u + (u32)((lane & 3) << 1);
#pragma unroll
    for (int i = 0; i < 8; i++) {
        u32 col = cb + (u32)i * 8u;
        *(u32*)&g_cs[r0 * 1024u + col] =
            pk2h(__float2half_rn(o[i][0] * inv0), __float2half_rn(o[i][1] * inv0));
        *(u32*)&g_cs[(r0 + 8u) * 1024u + col] =
            pk2h(__float2half_rn(o[i][2] * inv1), __float2half_rn(o[i][3] * inv1));
    }
}

// ================= launch =================
extern "C" void kernel_launch(void* const* d_in, const int* in_sizes, int n_in,
                              void* d_out, int out_size) {
    const float* q  = (const float*)d_in[0];
    const float* k  = (const float*)d_in[1];
    const float* v  = (const float*)d_in[2];
    const float* Wq = (const float*)d_in[3];
    const float* Wk = (const float*)d_in[4];
    const float* Wv = (const float*)d_in[5];
    const float* Wo = (const float*)d_in[6];
    const float* bo = (const float*)d_in[7];
    float* out = (float*)d_out;

    split_io_kernel<<<13312, 256>>>(q, k, v, Wo);
    split_w3t_kernel<<<384, 256>>>(Wq, Wk, Wv);

    cudaFuncSetAttribute(gemm_mma_kernel, cudaFuncAttributeMaxDynamicSharedMemorySize, GSMEM);
    gemm_mma_kernel<<<dim3(8, 32, 3), 256, GSMEM>>>(0, nullptr, nullptr);

    cudaFuncSetAttribute(attn_mma_kernel, cudaFuncAttributeMaxDynamicSharedMemorySize, ASMEM);
    attn_mma_kernel<<<dim3(16, 32), 256, ASMEM>>>();

    gemm_mma_kernel<<<dim3(8, 32, 1), 256, GSMEM>>>(3, out, bo);
}